// round 5
// baseline (speedup 1.0000x reference)
#include <cuda_runtime.h>
#include <math.h>
#include <stdint.h>

// ====================================================================
// Static device scratch (allocation-free rule)
// ====================================================================
__device__ __align__(256) float g_knT[128 * 800];
__device__ __align__(256) float g_hnT[128 * 800];
__device__ __align__(256) float g_A  [16 * 32 * 128 * 128];   // enc1 out (<=32 ch)
__device__ __align__(256) float g_Bf [16 * 128 * 128 * 128];  // conv2 pre-pool
__device__ __align__(256) float g_zc [16 * 128 * 64 * 64];
__device__ __align__(256) float g_zs [16 * 128 * 64 * 64];
__device__ __align__(256) float g_scale[65536];
__device__ __align__(256) float g_S  [65536 * 800];           // sim scratch (both paths)
__device__ __align__(256) int   g_tidx[65536 * 10];
__device__ __align__(256) float g_tw  [65536 * 10];
__device__ __align__(256) int   g_amax[65536];
__device__ __align__(256) float g_zm [16 * 256 * 64 * 64];    // concat(center, skip)
__device__ __align__(256) float g_d1 [16 * 64 * 64 * 64];
__device__ __align__(256) float g_u1 [16 * 32 * 128 * 128];
__device__ __align__(256) float g_u2 [16 * 16 * 256 * 256];

// ====================================================================
// Normalize memory rows -> transposed tables knT[c][m], hnT[c][m]
// one warp per row; 1600 warps total
// ====================================================================
__global__ void k_normrows(const float* __restrict__ keys,
                           const float* __restrict__ hard,
                           float* __restrict__ knT, float* __restrict__ hnT)
{
    int gw = (blockIdx.x * blockDim.x + threadIdx.x) >> 5;
    int lane = threadIdx.x & 31;
    if (gw >= 1600) return;
    const float* src; float* dst; int r;
    if (gw < 800) { src = keys; dst = knT; r = gw; }
    else          { src = hard; dst = hnT; r = gw - 800; }
    float4 v = *(const float4*)(src + (size_t)r * 128 + lane * 4);
    float s = v.x * v.x + v.y * v.y + v.z * v.z + v.w * v.w;
#pragma unroll
    for (int o = 16; o > 0; o >>= 1) s += __shfl_xor_sync(0xffffffffu, s, o);
    float d = 1.0f / fmaxf(sqrtf(s), 1e-12f);
    dst[(size_t)(4 * lane + 0) * 800 + r] = v.x * d;
    dst[(size_t)(4 * lane + 1) * 800 + r] = v.y * d;
    dst[(size_t)(4 * lane + 2) * 800 + r] = v.z * d;
    dst[(size_t)(4 * lane + 3) * 800 + r] = v.w * d;
}

// ====================================================================
// Encoder stage 1: conv3x3 (1 -> CO) + bias + relu + maxpool2.
// MASK: zero input outside center crop [96,160)^2.
// grid (8,8,16), block 256. Pooled tile 16x16 <- input tile 34x34.
// ====================================================================
template<int CO, bool MASK>
__global__ __launch_bounds__(256) void k_enc1(const float* __restrict__ x,
    const float* __restrict__ w, const float* __restrict__ bias,
    float* __restrict__ out)
{
    __shared__ float tile[34][36];
    __shared__ float sw[CO * 9];
    __shared__ float sb[CO];
    const int t  = threadIdx.x;
    const int b  = blockIdx.z;
    const int Y0 = blockIdx.y * 32;      // conv-region origin
    const int X0 = blockIdx.x * 32;
    const float* xb = x + (size_t)b * 65536;
    for (int i = t; i < 34 * 34; i += 256) {
        int r = i / 34, c = i % 34;
        int gy = Y0 + r - 1, gx = X0 + c - 1;
        bool ok = (gy >= 0 && gy < 256 && gx >= 0 && gx < 256);
        if (MASK) ok = ok && (gy >= 96 && gy < 160 && gx >= 96 && gx < 160);
        tile[r][c] = ok ? xb[gy * 256 + gx] : 0.f;
    }
    for (int i = t; i < CO * 9; i += 256) sw[i] = w[i];
    if (t < CO) sb[t] = bias[t];
    __syncthreads();
    const int ty = t >> 4, tx = t & 15;
    float p[4][4];
#pragma unroll
    for (int i = 0; i < 4; i++)
#pragma unroll
        for (int j = 0; j < 4; j++) p[i][j] = tile[2 * ty + i][2 * tx + j];
    const int py = blockIdx.y * 16 + ty, px = blockIdx.x * 16 + tx;
    float* ob = out + (size_t)b * CO * 128 * 128 + py * 128 + px;
#pragma unroll 4
    for (int oc = 0; oc < CO; oc++) {
        float w9[9];
#pragma unroll
        for (int k = 0; k < 9; k++) w9[k] = sw[oc * 9 + k];
        float bv = sb[oc];
        float m = -INFINITY;
#pragma unroll
        for (int i = 0; i < 2; i++)
#pragma unroll
            for (int j = 0; j < 2; j++) {
                float s = bv;
#pragma unroll
                for (int dy = 0; dy < 3; dy++)
#pragma unroll
                    for (int dx = 0; dx < 3; dx++)
                        s = fmaf(w9[dy * 3 + dx], p[i + dy][j + dx], s);
                s = fmaxf(s, 0.f);
                m = fmaxf(m, s);
            }
        ob[(size_t)oc * 128 * 128] = m;
    }
}

// ====================================================================
// Generic conv3x3, pad 1, OIHW weights, optional relu.
// Output tile 32(w) x 16(h); each thread computes 2 horizontally
// adjacent pixels for OCB output channels. IC must be multiple of 8.
// grid: x = W/32, y = tilesY * (OC/OCB), z = B
// ====================================================================
template<int OCB, bool RELU>
__global__ __launch_bounds__(256) void k_conv3(const float* __restrict__ in,
    const float* __restrict__ w, const float* __restrict__ bias,
    float* __restrict__ out, int IC, int OC, int H, int W, int tilesY)
{
    __shared__ float tin[8][18][36];
    __shared__ float sw[OCB][8][9];
    const int tY = blockIdx.y % tilesY;
    const int ob = blockIdx.y / tilesY;
    const int x0 = blockIdx.x * 32, y0 = tY * 16;
    const int b  = blockIdx.z;
    const int tid = threadIdx.x;
    const int u = tid & 15, v = tid >> 4;
    float acc0[OCB], acc1[OCB];
#pragma unroll
    for (int o = 0; o < OCB; o++) { acc0[o] = 0.f; acc1[o] = 0.f; }
    const float* inb = in + (size_t)b * IC * H * W;
    for (int ic0 = 0; ic0 < IC; ic0 += 8) {
        __syncthreads();
        for (int i = tid; i < 8 * 18 * 34; i += 256) {
            int ic = i / (18 * 34); int rem = i % (18 * 34);
            int r = rem / 34, c = rem % 34;
            int gy = y0 + r - 1, gx = x0 + c - 1;
            float val = 0.f;
            if (gy >= 0 && gy < H && gx >= 0 && gx < W)
                val = inb[(size_t)(ic0 + ic) * H * W + gy * W + gx];
            tin[ic][r][c] = val;
        }
        for (int i = tid; i < OCB * 8 * 9; i += 256) {
            int o = i / 72; int rem = i % 72; int ic = rem / 9; int k = rem % 9;
            sw[o][ic][k] = w[((size_t)(ob * OCB + o) * IC + ic0 + ic) * 9 + k];
        }
        __syncthreads();
#pragma unroll
        for (int ic = 0; ic < 8; ic++) {
            float p[3][4];
#pragma unroll
            for (int dy = 0; dy < 3; dy++)
#pragma unroll
                for (int dx = 0; dx < 4; dx++)
                    p[dy][dx] = tin[ic][v + dy][2 * u + dx];
#pragma unroll
            for (int o = 0; o < OCB; o++) {
                float s0 = 0.f, s1 = 0.f;
#pragma unroll
                for (int dy = 0; dy < 3; dy++)
#pragma unroll
                    for (int dx = 0; dx < 3; dx++) {
                        float wv = sw[o][ic][dy * 3 + dx];
                        s0 = fmaf(wv, p[dy][dx],     s0);
                        s1 = fmaf(wv, p[dy][dx + 1], s1);
                    }
                acc0[o] += s0; acc1[o] += s1;
            }
        }
    }
#pragma unroll
    for (int o = 0; o < OCB; o++) {
        int oc = ob * OCB + o;
        float bv = bias[oc];
        float v0 = acc0[o] + bv, v1 = acc1[o] + bv;
        if (RELU) { v0 = fmaxf(v0, 0.f); v1 = fmaxf(v1, 0.f); }
        *(float2*)(out + ((size_t)((size_t)b * OC + oc) * H + (y0 + v)) * W
                       + x0 + 2 * u) = make_float2(v0, v1);
    }
}

// ====================================================================
// 2x2 maxpool (stride 2): Hi x Wi -> (Hi/2) x (Wi/2)
// ====================================================================
__global__ void k_pool(const float* __restrict__ in, float* __restrict__ out,
                       int Wo, int Wi, int total)
{
    int o = blockIdx.x * blockDim.x + threadIdx.x;
    if (o >= total) return;
    int bc = o / (Wo * Wo);
    int rem = o % (Wo * Wo);
    int y = rem / Wo, x = rem % Wo;
    const float* p = in + (size_t)bc * Wi * Wi + (2 * y) * Wi + 2 * x;
    float m = fmaxf(fmaxf(p[0], p[1]), fmaxf(p[Wi], p[Wi + 1]));
    out[o] = m;
}

// ====================================================================
// Per-(b,n) L2 norm of zc over C=128 -> scale = 1/max(norm, 1e-12)
// block: 32 n-positions x 8 c-groups; grid 2048
// ====================================================================
__global__ void k_rowscale(const float* __restrict__ zc, float* __restrict__ scale)
{
    __shared__ float part[8][32];
    const int tid = threadIdx.x;
    const int r0 = blockIdx.x * 32;
    const int b  = r0 >> 12;
    const int n0 = r0 & 4095;
    const int nx = tid & 31, cy = tid >> 5;
    const float* base = zc + (size_t)b * 128 * 4096 + n0 + nx;
    float s = 0.f;
#pragma unroll
    for (int j = 0; j < 16; j++) {
        float v = base[(size_t)(cy + 8 * j) * 4096];
        s = fmaf(v, v, s);
    }
    part[cy][nx] = s;
    __syncthreads();
    if (cy == 0) {
        float t = 0.f;
#pragma unroll
        for (int j = 0; j < 8; j++) t += part[j][nx];
        scale[r0 + nx] = 1.0f / fmaxf(sqrtf(t), 1e-12f);
    }
}

// ====================================================================
// SGEMM: S[b*4096+n][m] = sum_c A[b][c][n] * Bm[c][m]
// Tile 64(n) x 64(m), K chunks of 16, 4x4 micro-tile per thread.
// grid: x = 13 (m tiles), y = 64 (n tiles), z = 16
// ====================================================================
__global__ __launch_bounds__(256) void k_gemm(const float* __restrict__ A,
    const float* __restrict__ Bm, float* __restrict__ S)
{
    __shared__ float As[16][64];
    __shared__ float Bs[16][64];
    const int b  = blockIdx.z;
    const int n0 = blockIdx.y * 64;
    const int m0 = blockIdx.x * 64;
    const int tid = threadIdx.x;
    const int tm = tid & 15, tn = tid >> 4;
    float acc[4][4];
#pragma unroll
    for (int i = 0; i < 4; i++)
#pragma unroll
        for (int j = 0; j < 4; j++) acc[i][j] = 0.f;
    const float* Ab = A + (size_t)b * 128 * 4096;
    const int idx = tid * 4;
    const int lkk = idx >> 6;
    const int lnn = idx & 63;
    for (int k0 = 0; k0 < 128; k0 += 16) {
        __syncthreads();
        *(float4*)&As[lkk][lnn] = *(const float4*)&Ab[(size_t)(k0 + lkk) * 4096 + n0 + lnn];
        float4 bv = make_float4(0.f, 0.f, 0.f, 0.f);
        if (m0 + lnn < 800)
            bv = *(const float4*)&Bm[(size_t)(k0 + lkk) * 800 + m0 + lnn];
        *(float4*)&Bs[lkk][lnn] = bv;
        __syncthreads();
#pragma unroll
        for (int k = 0; k < 16; k++) {
            float4 a  = *(float4*)&As[k][tn * 4];
            float4 bb = *(float4*)&Bs[k][tm * 4];
            acc[0][0] = fmaf(a.x, bb.x, acc[0][0]); acc[0][1] = fmaf(a.x, bb.y, acc[0][1]);
            acc[0][2] = fmaf(a.x, bb.z, acc[0][2]); acc[0][3] = fmaf(a.x, bb.w, acc[0][3]);
            acc[1][0] = fmaf(a.y, bb.x, acc[1][0]); acc[1][1] = fmaf(a.y, bb.y, acc[1][1]);
            acc[1][2] = fmaf(a.y, bb.z, acc[1][2]); acc[1][3] = fmaf(a.y, bb.w, acc[1][3]);
            acc[2][0] = fmaf(a.z, bb.x, acc[2][0]); acc[2][1] = fmaf(a.z, bb.y, acc[2][1]);
            acc[2][2] = fmaf(a.z, bb.z, acc[2][2]); acc[2][3] = fmaf(a.z, bb.w, acc[2][3]);
            acc[3][0] = fmaf(a.w, bb.x, acc[3][0]); acc[3][1] = fmaf(a.w, bb.y, acc[3][1]);
            acc[3][2] = fmaf(a.w, bb.z, acc[3][2]); acc[3][3] = fmaf(a.w, bb.w, acc[3][3]);
        }
    }
    const int m = m0 + tm * 4;
    if (m < 800) {
#pragma unroll
        for (int i = 0; i < 4; i++) {
            size_t row = (size_t)b * 4096 + n0 + tn * 4 + i;
            *(float4*)&S[row * 800 + m] =
                make_float4(acc[i][0], acc[i][1], acc[i][2], acc[i][3]);
        }
    }
}

// ====================================================================
// Top-10 + scaled softmax. One warp per row (M=800 = 32 lanes x 25).
// Tie-break: lower index first (matches lax.top_k stable ordering).
// ====================================================================
__global__ void k_topk(const float* __restrict__ S, const float* __restrict__ scale,
                       int* __restrict__ tidx, float* __restrict__ tw)
{
    int gw = (blockIdx.x * blockDim.x + threadIdx.x) >> 5;
    int lane = threadIdx.x & 31;
    if (gw >= 65536) return;
    const float* row = S + (size_t)gw * 800;
    float lv[10]; int li[10];
#pragma unroll
    for (int j = 0; j < 10; j++) { lv[j] = -INFINITY; li[j] = 0x7fffffff; }
    for (int t = 0; t < 25; t++) {
        int m = lane + 32 * t;
        float v = row[m];
        int i = m;
#pragma unroll
        for (int j = 0; j < 10; j++) {
            bool better = (v > lv[j]) || (v == lv[j] && i < li[j]);
            if (better) {
                float tv = lv[j]; lv[j] = v; v = tv;
                int ti = li[j]; li[j] = i; i = ti;
            }
        }
    }
    float bv[10]; int bi[10];
#pragma unroll
    for (int k = 0; k < 10; k++) {
        float cv = lv[0]; int ci = li[0];
#pragma unroll
        for (int off = 16; off > 0; off >>= 1) {
            float ov = __shfl_xor_sync(0xffffffffu, cv, off);
            int   oi = __shfl_xor_sync(0xffffffffu, ci, off);
            if (ov > cv || (ov == cv && oi < ci)) { cv = ov; ci = oi; }
        }
        bv[k] = cv; bi[k] = ci;
        if (lv[0] == cv && li[0] == ci) {
#pragma unroll
            for (int j = 0; j < 9; j++) { lv[j] = lv[j + 1]; li[j] = li[j + 1]; }
            lv[9] = -INFINITY; li[9] = 0x7fffffff;
        }
    }
    if (lane == 0) {
        float sc = scale[gw];
        float mx = bv[0] * sc;
        float e[10], sum = 0.f;
#pragma unroll
        for (int k = 0; k < 10; k++) { e[k] = expf(bv[k] * sc - mx); sum += e[k]; }
        float inv = 1.0f / sum;
#pragma unroll
        for (int k = 0; k < 10; k++) {
            tidx[gw * 10 + k] = bi[k];
            tw[gw * 10 + k]   = e[k] * inv;
        }
    }
}

// ====================================================================
// Argmax over 800 (first-max tie-break). One warp per row.
// ====================================================================
__global__ void k_argmax(const float* __restrict__ S, int* __restrict__ amax)
{
    int gw = (blockIdx.x * blockDim.x + threadIdx.x) >> 5;
    int lane = threadIdx.x & 31;
    if (gw >= 65536) return;
    const float* row = S + (size_t)gw * 800;
    float bv = -INFINITY; int bi = 0x7fffffff;
    for (int t = 0; t < 25; t++) {
        int m = lane + 32 * t;
        float v = row[m];
        if (v > bv || (v == bv && m < bi)) { bv = v; bi = m; }
    }
#pragma unroll
    for (int off = 16; off > 0; off >>= 1) {
        float ov = __shfl_xor_sync(0xffffffffu, bv, off);
        int   oi = __shfl_xor_sync(0xffffffffu, bi, off);
        if (ov > bv || (ov == bv && oi < bi)) { bv = ov; bi = oi; }
    }
    if (lane == 0) amax[gw] = bi;
}

// ====================================================================
// Weighted top-k gather -> zm channels [0,128).  block: 32 c x 8 n.
// ====================================================================
__global__ void k_gatherC(const float* __restrict__ vals, const int* __restrict__ tidx,
                          const float* __restrict__ tw, float* __restrict__ zm)
{
    __shared__ int   sidx[8][10];
    __shared__ float swt [8][10];
    const int r0 = blockIdx.x * 8;
    const int tid = threadIdx.x;
    if (tid < 80) {
        int ny = tid / 10, k = tid % 10;
        sidx[ny][k] = tidx[(size_t)(r0 + ny) * 10 + k];
        swt [ny][k] = tw  [(size_t)(r0 + ny) * 10 + k];
    }
    __syncthreads();
    const int cx = tid & 31, ny = tid >> 5;
    const int row = r0 + ny;
    const int b = row >> 12, n = row & 4095;
#pragma unroll
    for (int cc = 0; cc < 4; cc++) {
        int c = cx + 32 * cc;
        float acc = 0.f;
#pragma unroll
        for (int k = 0; k < 10; k++)
            acc = fmaf(vals[(size_t)sidx[ny][k] * 128 + c], swt[ny][k], acc);
        zm[((size_t)b * 256 + c) * 4096 + n] = acc;
    }
}

// ====================================================================
// Hard gather -> zm channels [128,256)
// ====================================================================
__global__ void k_gatherS(const float* __restrict__ hard, const int* __restrict__ amax,
                          float* __restrict__ zm)
{
    const int r0 = blockIdx.x * 8;
    const int tid = threadIdx.x;
    const int cx = tid & 31, ny = tid >> 5;
    const int row = r0 + ny;
    const int b = row >> 12, n = row & 4095;
    const int a = amax[row];
#pragma unroll
    for (int cc = 0; cc < 4; cc++) {
        int c = cx + 32 * cc;
        zm[((size_t)b * 256 + 128 + c) * 4096 + n] = hard[(size_t)a * 128 + c];
    }
}

// ====================================================================
// Transposed conv (k=4, stride 2, pad 2 equivalent) + bias + relu.
// Weights raw layout (IC, OC, 4, 4) = dec_tw; effective weight for
// input row r contributing to output p is w[i][o][3-kh][3-kw].
// Each thread computes one 2x2 output quad (shared 3x3 input patch).
// Output tile 32x32. grid: x = Wo/32, y = tilesY*(OC/OCB), z = B.
// ====================================================================
template<int IC, int OC, int OCB>
__global__ __launch_bounds__(256) void k_deconv(const float* __restrict__ in,
    const float* __restrict__ w, const float* __restrict__ bias,
    float* __restrict__ out, int Hi, int tilesY)
{
    __shared__ float tin[4][18][20];
    __shared__ float sw[4][OCB][16];
    const int Ho = 2 * Hi;
    const int tY = blockIdx.y % tilesY;
    const int ob = blockIdx.y / tilesY;
    const int b  = blockIdx.z;
    const int X0 = blockIdx.x * 32, Y0 = tY * 32;
    const int a0 = Y0 >> 1, c0 = X0 >> 1;
    const int tid = threadIdx.x;
    const int qx = tid & 15, qy = tid >> 4;
    float acc[OCB][2][2];
#pragma unroll
    for (int o = 0; o < OCB; o++)
#pragma unroll
        for (int e = 0; e < 2; e++)
#pragma unroll
            for (int f = 0; f < 2; f++) acc[o][e][f] = 0.f;
    const float* inb = in + (size_t)b * IC * Hi * Hi;
    for (int ic0 = 0; ic0 < IC; ic0 += 4) {
        __syncthreads();
        for (int i = tid; i < 4 * 18 * 18; i += 256) {
            int ic = i / 324; int rem = i % 324;
            int r = rem / 18, c = rem % 18;
            int gy = a0 + r - 1, gx = c0 + c - 1;
            float v = 0.f;
            if (gy >= 0 && gy < Hi && gx >= 0 && gx < Hi)
                v = inb[(size_t)(ic0 + ic) * Hi * Hi + gy * Hi + gx];
            tin[ic][r][c] = v;
        }
        for (int i = tid; i < 4 * OCB * 16; i += 256) {
            int ic = i / (OCB * 16); int rem = i % (OCB * 16);
            int o = rem / 16; int t = rem % 16;
            sw[ic][o][t] = w[((size_t)(ic0 + ic) * OC + ob * OCB + o) * 16 + t];
        }
        __syncthreads();
#pragma unroll
        for (int ic = 0; ic < 4; ic++) {
            float p[3][3];
#pragma unroll
            for (int uu = 0; uu < 3; uu++)
#pragma unroll
                for (int tt = 0; tt < 3; tt++)
                    p[uu][tt] = tin[ic][qy + uu][qx + tt];
#pragma unroll
            for (int o = 0; o < OCB; o++) {
                const float* W4 = &sw[ic][o][0];   // [kh*4 + kw]
                // (e=0,f=0): rows a-1(w3),a(w1); cols b-1(w3),b(w1)
                acc[o][0][0] += W4[15] * p[0][0] + W4[13] * p[0][1]
                              + W4[7]  * p[1][0] + W4[5]  * p[1][1];
                // (e=0,f=1): cols b(w2), b+1(w0)
                acc[o][0][1] += W4[14] * p[0][1] + W4[12] * p[0][2]
                              + W4[6]  * p[1][1] + W4[4]  * p[1][2];
                // (e=1,f=0): rows a(w2), a+1(w0)
                acc[o][1][0] += W4[11] * p[1][0] + W4[9]  * p[1][1]
                              + W4[3]  * p[2][0] + W4[1]  * p[2][1];
                // (e=1,f=1)
                acc[o][1][1] += W4[10] * p[1][1] + W4[8]  * p[1][2]
                              + W4[2]  * p[2][1] + W4[0]  * p[2][2];
            }
        }
    }
#pragma unroll
    for (int o = 0; o < OCB; o++) {
        int oc = ob * OCB + o;
        float bv = bias[oc];
#pragma unroll
        for (int e = 0; e < 2; e++) {
            float v0 = fmaxf(acc[o][e][0] + bv, 0.f);
            float v1 = fmaxf(acc[o][e][1] + bv, 0.f);
            *(float2*)(out + ((size_t)((size_t)b * OC + oc) * Ho + (Y0 + 2 * qy + e)) * Ho
                           + X0 + 2 * qx) = make_float2(v0, v1);
        }
    }
}

// ====================================================================
// Host launcher
// ====================================================================
extern "C" void kernel_launch(void* const* d_in, const int* in_sizes, int n_in,
                              void* d_out, int out_size)
{
    const float* x        = (const float*)d_in[0];
    const float* ce_w1    = (const float*)d_in[1];
    const float* ce_b1    = (const float*)d_in[2];
    const float* ce_w2    = (const float*)d_in[3];
    const float* ce_b2    = (const float*)d_in[4];
    const float* se_w1    = (const float*)d_in[5];
    const float* se_b1    = (const float*)d_in[6];
    const float* se_w2    = (const float*)d_in[7];
    const float* se_b2    = (const float*)d_in[8];
    const float* mem_keys = (const float*)d_in[9];
    const float* mem_vals = (const float*)d_in[10];
    const float* mem_hard = (const float*)d_in[11];
    const float* dec_w1   = (const float*)d_in[12];
    const float* dec_b1   = (const float*)d_in[13];
    const float* dec_tw1  = (const float*)d_in[14];
    const float* dec_tb1  = (const float*)d_in[15];
    const float* dec_tw2  = (const float*)d_in[16];
    const float* dec_tb2  = (const float*)d_in[17];
    const float* dec_w2   = (const float*)d_in[18];
    const float* dec_b2   = (const float*)d_in[19];
    float* outp = (float*)d_out;

    float *knT, *hnT, *A, *Bf, *zc, *zs, *scale, *S, *tw, *zm, *d1, *u1, *u2;
    int *tidx, *amax;
    cudaGetSymbolAddress((void**)&knT,   g_knT);
    cudaGetSymbolAddress((void**)&hnT,   g_hnT);
    cudaGetSymbolAddress((void**)&A,     g_A);
    cudaGetSymbolAddress((void**)&Bf,    g_Bf);
    cudaGetSymbolAddress((void**)&zc,    g_zc);
    cudaGetSymbolAddress((void**)&zs,    g_zs);
    cudaGetSymbolAddress((void**)&scale, g_scale);
    cudaGetSymbolAddress((void**)&S,     g_S);
    cudaGetSymbolAddress((void**)&tidx,  g_tidx);
    cudaGetSymbolAddress((void**)&tw,    g_tw);
    cudaGetSymbolAddress((void**)&amax,  g_amax);
    cudaGetSymbolAddress((void**)&zm,    g_zm);
    cudaGetSymbolAddress((void**)&d1,    g_d1);
    cudaGetSymbolAddress((void**)&u1,    g_u1);
    cudaGetSymbolAddress((void**)&u2,    g_u2);

    // memory tables (normalized + transposed)
    k_normrows<<<200, 256>>>(mem_keys, mem_hard, knT, hnT);

    // ---- center encoder ----
    k_enc1<32, true><<<dim3(8, 8, 16), 256>>>(x, ce_w1, ce_b1, A);
    k_conv3<16, true><<<dim3(4, 64, 16), 256>>>(A, ce_w2, ce_b2, Bf, 32, 128, 128, 128, 8);
    {
        int total = 16 * 128 * 64 * 64;
        k_pool<<<total / 256, 256>>>(Bf, zc, 64, 128, total);
    }
    // ---- skip encoder ----
    k_enc1<16, false><<<dim3(8, 8, 16), 256>>>(x, se_w1, se_b1, A);
    k_conv3<16, true><<<dim3(4, 64, 16), 256>>>(A, se_w2, se_b2, Bf, 16, 128, 128, 128, 8);
    {
        int total = 16 * 128 * 64 * 64;
        k_pool<<<total / 256, 256>>>(Bf, zs, 64, 128, total);
    }

    // ---- center memory matching ----
    k_rowscale<<<2048, 256>>>(zc, scale);
    k_gemm<<<dim3(13, 64, 16), 256>>>(zc, knT, S);
    k_topk<<<8192, 256>>>(S, scale, tidx, tw);
    k_gatherC<<<8192, 256>>>(mem_vals, tidx, tw, zm);

    // ---- skip memory matching ----
    k_gemm<<<dim3(13, 64, 16), 256>>>(zs, hnT, S);
    k_argmax<<<8192, 256>>>(S, amax);
    k_gatherS<<<8192, 256>>>(mem_hard, amax, zm);

    // ---- decoder ----
    k_conv3<16, true><<<dim3(2, 16, 16), 256>>>(zm, dec_w1, dec_b1, d1, 256, 64, 64, 64, 4);
    k_deconv<64, 32, 8><<<dim3(4, 16, 16), 256>>>(d1, dec_tw1, dec_tb1, u1, 64, 4);
    k_deconv<32, 16, 8><<<dim3(8, 16, 16), 256>>>(u1, dec_tw2, dec_tb2, u2, 128, 8);
    k_conv3<1, false><<<dim3(8, 16, 16), 256>>>(u2, dec_w2, dec_b2, outp, 16, 1, 256, 256, 16);
}

// round 6
// speedup vs baseline: 1.1811x; 1.1811x over previous
#include <cuda_runtime.h>
#include <math.h>
#include <stdint.h>

// ====================================================================
// Static device scratch
// ====================================================================
__device__ __align__(256) float g_knT[128 * 800];
__device__ __align__(256) float g_hnT[128 * 800];
__device__ __align__(256) float g_A  [16 * 32 * 128 * 128];
__device__ __align__(256) float g_zc [16 * 128 * 64 * 64];
__device__ __align__(256) float g_zs [16 * 128 * 64 * 64];
__device__ __align__(256) float g_scale[65536];
__device__ __align__(256) float g_S  [65536 * 800];
__device__ __align__(256) int   g_tidx[65536 * 10];
__device__ __align__(256) float g_tw  [65536 * 10];
__device__ __align__(256) int   g_amax[65536];
__device__ __align__(256) float g_zm [16 * 256 * 64 * 64];
__device__ __align__(256) float g_d1 [16 * 64 * 64 * 64];
__device__ __align__(256) float g_u1 [16 * 32 * 128 * 128];
__device__ __align__(256) float g_u2 [16 * 16 * 256 * 256];

// ====================================================================
// Normalize memory rows -> transposed tables knT[c][m], hnT[c][m]
// ====================================================================
__global__ void k_normrows(const float* __restrict__ keys,
                           const float* __restrict__ hard,
                           float* __restrict__ knT, float* __restrict__ hnT)
{
    int gw = (blockIdx.x * blockDim.x + threadIdx.x) >> 5;
    int lane = threadIdx.x & 31;
    if (gw >= 1600) return;
    const float* src; float* dst; int r;
    if (gw < 800) { src = keys; dst = knT; r = gw; }
    else          { src = hard; dst = hnT; r = gw - 800; }
    float4 v = *(const float4*)(src + (size_t)r * 128 + lane * 4);
    float s = v.x * v.x + v.y * v.y + v.z * v.z + v.w * v.w;
#pragma unroll
    for (int o = 16; o > 0; o >>= 1) s += __shfl_xor_sync(0xffffffffu, s, o);
    float d = 1.0f / fmaxf(sqrtf(s), 1e-12f);
    dst[(size_t)(4 * lane + 0) * 800 + r] = v.x * d;
    dst[(size_t)(4 * lane + 1) * 800 + r] = v.y * d;
    dst[(size_t)(4 * lane + 2) * 800 + r] = v.z * d;
    dst[(size_t)(4 * lane + 3) * 800 + r] = v.w * d;
}

// ====================================================================
// Fill A (enc1-center out) with relu(b1[c]).  A: [16][32][16384]
// ====================================================================
__global__ void k_fillA(float* __restrict__ A, const float* __restrict__ b1)
{
    int i = blockIdx.x * blockDim.x + threadIdx.x;   // < 16*32*16384
    int c = (i >> 14) & 31;
    A[i] = fmaxf(b1[c], 0.f);
}

// ====================================================================
// Fill zc with uniform background relu(b2 + sum_{ic,k} w2*relu(b1)).
// One block per oc (grid 128).
// ====================================================================
__global__ void k_fillzc(float* __restrict__ zc, const float* __restrict__ w2,
                         const float* __restrict__ b1, const float* __restrict__ b2)
{
    const int oc = blockIdx.x;
    float s = b2[oc];
    for (int ic = 0; ic < 32; ic++) {
        float r = fmaxf(b1[ic], 0.f);
        float wsum = 0.f;
#pragma unroll
        for (int k = 0; k < 9; k++) wsum += w2[((size_t)oc * 32 + ic) * 9 + k];
        s = fmaf(wsum, r, s);
    }
    float bg = fmaxf(s, 0.f);
    for (int b = 0; b < 16; b++) {
        float* dst = zc + ((size_t)b * 128 + oc) * 4096;
        for (int i = threadIdx.x; i < 4096; i += 256) dst[i] = bg;
    }
}

// ====================================================================
// Encoder stage 1: conv3x3 (1 -> CO) + relu + maxpool2, tile offset.
// ====================================================================
template<int CO, bool MASK>
__global__ __launch_bounds__(256) void k_enc1(const float* __restrict__ x,
    const float* __restrict__ w, const float* __restrict__ bias,
    float* __restrict__ out, int offX, int offY)
{
    __shared__ float tile[34][36];
    __shared__ float sw[CO * 9];
    __shared__ float sb[CO];
    const int t  = threadIdx.x;
    const int b  = blockIdx.z;
    const int Y0 = (blockIdx.y + offY) * 32;
    const int X0 = (blockIdx.x + offX) * 32;
    const float* xb = x + (size_t)b * 65536;
    for (int i = t; i < 34 * 34; i += 256) {
        int r = i / 34, c = i % 34;
        int gy = Y0 + r - 1, gx = X0 + c - 1;
        bool ok = (gy >= 0 && gy < 256 && gx >= 0 && gx < 256);
        if (MASK) ok = ok && (gy >= 96 && gy < 160 && gx >= 96 && gx < 160);
        tile[r][c] = ok ? xb[gy * 256 + gx] : 0.f;
    }
    for (int i = t; i < CO * 9; i += 256) sw[i] = w[i];
    if (t < CO) sb[t] = bias[t];
    __syncthreads();
    const int ty = t >> 4, tx = t & 15;
    float p[4][4];
#pragma unroll
    for (int i = 0; i < 4; i++)
#pragma unroll
        for (int j = 0; j < 4; j++) p[i][j] = tile[2 * ty + i][2 * tx + j];
    const int py = (blockIdx.y + offY) * 16 + ty, px = (blockIdx.x + offX) * 16 + tx;
    float* ob = out + (size_t)b * CO * 128 * 128 + py * 128 + px;
#pragma unroll 4
    for (int oc = 0; oc < CO; oc++) {
        float w9[9];
#pragma unroll
        for (int k = 0; k < 9; k++) w9[k] = sw[oc * 9 + k];
        float bv = sb[oc];
        float m = -INFINITY;
#pragma unroll
        for (int i = 0; i < 2; i++)
#pragma unroll
            for (int j = 0; j < 2; j++) {
                float s = bv;
#pragma unroll
                for (int dy = 0; dy < 3; dy++)
#pragma unroll
                    for (int dx = 0; dx < 3; dx++)
                        s = fmaf(w9[dy * 3 + dx], p[i + dy][j + dx], s);
                m = fmaxf(m, fmaxf(s, 0.f));
            }
        ob[(size_t)oc * 128 * 128] = m;
    }
}

// ====================================================================
// conv3x3 pad1, OIHW weights. 32x32 output tile, 2x2 px per thread,
// IC chunks of 4, optional relu, optional fused 2x2 maxpool.
// grid: x = W/32 (minus offset), y = tilesY*(OC/OCB), z = B
// ====================================================================
template<int OCB, bool RELU, bool POOL>
__global__ __launch_bounds__(256) void k_conv3b(const float* __restrict__ in,
    const float* __restrict__ w, const float* __restrict__ bias,
    float* __restrict__ out, int IC, int OC, int H, int W, int tilesY,
    int offX, int offY)
{
    __shared__ float tin[4][34][36];
    __shared__ float sw[OCB][4][9];
    const int tY = blockIdx.y % tilesY;
    const int ob = blockIdx.y / tilesY;
    const int Y0 = (tY + offY) * 32;
    const int X0 = (blockIdx.x + offX) * 32;
    const int b  = blockIdx.z;
    const int tid = threadIdx.x;
    const int ty = tid >> 4, tx = tid & 15;
    float acc[OCB][2][2];
#pragma unroll
    for (int o = 0; o < OCB; o++)
#pragma unroll
        for (int e = 0; e < 2; e++)
#pragma unroll
            for (int f = 0; f < 2; f++) acc[o][e][f] = 0.f;
    const float* inb = in + (size_t)b * IC * H * W;
    for (int ic0 = 0; ic0 < IC; ic0 += 4) {
        __syncthreads();
        for (int i = tid; i < 4 * 34 * 34; i += 256) {
            int ic = i / (34 * 34); int rem = i % (34 * 34);
            int r = rem / 34, c = rem % 34;
            int gy = Y0 + r - 1, gx = X0 + c - 1;
            float v = 0.f;
            if (gy >= 0 && gy < H && gx >= 0 && gx < W)
                v = inb[(size_t)(ic0 + ic) * H * W + gy * W + gx];
            tin[ic][r][c] = v;
        }
        for (int i = tid; i < OCB * 4 * 9; i += 256) {
            int o = i / 36; int rem = i % 36; int ic = rem / 9; int k = rem % 9;
            sw[o][ic][k] = w[((size_t)(ob * OCB + o) * IC + ic0 + ic) * 9 + k];
        }
        __syncthreads();
#pragma unroll
        for (int ic = 0; ic < 4; ic++) {
            float p[4][4];
#pragma unroll
            for (int i = 0; i < 4; i++)
#pragma unroll
                for (int j = 0; j < 4; j++)
                    p[i][j] = tin[ic][2 * ty + i][2 * tx + j];
#pragma unroll
            for (int o = 0; o < OCB; o++) {
                float w9[9];
#pragma unroll
                for (int k = 0; k < 9; k++) w9[k] = sw[o][ic][k];
#pragma unroll
                for (int e = 0; e < 2; e++)
#pragma unroll
                    for (int f = 0; f < 2; f++) {
                        float s = acc[o][e][f];
#pragma unroll
                        for (int dy = 0; dy < 3; dy++)
#pragma unroll
                            for (int dx = 0; dx < 3; dx++)
                                s = fmaf(w9[dy * 3 + dx], p[e + dy][f + dx], s);
                        acc[o][e][f] = s;
                    }
            }
        }
    }
#pragma unroll
    for (int o = 0; o < OCB; o++) {
        int oc = ob * OCB + o;
        float bv = bias[oc];
        if (POOL) {
            float m = -INFINITY;
#pragma unroll
            for (int e = 0; e < 2; e++)
#pragma unroll
                for (int f = 0; f < 2; f++)
                    m = fmaxf(m, fmaxf(acc[o][e][f] + bv, 0.f));
            int Ho = H >> 1, Wo = W >> 1;
            out[((size_t)((size_t)b * OC + oc) * Ho + ((Y0 >> 1) + ty)) * Wo
                + (X0 >> 1) + tx] = m;
        } else {
#pragma unroll
            for (int e = 0; e < 2; e++) {
                float v0 = acc[o][e][0] + bv, v1 = acc[o][e][1] + bv;
                if (RELU) { v0 = fmaxf(v0, 0.f); v1 = fmaxf(v1, 0.f); }
                *(float2*)(out + ((size_t)((size_t)b * OC + oc) * H + (Y0 + 2 * ty + e)) * W
                               + X0 + 2 * tx) = make_float2(v0, v1);
            }
        }
    }
}

// ====================================================================
// Per-(b,n) L2 norm scale of zc over C=128
// ====================================================================
__global__ void k_rowscale(const float* __restrict__ zc, float* __restrict__ scale)
{
    __shared__ float part[8][32];
    const int tid = threadIdx.x;
    const int r0 = blockIdx.x * 32;
    const int b  = r0 >> 12;
    const int n0 = r0 & 4095;
    const int nx = tid & 31, cy = tid >> 5;
    const float* base = zc + (size_t)b * 128 * 4096 + n0 + nx;
    float s = 0.f;
#pragma unroll
    for (int j = 0; j < 16; j++) {
        float v = base[(size_t)(cy + 8 * j) * 4096];
        s = fmaf(v, v, s);
    }
    part[cy][nx] = s;
    __syncthreads();
    if (cy == 0) {
        float t = 0.f;
#pragma unroll
        for (int j = 0; j < 8; j++) t += part[j][nx];
        scale[r0 + nx] = 1.0f / fmaxf(sqrtf(t), 1e-12f);
    }
}

// ====================================================================
// SGEMM: S[b*4096+n][m] = sum_c A[b][c][n] * Bm[c][m]
// Tile 128(n) x 64(m), K chunks 16, 8x4 micro-tile.
// grid: x = 13 (m), y = 32 (n), z = 16
// ====================================================================
__global__ __launch_bounds__(256) void k_gemm(const float* __restrict__ A,
    const float* __restrict__ Bm, float* __restrict__ S)
{
    __shared__ float As[16][128];
    __shared__ float Bs[16][64];
    const int b  = blockIdx.z;
    const int n0 = blockIdx.y * 128;
    const int m0 = blockIdx.x * 64;
    const int tid = threadIdx.x;
    const int tm = tid & 15, tn = tid >> 4;
    float acc[8][4];
#pragma unroll
    for (int i = 0; i < 8; i++)
#pragma unroll
        for (int j = 0; j < 4; j++) acc[i][j] = 0.f;
    const float* Ab = A + (size_t)b * 128 * 4096;
    const int lkA = tid >> 4, lnA = (tid * 8) & 127;
    const int lkB = tid >> 4, lmB = (tid * 4) & 63;
    for (int k0 = 0; k0 < 128; k0 += 16) {
        __syncthreads();
        const float* arow = &Ab[(size_t)(k0 + lkA) * 4096 + n0 + lnA];
        *(float4*)&As[lkA][lnA]     = *(const float4*)arow;
        *(float4*)&As[lkA][lnA + 4] = *(const float4*)(arow + 4);
        float4 bv = make_float4(0.f, 0.f, 0.f, 0.f);
        if (m0 + lmB < 800)
            bv = *(const float4*)&Bm[(size_t)(k0 + lkB) * 800 + m0 + lmB];
        *(float4*)&Bs[lkB][lmB] = bv;
        __syncthreads();
#pragma unroll
        for (int k = 0; k < 16; k++) {
            float4 a0 = *(float4*)&As[k][tn * 8];
            float4 a1 = *(float4*)&As[k][tn * 8 + 4];
            float4 bb = *(float4*)&Bs[k][tm * 4];
            float av[8] = {a0.x, a0.y, a0.z, a0.w, a1.x, a1.y, a1.z, a1.w};
#pragma unroll
            for (int i = 0; i < 8; i++) {
                acc[i][0] = fmaf(av[i], bb.x, acc[i][0]);
                acc[i][1] = fmaf(av[i], bb.y, acc[i][1]);
                acc[i][2] = fmaf(av[i], bb.z, acc[i][2]);
                acc[i][3] = fmaf(av[i], bb.w, acc[i][3]);
            }
        }
    }
    const int m = m0 + tm * 4;
    if (m < 800) {
#pragma unroll
        for (int i = 0; i < 8; i++) {
            size_t row = (size_t)b * 4096 + n0 + tn * 8 + i;
            *(float4*)&S[row * 800 + m] =
                make_float4(acc[i][0], acc[i][1], acc[i][2], acc[i][3]);
        }
    }
}

// ====================================================================
// Top-10 + scaled softmax (one warp per row, stable tie-break)
// ====================================================================
__global__ void k_topk(const float* __restrict__ S, const float* __restrict__ scale,
                       int* __restrict__ tidx, float* __restrict__ tw)
{
    int gw = (blockIdx.x * blockDim.x + threadIdx.x) >> 5;
    int lane = threadIdx.x & 31;
    if (gw >= 65536) return;
    const float* row = S + (size_t)gw * 800;
    float lv[10]; int li[10];
#pragma unroll
    for (int j = 0; j < 10; j++) { lv[j] = -INFINITY; li[j] = 0x7fffffff; }
    for (int t = 0; t < 25; t++) {
        int m = lane + 32 * t;
        float v = row[m];
        int i = m;
#pragma unroll
        for (int j = 0; j < 10; j++) {
            bool better = (v > lv[j]) || (v == lv[j] && i < li[j]);
            if (better) {
                float tv = lv[j]; lv[j] = v; v = tv;
                int ti = li[j]; li[j] = i; i = ti;
            }
        }
    }
    float bv[10]; int bi[10];
#pragma unroll
    for (int k = 0; k < 10; k++) {
        float cv = lv[0]; int ci = li[0];
#pragma unroll
        for (int off = 16; off > 0; off >>= 1) {
            float ov = __shfl_xor_sync(0xffffffffu, cv, off);
            int   oi = __shfl_xor_sync(0xffffffffu, ci, off);
            if (ov > cv || (ov == cv && oi < ci)) { cv = ov; ci = oi; }
        }
        bv[k] = cv; bi[k] = ci;
        if (lv[0] == cv && li[0] == ci) {
#pragma unroll
            for (int j = 0; j < 9; j++) { lv[j] = lv[j + 1]; li[j] = li[j + 1]; }
            lv[9] = -INFINITY; li[9] = 0x7fffffff;
        }
    }
    if (lane == 0) {
        float sc = scale[gw];
        float mx = bv[0] * sc;
        float e[10], sum = 0.f;
#pragma unroll
        for (int k = 0; k < 10; k++) { e[k] = expf(bv[k] * sc - mx); sum += e[k]; }
        float inv = 1.0f / sum;
#pragma unroll
        for (int k = 0; k < 10; k++) {
            tidx[gw * 10 + k] = bi[k];
            tw[gw * 10 + k]   = e[k] * inv;
        }
    }
}

// ====================================================================
// Argmax over 800 (first-max tie-break)
// ====================================================================
__global__ void k_argmax(const float* __restrict__ S, int* __restrict__ amax)
{
    int gw = (blockIdx.x * blockDim.x + threadIdx.x) >> 5;
    int lane = threadIdx.x & 31;
    if (gw >= 65536) return;
    const float* row = S + (size_t)gw * 800;
    float bv = -INFINITY; int bi = 0x7fffffff;
    for (int t = 0; t < 25; t++) {
        int m = lane + 32 * t;
        float v = row[m];
        if (v > bv || (v == bv && m < bi)) { bv = v; bi = m; }
    }
#pragma unroll
    for (int off = 16; off > 0; off >>= 1) {
        float ov = __shfl_xor_sync(0xffffffffu, bv, off);
        int   oi = __shfl_xor_sync(0xffffffffu, bi, off);
        if (ov > bv || (ov == bv && oi < bi)) { bv = ov; bi = oi; }
    }
    if (lane == 0) amax[gw] = bi;
}

// ====================================================================
// Weighted top-k gather -> zm channels [0,128)
// ====================================================================
__global__ void k_gatherC(const float* __restrict__ vals, const int* __restrict__ tidx,
                          const float* __restrict__ tw, float* __restrict__ zm)
{
    __shared__ int   sidx[8][10];
    __shared__ float swt [8][10];
    const int r0 = blockIdx.x * 8;
    const int tid = threadIdx.x;
    if (tid < 80) {
        int ny = tid / 10, k = tid % 10;
        sidx[ny][k] = tidx[(size_t)(r0 + ny) * 10 + k];
        swt [ny][k] = tw  [(size_t)(r0 + ny) * 10 + k];
    }
    __syncthreads();
    const int cx = tid & 31, ny = tid >> 5;
    const int row = r0 + ny;
    const int b = row >> 12, n = row & 4095;
#pragma unroll
    for (int cc = 0; cc < 4; cc++) {
        int c = cx + 32 * cc;
        float acc = 0.f;
#pragma unroll
        for (int k = 0; k < 10; k++)
            acc = fmaf(vals[(size_t)sidx[ny][k] * 128 + c], swt[ny][k], acc);
        zm[((size_t)b * 256 + c) * 4096 + n] = acc;
    }
}

// ====================================================================
// Hard gather -> zm channels [128,256)
// ====================================================================
__global__ void k_gatherS(const float* __restrict__ hard, const int* __restrict__ amax,
                          float* __restrict__ zm)
{
    const int r0 = blockIdx.x * 8;
    const int tid = threadIdx.x;
    const int cx = tid & 31, ny = tid >> 5;
    const int row = r0 + ny;
    const int b = row >> 12, n = row & 4095;
    const int a = amax[row];
#pragma unroll
    for (int cc = 0; cc < 4; cc++) {
        int c = cx + 32 * cc;
        zm[((size_t)b * 256 + 128 + c) * 4096 + n] = hard[(size_t)a * 128 + c];
    }
}

// ====================================================================
// Transposed conv (k=4, s=2) + relu. 64x64 output tile, 2x2 quads
// (= 4x4 output px) per thread, IC chunks of 2, OCB output channels.
// grid: x = Ho/64, y = (Ho/64)*(OC/OCB), z = B
// ====================================================================
template<int IC, int OC, int OCB>
__global__ __launch_bounds__(256) void k_deconv(const float* __restrict__ in,
    const float* __restrict__ w, const float* __restrict__ bias,
    float* __restrict__ out, int Hi, int tilesY)
{
    __shared__ float tin[2][34][36];
    __shared__ float sw[2][OCB][16];
    const int Ho = 2 * Hi;
    const int tY = blockIdx.y % tilesY;
    const int ob = blockIdx.y / tilesY;
    const int b  = blockIdx.z;
    const int Xo0 = blockIdx.x * 64, Yo0 = tY * 64;
    const int a0 = Yo0 >> 1, c0 = Xo0 >> 1;
    const int tid = threadIdx.x;
    const int ty = tid >> 4, tx = tid & 15;
    float acc[OCB][4][4];
#pragma unroll
    for (int o = 0; o < OCB; o++)
#pragma unroll
        for (int r = 0; r < 4; r++)
#pragma unroll
            for (int c = 0; c < 4; c++) acc[o][r][c] = 0.f;
    const float* inb = in + (size_t)b * IC * Hi * Hi;
    for (int ic0 = 0; ic0 < IC; ic0 += 2) {
        __syncthreads();
        for (int i = tid; i < 2 * 34 * 34; i += 256) {
            int ic = i / (34 * 34); int rem = i % (34 * 34);
            int r = rem / 34, c = rem % 34;
            int gy = a0 + r - 1, gx = c0 + c - 1;
            float v = 0.f;
            if (gy >= 0 && gy < Hi && gx >= 0 && gx < Hi)
                v = inb[(size_t)(ic0 + ic) * Hi * Hi + gy * Hi + gx];
            tin[ic][r][c] = v;
        }
        for (int i = tid; i < 2 * OCB * 16; i += 256) {
            int ic = i / (OCB * 16); int rem = i % (OCB * 16);
            int o = rem / 16; int t = rem % 16;
            sw[ic][o][t] = w[((size_t)(ic0 + ic) * OC + ob * OCB + o) * 16 + t];
        }
        __syncthreads();
#pragma unroll
        for (int ic = 0; ic < 2; ic++) {
            float p[4][4];
#pragma unroll
            for (int i = 0; i < 4; i++)
#pragma unroll
                for (int j = 0; j < 4; j++)
                    p[i][j] = tin[ic][2 * ty + i][2 * tx + j];
#pragma unroll
            for (int o = 0; o < OCB; o++) {
                float W4[16];
#pragma unroll
                for (int t = 0; t < 16; t++) W4[t] = sw[ic][o][t];
#pragma unroll
                for (int e = 0; e < 2; e++)
#pragma unroll
                    for (int f = 0; f < 2; f++) {
                        float P00 = p[e][f],     P01 = p[e][f + 1],     P02 = p[e][f + 2];
                        float P10 = p[e + 1][f], P11 = p[e + 1][f + 1], P12 = p[e + 1][f + 2];
                        float P20 = p[e + 2][f], P21 = p[e + 2][f + 1], P22 = p[e + 2][f + 2];
                        acc[o][2 * e][2 * f]         += W4[15] * P00 + W4[13] * P01 + W4[7] * P10 + W4[5] * P11;
                        acc[o][2 * e][2 * f + 1]     += W4[14] * P01 + W4[12] * P02 + W4[6] * P11 + W4[4] * P12;
                        acc[o][2 * e + 1][2 * f]     += W4[11] * P10 + W4[9]  * P11 + W4[3] * P20 + W4[1] * P21;
                        acc[o][2 * e + 1][2 * f + 1] += W4[10] * P11 + W4[8]  * P12 + W4[2] * P21 + W4[0] * P22;
                    }
            }
        }
    }
#pragma unroll
    for (int o = 0; o < OCB; o++) {
        int oc = ob * OCB + o;
        float bv = bias[oc];
#pragma unroll
        for (int r = 0; r < 4; r++)
#pragma unroll
            for (int c = 0; c < 4; c += 2) {
                float v0 = fmaxf(acc[o][r][c] + bv, 0.f);
                float v1 = fmaxf(acc[o][r][c + 1] + bv, 0.f);
                *(float2*)(out + ((size_t)((size_t)b * OC + oc) * Ho + (Yo0 + 4 * ty + r)) * Ho
                               + Xo0 + 4 * tx + c) = make_float2(v0, v1);
            }
    }
}

// ====================================================================
// Host launcher
// ====================================================================
extern "C" void kernel_launch(void* const* d_in, const int* in_sizes, int n_in,
                              void* d_out, int out_size)
{
    const float* x        = (const float*)d_in[0];
    const float* ce_w1    = (const float*)d_in[1];
    const float* ce_b1    = (const float*)d_in[2];
    const float* ce_w2    = (const float*)d_in[3];
    const float* ce_b2    = (const float*)d_in[4];
    const float* se_w1    = (const float*)d_in[5];
    const float* se_b1    = (const float*)d_in[6];
    const float* se_w2    = (const float*)d_in[7];
    const float* se_b2    = (const float*)d_in[8];
    const float* mem_keys = (const float*)d_in[9];
    const float* mem_vals = (const float*)d_in[10];
    const float* mem_hard = (const float*)d_in[11];
    const float* dec_w1   = (const float*)d_in[12];
    const float* dec_b1   = (const float*)d_in[13];
    const float* dec_tw1  = (const float*)d_in[14];
    const float* dec_tb1  = (const float*)d_in[15];
    const float* dec_tw2  = (const float*)d_in[16];
    const float* dec_tb2  = (const float*)d_in[17];
    const float* dec_w2   = (const float*)d_in[18];
    const float* dec_b2   = (const float*)d_in[19];
    float* outp = (float*)d_out;

    float *knT, *hnT, *A, *zc, *zs, *scale, *S, *tw, *zm, *d1, *u1, *u2;
    int *tidx, *amax;
    cudaGetSymbolAddress((void**)&knT,   g_knT);
    cudaGetSymbolAddress((void**)&hnT,   g_hnT);
    cudaGetSymbolAddress((void**)&A,     g_A);
    cudaGetSymbolAddress((void**)&zc,    g_zc);
    cudaGetSymbolAddress((void**)&zs,    g_zs);
    cudaGetSymbolAddress((void**)&scale, g_scale);
    cudaGetSymbolAddress((void**)&S,     g_S);
    cudaGetSymbolAddress((void**)&tidx,  g_tidx);
    cudaGetSymbolAddress((void**)&tw,    g_tw);
    cudaGetSymbolAddress((void**)&amax,  g_amax);
    cudaGetSymbolAddress((void**)&zm,    g_zm);
    cudaGetSymbolAddress((void**)&d1,    g_d1);
    cudaGetSymbolAddress((void**)&u1,    g_u1);
    cudaGetSymbolAddress((void**)&u2,    g_u2);

    k_normrows<<<200, 256>>>(mem_keys, mem_hard, knT, hnT);

    // ---- center encoder (active-region only; background analytic) ----
    k_fillA<<<(16 * 32 * 16384) / 256, 256>>>(A, ce_b1);
    k_enc1<32, true><<<dim3(4, 4, 16), 256>>>(x, ce_w1, ce_b1, A, 2, 2);
    k_fillzc<<<128, 256>>>(zc, ce_w2, ce_b1, ce_b2);
    k_conv3b<16, true, true><<<dim3(2, 2 * 8, 16), 256>>>(
        A, ce_w2, ce_b2, zc, 32, 128, 128, 128, 2, 1, 1);

    // ---- skip encoder (full) ----
    k_enc1<16, false><<<dim3(8, 8, 16), 256>>>(x, se_w1, se_b1, A, 0, 0);
    k_conv3b<16, true, true><<<dim3(4, 4 * 8, 16), 256>>>(
        A, se_w2, se_b2, zs, 16, 128, 128, 128, 4, 0, 0);

    // ---- center memory matching ----
    k_rowscale<<<2048, 256>>>(zc, scale);
    k_gemm<<<dim3(13, 32, 16), 256>>>(zc, knT, S);
    k_topk<<<8192, 256>>>(S, scale, tidx, tw);
    k_gatherC<<<8192, 256>>>(mem_vals, tidx, tw, zm);

    // ---- skip memory matching ----
    k_gemm<<<dim3(13, 32, 16), 256>>>(zs, hnT, S);
    k_argmax<<<8192, 256>>>(S, amax);
    k_gatherS<<<8192, 256>>>(mem_hard, amax, zm);

    // ---- decoder ----
    k_conv3b<16, true, false><<<dim3(2, 2 * 4, 16), 256>>>(
        zm, dec_w1, dec_b1, d1, 256, 64, 64, 64, 2, 0, 0);
    k_deconv<64, 32, 4><<<dim3(2, 2 * 8, 16), 256>>>(d1, dec_tw1, dec_tb1, u1, 64, 2);
    k_deconv<32, 16, 4><<<dim3(4, 4 * 4, 16), 256>>>(u1, dec_tw2, dec_tb2, u2, 128, 4);
    k_conv3b<1, false, false><<<dim3(8, 8, 16), 256>>>(
        u2, dec_w2, dec_b2, outp, 16, 1, 256, 256, 8, 0, 0);
}

// round 7
// speedup vs baseline: 1.3519x; 1.1446x over previous
#include <cuda_runtime.h>
#include <math.h>
#include <stdint.h>

// ====================================================================
// Static device scratch
// ====================================================================
__device__ __align__(256) float g_knT[128 * 800];
__device__ __align__(256) float g_hnT[128 * 800];
__device__ __align__(256) float g_A  [16 * 32 * 128 * 128];
__device__ __align__(256) float g_zc [16 * 128 * 64 * 64];
__device__ __align__(256) float g_zs [16 * 128 * 64 * 64];
__device__ __align__(256) float g_Sact[16 * 384 * 800];
__device__ __align__(256) int   g_tidx[16 * 324 * 10];
__device__ __align__(256) float g_tw  [16 * 324 * 10];
__device__ __align__(256) int   g_amax[65536];
__device__ __align__(256) float g_bgz [128];
__device__ __align__(256) float g_zm [16 * 256 * 64 * 64];
__device__ __align__(256) float g_d1 [16 * 64 * 64 * 64];
__device__ __align__(256) float g_u1 [16 * 32 * 128 * 128];
__device__ __align__(256) float g_u2 [16 * 16 * 256 * 256];

// ====================================================================
// Normalize memory rows -> transposed tables knT[c][m], hnT[c][m]
// ====================================================================
__global__ void k_normrows(const float* __restrict__ keys,
                           const float* __restrict__ hard,
                           float* __restrict__ knT, float* __restrict__ hnT)
{
    int gw = (blockIdx.x * blockDim.x + threadIdx.x) >> 5;
    int lane = threadIdx.x & 31;
    if (gw >= 1600) return;
    const float* src; float* dst; int r;
    if (gw < 800) { src = keys; dst = knT; r = gw; }
    else          { src = hard; dst = hnT; r = gw - 800; }
    float4 v = *(const float4*)(src + (size_t)r * 128 + lane * 4);
    float s = v.x * v.x + v.y * v.y + v.z * v.z + v.w * v.w;
#pragma unroll
    for (int o = 16; o > 0; o >>= 1) s += __shfl_xor_sync(0xffffffffu, s, o);
    float d = 1.0f / fmaxf(sqrtf(s), 1e-12f);
    dst[(size_t)(4 * lane + 0) * 800 + r] = v.x * d;
    dst[(size_t)(4 * lane + 1) * 800 + r] = v.y * d;
    dst[(size_t)(4 * lane + 2) * 800 + r] = v.z * d;
    dst[(size_t)(4 * lane + 3) * 800 + r] = v.w * d;
}

// ====================================================================
// Background z_match: bgc -> scores -> topk -> softmax -> gather (1 block)
// ====================================================================
__global__ __launch_bounds__(256) void k_bg(const float* __restrict__ w2,
    const float* __restrict__ b1, const float* __restrict__ b2,
    const float* __restrict__ knT, const float* __restrict__ vals,
    float* __restrict__ bgz)
{
    __shared__ float bgc[128];
    __shared__ float sc[800];
    __shared__ int   swidx[10];
    __shared__ float sww[10];
    const int tid = threadIdx.x;
    if (tid < 128) {
        float s = b2[tid];
        for (int ic = 0; ic < 32; ic++) {
            float wsum = 0.f;
#pragma unroll
            for (int k = 0; k < 9; k++) wsum += w2[((size_t)tid * 32 + ic) * 9 + k];
            s = fmaf(wsum, fmaxf(b1[ic], 0.f), s);
        }
        bgc[tid] = fmaxf(s, 0.f);
    }
    __syncthreads();
    for (int m = tid; m < 800; m += 256) {
        float s = 0.f;
#pragma unroll 8
        for (int c = 0; c < 128; c++) s = fmaf(bgc[c], knT[(size_t)c * 800 + m], s);
        sc[m] = s;
    }
    __syncthreads();
    if (tid < 32) {
        const int lane = tid;
        float ss = 0.f;
#pragma unroll
        for (int j = 0; j < 4; j++) { float v = bgc[lane * 4 + j]; ss = fmaf(v, v, ss); }
#pragma unroll
        for (int o = 16; o > 0; o >>= 1) ss += __shfl_xor_sync(0xffffffffu, ss, o);
        float scale = 1.0f / fmaxf(sqrtf(ss), 1e-12f);
        float lv[10]; int li[10];
#pragma unroll
        for (int j = 0; j < 10; j++) { lv[j] = -INFINITY; li[j] = 0x7fffffff; }
        for (int t = 0; t < 25; t++) {
            int m = lane + 32 * t;
            float v = sc[m];
            int i = m;
#pragma unroll
            for (int j = 0; j < 10; j++) {
                bool better = (v > lv[j]) || (v == lv[j] && i < li[j]);
                if (better) {
                    float tv = lv[j]; lv[j] = v; v = tv;
                    int ti = li[j]; li[j] = i; i = ti;
                }
            }
        }
        float bv[10]; int bi[10];
#pragma unroll
        for (int k = 0; k < 10; k++) {
            float cv = lv[0]; int ci = li[0];
#pragma unroll
            for (int off = 16; off > 0; off >>= 1) {
                float ov = __shfl_xor_sync(0xffffffffu, cv, off);
                int   oi = __shfl_xor_sync(0xffffffffu, ci, off);
                if (ov > cv || (ov == cv && oi < ci)) { cv = ov; ci = oi; }
            }
            bv[k] = cv; bi[k] = ci;
            if (lv[0] == cv && li[0] == ci) {
#pragma unroll
                for (int j = 0; j < 9; j++) { lv[j] = lv[j + 1]; li[j] = li[j + 1]; }
                lv[9] = -INFINITY; li[9] = 0x7fffffff;
            }
        }
        if (lane == 0) {
            float mx = bv[0] * scale;
            float e[10], sum = 0.f;
#pragma unroll
            for (int k = 0; k < 10; k++) { e[k] = expf(bv[k] * scale - mx); sum += e[k]; }
            float inv = 1.0f / sum;
#pragma unroll
            for (int k = 0; k < 10; k++) { swidx[k] = bi[k]; sww[k] = e[k] * inv; }
        }
    }
    __syncthreads();
    if (tid < 128) {
        float a = 0.f;
#pragma unroll
        for (int k = 0; k < 10; k++)
            a = fmaf(vals[(size_t)swidx[k] * 128 + tid], sww[k], a);
        bgz[tid] = a;
    }
}

// ====================================================================
// Fill zm center channels [0,128) with background z_match
// ====================================================================
__global__ void k_fillbg(float* __restrict__ zm, const float* __restrict__ bgz)
{
    int i = blockIdx.x * 256 + threadIdx.x;   // < 16*128*4096 = 2^23
    int c = (i >> 12) & 127;
    int b = i >> 19;
    zm[((size_t)b * 256 + c) * 4096 + (i & 4095)] = __ldg(&bgz[c]);
}

// ====================================================================
// Fill A (enc1-center out) with relu(b1[c])
// ====================================================================
__global__ void k_fillA(float* __restrict__ A, const float* __restrict__ b1)
{
    int i = blockIdx.x * blockDim.x + threadIdx.x;   // < 16*32*16384
    int c = (i >> 14) & 31;
    A[i] = fmaxf(b1[c], 0.f);
}

// ====================================================================
// Encoder stage 1: conv3x3 (1 -> CO) + relu + maxpool2, tile offset.
// ====================================================================
template<int CO, bool MASK>
__global__ __launch_bounds__(256) void k_enc1(const float* __restrict__ x,
    const float* __restrict__ w, const float* __restrict__ bias,
    float* __restrict__ out, int offX, int offY)
{
    __shared__ float tile[34][36];
    __shared__ float sw[CO * 9];
    __shared__ float sb[CO];
    const int t  = threadIdx.x;
    const int b  = blockIdx.z;
    const int Y0 = (blockIdx.y + offY) * 32;
    const int X0 = (blockIdx.x + offX) * 32;
    const float* xb = x + (size_t)b * 65536;
    for (int i = t; i < 34 * 34; i += 256) {
        int r = i / 34, c = i % 34;
        int gy = Y0 + r - 1, gx = X0 + c - 1;
        bool ok = (gy >= 0 && gy < 256 && gx >= 0 && gx < 256);
        if (MASK) ok = ok && (gy >= 96 && gy < 160 && gx >= 96 && gx < 160);
        tile[r][c] = ok ? xb[gy * 256 + gx] : 0.f;
    }
    for (int i = t; i < CO * 9; i += 256) sw[i] = w[i];
    if (t < CO) sb[t] = bias[t];
    __syncthreads();
    const int ty = t >> 4, tx = t & 15;
    float p[4][4];
#pragma unroll
    for (int i = 0; i < 4; i++)
#pragma unroll
        for (int j = 0; j < 4; j++) p[i][j] = tile[2 * ty + i][2 * tx + j];
    const int py = (blockIdx.y + offY) * 16 + ty, px = (blockIdx.x + offX) * 16 + tx;
    float* ob = out + (size_t)b * CO * 128 * 128 + py * 128 + px;
#pragma unroll 4
    for (int oc = 0; oc < CO; oc++) {
        float w9[9];
#pragma unroll
        for (int k = 0; k < 9; k++) w9[k] = sw[oc * 9 + k];
        float bv = sb[oc];
        float m = -INFINITY;
#pragma unroll
        for (int i = 0; i < 2; i++)
#pragma unroll
            for (int j = 0; j < 2; j++) {
                float s = bv;
#pragma unroll
                for (int dy = 0; dy < 3; dy++)
#pragma unroll
                    for (int dx = 0; dx < 3; dx++)
                        s = fmaf(w9[dy * 3 + dx], p[i + dy][j + dx], s);
                m = fmaxf(m, fmaxf(s, 0.f));
            }
        ob[(size_t)oc * 128 * 128] = m;
    }
}

// ====================================================================
// conv3x3 pad1, OIHW weights. 32x32 output tile, 2x2 px per thread,
// IC chunks of 4, optional relu, optional fused 2x2 maxpool.
// ====================================================================
template<int OCB, bool RELU, bool POOL>
__global__ __launch_bounds__(256) void k_conv3b(const float* __restrict__ in,
    const float* __restrict__ w, const float* __restrict__ bias,
    float* __restrict__ out, int IC, int OC, int H, int W, int tilesY,
    int offX, int offY)
{
    __shared__ float tin[4][34][36];
    __shared__ float sw[OCB][4][9];
    const int tY = blockIdx.y % tilesY;
    const int ob = blockIdx.y / tilesY;
    const int Y0 = (tY + offY) * 32;
    const int X0 = (blockIdx.x + offX) * 32;
    const int b  = blockIdx.z;
    const int tid = threadIdx.x;
    const int ty = tid >> 4, tx = tid & 15;
    float acc[OCB][2][2];
#pragma unroll
    for (int o = 0; o < OCB; o++)
#pragma unroll
        for (int e = 0; e < 2; e++)
#pragma unroll
            for (int f = 0; f < 2; f++) acc[o][e][f] = 0.f;
    const float* inb = in + (size_t)b * IC * H * W;
    for (int ic0 = 0; ic0 < IC; ic0 += 4) {
        __syncthreads();
        for (int i = tid; i < 4 * 34 * 34; i += 256) {
            int ic = i / (34 * 34); int rem = i % (34 * 34);
            int r = rem / 34, c = rem % 34;
            int gy = Y0 + r - 1, gx = X0 + c - 1;
            float v = 0.f;
            if (gy >= 0 && gy < H && gx >= 0 && gx < W)
                v = inb[(size_t)(ic0 + ic) * H * W + gy * W + gx];
            tin[ic][r][c] = v;
        }
        for (int i = tid; i < OCB * 4 * 9; i += 256) {
            int o = i / 36; int rem = i % 36; int ic = rem / 9; int k = rem % 9;
            sw[o][ic][k] = w[((size_t)(ob * OCB + o) * IC + ic0 + ic) * 9 + k];
        }
        __syncthreads();
#pragma unroll
        for (int ic = 0; ic < 4; ic++) {
            float p[4][4];
#pragma unroll
            for (int i = 0; i < 4; i++)
#pragma unroll
                for (int j = 0; j < 4; j++)
                    p[i][j] = tin[ic][2 * ty + i][2 * tx + j];
#pragma unroll
            for (int o = 0; o < OCB; o++) {
                float w9[9];
#pragma unroll
                for (int k = 0; k < 9; k++) w9[k] = sw[o][ic][k];
#pragma unroll
                for (int e = 0; e < 2; e++)
#pragma unroll
                    for (int f = 0; f < 2; f++) {
                        float s = acc[o][e][f];
#pragma unroll
                        for (int dy = 0; dy < 3; dy++)
#pragma unroll
                            for (int dx = 0; dx < 3; dx++)
                                s = fmaf(w9[dy * 3 + dx], p[e + dy][f + dx], s);
                        acc[o][e][f] = s;
                    }
            }
        }
    }
#pragma unroll
    for (int o = 0; o < OCB; o++) {
        int oc = ob * OCB + o;
        float bv = bias[oc];
        if (POOL) {
            float m = -INFINITY;
#pragma unroll
            for (int e = 0; e < 2; e++)
#pragma unroll
                for (int f = 0; f < 2; f++)
                    m = fmaxf(m, fmaxf(acc[o][e][f] + bv, 0.f));
            int Ho = H >> 1, Wo = W >> 1;
            out[((size_t)((size_t)b * OC + oc) * Ho + ((Y0 >> 1) + ty)) * Wo
                + (X0 >> 1) + tx] = m;
        } else {
#pragma unroll
            for (int e = 0; e < 2; e++) {
                float v0 = acc[o][e][0] + bv, v1 = acc[o][e][1] + bv;
                if (RELU) { v0 = fmaxf(v0, 0.f); v1 = fmaxf(v1, 0.f); }
                *(float2*)(out + ((size_t)((size_t)b * OC + oc) * H + (Y0 + 2 * ty + e)) * W
                               + X0 + 2 * tx) = make_float2(v0, v1);
            }
        }
    }
}

// ====================================================================
// Center active GEMM: S_act[b*384+ai][m] = sum_c zc[b][c][n(ai)]*knT[c][m]
// ai in [0,324): n = (23+ai/18)*64 + 23+ai%18. Tile 128n x 64m, 8x4.
// grid (13, 3, 16)
// ====================================================================
__global__ __launch_bounds__(256) void k_gemm_act(const float* __restrict__ A,
    const float* __restrict__ Bm, float* __restrict__ S)
{
    __shared__ float As[16][128];
    __shared__ float Bs[16][64];
    __shared__ int   map[128];
    const int b  = blockIdx.z;
    const int n0 = blockIdx.y * 128;
    const int m0 = blockIdx.x * 64;
    const int tid = threadIdx.x;
    const int tm = tid & 15, tn = tid >> 4;
    if (tid < 128) {
        int ai = n0 + tid;
        map[tid] = (ai < 324) ? ((23 + ai / 18) * 64 + 23 + ai % 18) : (23 * 64 + 23);
    }
    float acc[8][4];
#pragma unroll
    for (int i = 0; i < 8; i++)
#pragma unroll
        for (int j = 0; j < 4; j++) acc[i][j] = 0.f;
    const float* Ab = A + (size_t)b * 128 * 4096;
    const int lkB = tid >> 4, lmB = (tid * 4) & 63;
    __syncthreads();
    for (int k0 = 0; k0 < 128; k0 += 16) {
        __syncthreads();
#pragma unroll
        for (int j = 0; j < 8; j++) {
            int idx = tid * 8 + j;
            int lk = idx >> 7, ln = idx & 127;
            As[lk][ln] = Ab[(size_t)(k0 + lk) * 4096 + map[ln]];
        }
        float4 bv = make_float4(0.f, 0.f, 0.f, 0.f);
        if (m0 + lmB < 800)
            bv = *(const float4*)&Bm[(size_t)(k0 + lkB) * 800 + m0 + lmB];
        *(float4*)&Bs[lkB][lmB] = bv;
        __syncthreads();
#pragma unroll
        for (int k = 0; k < 16; k++) {
            float4 a0 = *(float4*)&As[k][tn * 8];
            float4 a1 = *(float4*)&As[k][tn * 8 + 4];
            float4 bb = *(float4*)&Bs[k][tm * 4];
            float av[8] = {a0.x, a0.y, a0.z, a0.w, a1.x, a1.y, a1.z, a1.w};
#pragma unroll
            for (int i = 0; i < 8; i++) {
                acc[i][0] = fmaf(av[i], bb.x, acc[i][0]);
                acc[i][1] = fmaf(av[i], bb.y, acc[i][1]);
                acc[i][2] = fmaf(av[i], bb.z, acc[i][2]);
                acc[i][3] = fmaf(av[i], bb.w, acc[i][3]);
            }
        }
    }
    const int m = m0 + tm * 4;
    if (m < 800) {
#pragma unroll
        for (int i = 0; i < 8; i++) {
            size_t row = (size_t)b * 384 + n0 + tn * 8 + i;
            *(float4*)&S[row * 800 + m] =
                make_float4(acc[i][0], acc[i][1], acc[i][2], acc[i][3]);
        }
    }
}

// ====================================================================
// Active top-10 + softmax (scale computed inline from zc). 5184 warps.
// ====================================================================
__global__ void k_topk_act(const float* __restrict__ S, const float* __restrict__ zc,
                           int* __restrict__ tidx, float* __restrict__ tw)
{
    int gw = (blockIdx.x * blockDim.x + threadIdx.x) >> 5;
    int lane = threadIdx.x & 31;
    if (gw >= 16 * 324) return;
    const int b = gw / 324, ai = gw % 324;
    const int n = (23 + ai / 18) * 64 + 23 + ai % 18;
    // inline ||q||
    const float* zb = zc + (size_t)b * 128 * 4096 + n;
    float ss = 0.f;
#pragma unroll
    for (int j = 0; j < 4; j++) {
        float v = zb[(size_t)(lane + 32 * j) * 4096];
        ss = fmaf(v, v, ss);
    }
#pragma unroll
    for (int o = 16; o > 0; o >>= 1) ss += __shfl_xor_sync(0xffffffffu, ss, o);
    float sc = 1.0f / fmaxf(sqrtf(ss), 1e-12f);

    const float* row = S + (size_t)gw * 800 + (size_t)b * (384 - 324) * 800;
    // row index in S is b*384+ai: recompute directly
    row = S + ((size_t)b * 384 + ai) * 800;
    float lv[10]; int li[10];
#pragma unroll
    for (int j = 0; j < 10; j++) { lv[j] = -INFINITY; li[j] = 0x7fffffff; }
    for (int t = 0; t < 25; t++) {
        int m = lane + 32 * t;
        float v = row[m];
        int i = m;
#pragma unroll
        for (int j = 0; j < 10; j++) {
            bool better = (v > lv[j]) || (v == lv[j] && i < li[j]);
            if (better) {
                float tv = lv[j]; lv[j] = v; v = tv;
                int ti = li[j]; li[j] = i; i = ti;
            }
        }
    }
    float bv[10]; int bi[10];
#pragma unroll
    for (int k = 0; k < 10; k++) {
        float cv = lv[0]; int ci = li[0];
#pragma unroll
        for (int off = 16; off > 0; off >>= 1) {
            float ov = __shfl_xor_sync(0xffffffffu, cv, off);
            int   oi = __shfl_xor_sync(0xffffffffu, ci, off);
            if (ov > cv || (ov == cv && oi < ci)) { cv = ov; ci = oi; }
        }
        bv[k] = cv; bi[k] = ci;
        if (lv[0] == cv && li[0] == ci) {
#pragma unroll
            for (int j = 0; j < 9; j++) { lv[j] = lv[j + 1]; li[j] = li[j + 1]; }
            lv[9] = -INFINITY; li[9] = 0x7fffffff;
        }
    }
    if (lane == 0) {
        float mx = bv[0] * sc;
        float e[10], sum = 0.f;
#pragma unroll
        for (int k = 0; k < 10; k++) { e[k] = expf(bv[k] * sc - mx); sum += e[k]; }
        float inv = 1.0f / sum;
#pragma unroll
        for (int k = 0; k < 10; k++) {
            tidx[gw * 10 + k] = bi[k];
            tw[gw * 10 + k]   = e[k] * inv;
        }
    }
}

// ====================================================================
// Active weighted gather -> zm channels [0,128). 648 blocks x 8 rows.
// ====================================================================
__global__ void k_gatherC_act(const float* __restrict__ vals, const int* __restrict__ tidx,
                              const float* __restrict__ tw, float* __restrict__ zm)
{
    __shared__ int   sidx[8][10];
    __shared__ float swt [8][10];
    const int r0 = blockIdx.x * 8;
    const int tid = threadIdx.x;
    if (tid < 80) {
        int ny = tid / 10, k = tid % 10;
        sidx[ny][k] = tidx[(size_t)(r0 + ny) * 10 + k];
        swt [ny][k] = tw  [(size_t)(r0 + ny) * 10 + k];
    }
    __syncthreads();
    const int cx = tid & 31, ny = tid >> 5;
    const int row = r0 + ny;
    const int b = row / 324, ai = row % 324;
    const int n = (23 + ai / 18) * 64 + 23 + ai % 18;
#pragma unroll
    for (int cc = 0; cc < 4; cc++) {
        int c = cx + 32 * cc;
        float acc = 0.f;
#pragma unroll
        for (int k = 0; k < 10; k++)
            acc = fmaf(vals[(size_t)sidx[ny][k] * 128 + c], swt[ny][k], acc);
        zm[((size_t)b * 256 + c) * 4096 + n] = acc;
    }
}

// ====================================================================
// Skip GEMM + fused argmax. Tile 128n, m chunks of 128, 8x8 micro.
// grid (32 ntiles, 16 b). First-max tie-break (lower m wins).
// ====================================================================
__global__ __launch_bounds__(256) void k_gemm_amax(const float* __restrict__ A,
    const float* __restrict__ Bm, int* __restrict__ amax)
{
    __shared__ float As[16][128];
    __shared__ float Bs[16][128];
    __shared__ float rv[128][17];
    __shared__ int   ri[128][17];
    const int b  = blockIdx.y;
    const int n0 = blockIdx.x * 128;
    const int tid = threadIdx.x;
    const int tm = tid & 15, tn = tid >> 4;
    const int lk = tid >> 4, ln = (tid & 15) * 8;
    const float* Ab = A + (size_t)b * 128 * 4096;
    float bestv[8]; int besti[8];
#pragma unroll
    for (int i = 0; i < 8; i++) { bestv[i] = -INFINITY; besti[i] = 0x7fffffff; }
    for (int m0 = 0; m0 < 800; m0 += 128) {
        float acc[8][8];
#pragma unroll
        for (int i = 0; i < 8; i++)
#pragma unroll
            for (int j = 0; j < 8; j++) acc[i][j] = 0.f;
        for (int k0 = 0; k0 < 128; k0 += 16) {
            __syncthreads();
            const float* ap = &Ab[(size_t)(k0 + lk) * 4096 + n0 + ln];
            *(float4*)&As[lk][ln]     = *(const float4*)ap;
            *(float4*)&As[lk][ln + 4] = *(const float4*)(ap + 4);
            if (m0 + ln + 7 < 800) {
                const float* bp = &Bm[(size_t)(k0 + lk) * 800 + m0 + ln];
                *(float4*)&Bs[lk][ln]     = *(const float4*)bp;
                *(float4*)&Bs[lk][ln + 4] = *(const float4*)(bp + 4);
            } else {
#pragma unroll
                for (int j = 0; j < 8; j++)
                    Bs[lk][ln + j] = (m0 + ln + j < 800)
                        ? Bm[(size_t)(k0 + lk) * 800 + m0 + ln + j] : 0.f;
            }
            __syncthreads();
#pragma unroll
            for (int k = 0; k < 16; k++) {
                float4 a0 = *(float4*)&As[k][tn * 8];
                float4 a1 = *(float4*)&As[k][tn * 8 + 4];
                float4 b0 = *(float4*)&Bs[k][tm * 8];
                float4 b1 = *(float4*)&Bs[k][tm * 8 + 4];
                float av[8] = {a0.x, a0.y, a0.z, a0.w, a1.x, a1.y, a1.z, a1.w};
                float bw[8] = {b0.x, b0.y, b0.z, b0.w, b1.x, b1.y, b1.z, b1.w};
#pragma unroll
                for (int i = 0; i < 8; i++)
#pragma unroll
                    for (int j = 0; j < 8; j++)
                        acc[i][j] = fmaf(av[i], bw[j], acc[i][j]);
            }
        }
#pragma unroll
        for (int i = 0; i < 8; i++)
#pragma unroll
            for (int j = 0; j < 8; j++) {
                int m = m0 + tm * 8 + j;
                float v = acc[i][j];
                if (m < 800 && (v > bestv[i] || (v == bestv[i] && m < besti[i]))) {
                    bestv[i] = v; besti[i] = m;
                }
            }
    }
    __syncthreads();
#pragma unroll
    for (int i = 0; i < 8; i++) { rv[tn * 8 + i][tm] = bestv[i]; ri[tn * 8 + i][tm] = besti[i]; }
    __syncthreads();
    if (tid < 128) {
        float bv = -INFINITY; int bi = 0x7fffffff;
#pragma unroll
        for (int t = 0; t < 16; t++) {
            float v = rv[tid][t]; int i = ri[tid][t];
            if (v > bv || (v == bv && i < bi)) { bv = v; bi = i; }
        }
        amax[b * 4096 + n0 + tid] = bi;
    }
}

// ====================================================================
// Hard gather -> zm channels [128,256)
// ====================================================================
__global__ void k_gatherS(const float* __restrict__ hard, const int* __restrict__ amax,
                          float* __restrict__ zm)
{
    const int r0 = blockIdx.x * 8;
    const int tid = threadIdx.x;
    const int cx = tid & 31, ny = tid >> 5;
    const int row = r0 + ny;
    const int b = row >> 12, n = row & 4095;
    const int a = amax[row];
#pragma unroll
    for (int cc = 0; cc < 4; cc++) {
        int c = cx + 32 * cc;
        zm[((size_t)b * 256 + 128 + c) * 4096 + n] = hard[(size_t)a * 128 + c];
    }
}

// ====================================================================
// Transposed conv (k=4, s=2) + relu. 64x64 output tile, 4x4 px/thread.
// ====================================================================
template<int IC, int OC, int OCB>
__global__ __launch_bounds__(256) void k_deconv(const float* __restrict__ in,
    const float* __restrict__ w, const float* __restrict__ bias,
    float* __restrict__ out, int Hi, int tilesY)
{
    __shared__ float tin[2][34][36];
    __shared__ float sw[2][OCB][16];
    const int Ho = 2 * Hi;
    const int tY = blockIdx.y % tilesY;
    const int ob = blockIdx.y / tilesY;
    const int b  = blockIdx.z;
    const int Xo0 = blockIdx.x * 64, Yo0 = tY * 64;
    const int a0 = Yo0 >> 1, c0 = Xo0 >> 1;
    const int tid = threadIdx.x;
    const int ty = tid >> 4, tx = tid & 15;
    float acc[OCB][4][4];
#pragma unroll
    for (int o = 0; o < OCB; o++)
#pragma unroll
        for (int r = 0; r < 4; r++)
#pragma unroll
            for (int c = 0; c < 4; c++) acc[o][r][c] = 0.f;
    const float* inb = in + (size_t)b * IC * Hi * Hi;
    for (int ic0 = 0; ic0 < IC; ic0 += 2) {
        __syncthreads();
        for (int i = tid; i < 2 * 34 * 34; i += 256) {
            int ic = i / (34 * 34); int rem = i % (34 * 34);
            int r = rem / 34, c = rem % 34;
            int gy = a0 + r - 1, gx = c0 + c - 1;
            float v = 0.f;
            if (gy >= 0 && gy < Hi && gx >= 0 && gx < Hi)
                v = inb[(size_t)(ic0 + ic) * Hi * Hi + gy * Hi + gx];
            tin[ic][r][c] = v;
        }
        for (int i = tid; i < 2 * OCB * 16; i += 256) {
            int ic = i / (OCB * 16); int rem = i % (OCB * 16);
            int o = rem / 16; int t = rem % 16;
            sw[ic][o][t] = w[((size_t)(ic0 + ic) * OC + ob * OCB + o) * 16 + t];
        }
        __syncthreads();
#pragma unroll
        for (int ic = 0; ic < 2; ic++) {
            float p[4][4];
#pragma unroll
            for (int i = 0; i < 4; i++)
#pragma unroll
                for (int j = 0; j < 4; j++)
                    p[i][j] = tin[ic][2 * ty + i][2 * tx + j];
#pragma unroll
            for (int o = 0; o < OCB; o++) {
                float W4[16];
#pragma unroll
                for (int t = 0; t < 16; t++) W4[t] = sw[ic][o][t];
#pragma unroll
                for (int e = 0; e < 2; e++)
#pragma unroll
                    for (int f = 0; f < 2; f++) {
                        float P00 = p[e][f],     P01 = p[e][f + 1],     P02 = p[e][f + 2];
                        float P10 = p[e + 1][f], P11 = p[e + 1][f + 1], P12 = p[e + 1][f + 2];
                        float P20 = p[e + 2][f], P21 = p[e + 2][f + 1], P22 = p[e + 2][f + 2];
                        acc[o][2 * e][2 * f]         += W4[15] * P00 + W4[13] * P01 + W4[7] * P10 + W4[5] * P11;
                        acc[o][2 * e][2 * f + 1]     += W4[14] * P01 + W4[12] * P02 + W4[6] * P11 + W4[4] * P12;
                        acc[o][2 * e + 1][2 * f]     += W4[11] * P10 + W4[9]  * P11 + W4[3] * P20 + W4[1] * P21;
                        acc[o][2 * e + 1][2 * f + 1] += W4[10] * P11 + W4[8]  * P12 + W4[2] * P21 + W4[0] * P22;
                    }
            }
        }
    }
#pragma unroll
    for (int o = 0; o < OCB; o++) {
        int oc = ob * OCB + o;
        float bv = bias[oc];
#pragma unroll
        for (int r = 0; r < 4; r++)
#pragma unroll
            for (int c = 0; c < 4; c += 2) {
                float v0 = fmaxf(acc[o][r][c] + bv, 0.f);
                float v1 = fmaxf(acc[o][r][c + 1] + bv, 0.f);
                *(float2*)(out + ((size_t)((size_t)b * OC + oc) * Ho + (Yo0 + 4 * ty + r)) * Ho
                               + Xo0 + 4 * tx + c) = make_float2(v0, v1);
            }
    }
}

// ====================================================================
// Host launcher
// ====================================================================
extern "C" void kernel_launch(void* const* d_in, const int* in_sizes, int n_in,
                              void* d_out, int out_size)
{
    const float* x        = (const float*)d_in[0];
    const float* ce_w1    = (const float*)d_in[1];
    const float* ce_b1    = (const float*)d_in[2];
    const float* ce_w2    = (const float*)d_in[3];
    const float* ce_b2    = (const float*)d_in[4];
    const float* se_w1    = (const float*)d_in[5];
    const float* se_b1    = (const float*)d_in[6];
    const float* se_w2    = (const float*)d_in[7];
    const float* se_b2    = (const float*)d_in[8];
    const float* mem_keys = (const float*)d_in[9];
    const float* mem_vals = (const float*)d_in[10];
    const float* mem_hard = (const float*)d_in[11];
    const float* dec_w1   = (const float*)d_in[12];
    const float* dec_b1   = (const float*)d_in[13];
    const float* dec_tw1  = (const float*)d_in[14];
    const float* dec_tb1  = (const float*)d_in[15];
    const float* dec_tw2  = (const float*)d_in[16];
    const float* dec_tb2  = (const float*)d_in[17];
    const float* dec_w2   = (const float*)d_in[18];
    const float* dec_b2   = (const float*)d_in[19];
    float* outp = (float*)d_out;

    float *knT, *hnT, *A, *zc, *zs, *Sact, *tw, *bgz, *zm, *d1, *u1, *u2;
    int *tidx, *amax;
    cudaGetSymbolAddress((void**)&knT,  g_knT);
    cudaGetSymbolAddress((void**)&hnT,  g_hnT);
    cudaGetSymbolAddress((void**)&A,    g_A);
    cudaGetSymbolAddress((void**)&zc,   g_zc);
    cudaGetSymbolAddress((void**)&zs,   g_zs);
    cudaGetSymbolAddress((void**)&Sact, g_Sact);
    cudaGetSymbolAddress((void**)&tidx, g_tidx);
    cudaGetSymbolAddress((void**)&tw,   g_tw);
    cudaGetSymbolAddress((void**)&amax, g_amax);
    cudaGetSymbolAddress((void**)&bgz,  g_bgz);
    cudaGetSymbolAddress((void**)&zm,   g_zm);
    cudaGetSymbolAddress((void**)&d1,   g_d1);
    cudaGetSymbolAddress((void**)&u1,   g_u1);
    cudaGetSymbolAddress((void**)&u2,   g_u2);

    k_normrows<<<200, 256>>>(mem_keys, mem_hard, knT, hnT);
    k_bg<<<1, 256>>>(ce_w2, ce_b1, ce_b2, knT, mem_vals, bgz);

    // ---- center encoder (active region only) ----
    k_fillA<<<(16 * 32 * 16384) / 256, 256>>>(A, ce_b1);
    k_enc1<32, true><<<dim3(4, 4, 16), 256>>>(x, ce_w1, ce_b1, A, 2, 2);
    k_conv3b<16, true, true><<<dim3(2, 2 * 8, 16), 256>>>(
        A, ce_w2, ce_b2, zc, 32, 128, 128, 128, 2, 1, 1);

    // ---- center matching: background fill + active rows ----
    k_fillbg<<<(16 * 128 * 4096) / 256, 256>>>(zm, bgz);
    k_gemm_act<<<dim3(13, 3, 16), 256>>>(zc, knT, Sact);
    k_topk_act<<<(16 * 324 + 7) / 8, 256>>>(Sact, zc, tidx, tw);
    k_gatherC_act<<<(16 * 324) / 8, 256>>>(mem_vals, tidx, tw, zm);

    // ---- skip encoder + fused matching ----
    k_enc1<16, false><<<dim3(8, 8, 16), 256>>>(x, se_w1, se_b1, A, 0, 0);
    k_conv3b<16, true, true><<<dim3(4, 4 * 8, 16), 256>>>(
        A, se_w2, se_b2, zs, 16, 128, 128, 128, 4, 0, 0);
    k_gemm_amax<<<dim3(32, 16), 256>>>(zs, hnT, amax);
    k_gatherS<<<8192, 256>>>(mem_hard, amax, zm);

    // ---- decoder ----
    k_conv3b<16, true, false><<<dim3(2, 2 * 4, 16), 256>>>(
        zm, dec_w1, dec_b1, d1, 256, 64, 64, 64, 2, 0, 0);
    k_deconv<64, 32, 4><<<dim3(2, 2 * 8, 16), 256>>>(d1, dec_tw1, dec_tb1, u1, 64, 2);
    k_deconv<32, 16, 4><<<dim3(4, 4 * 4, 16), 256>>>(u1, dec_tw2, dec_tb2, u2, 128, 4);
    k_conv3b<1, false, false><<<dim3(8, 8, 16), 256>>>(
        u2, dec_w2, dec_b2, outp, 16, 1, 256, 256, 8, 0, 0);
}

// round 8
// speedup vs baseline: 1.4575x; 1.0781x over previous
#include <cuda_runtime.h>
#include <math.h>
#include <stdint.h>

// ====================================================================
// Static device scratch
// ====================================================================
__device__ __align__(256) float g_knT[128 * 800];
__device__ __align__(256) float g_hnT[128 * 800];
__device__ __align__(256) float g_A  [16 * 32 * 128 * 128];   // center enc1 out
__device__ __align__(256) float g_A2 [16 * 16 * 128 * 128];   // skip enc1 out
__device__ __align__(256) float g_zc [16 * 128 * 64 * 64];
__device__ __align__(256) float g_zs [16 * 128 * 64 * 64];
__device__ __align__(256) float g_Sact[16 * 384 * 800];
__device__ __align__(256) int   g_tidx[16 * 324 * 10];
__device__ __align__(256) float g_tw  [16 * 324 * 10];
__device__ __align__(256) int   g_amax[65536];
__device__ __align__(256) float g_bgz [128];
__device__ __align__(256) float g_zm [16 * 256 * 64 * 64];
__device__ __align__(256) float g_d1 [16 * 64 * 64 * 64];
__device__ __align__(256) float g_u1 [16 * 32 * 128 * 128];
__device__ __align__(256) float g_u2 [16 * 16 * 256 * 256];

// ====================================================================
// Normalize memory rows -> transposed tables knT[c][m], hnT[c][m]
// ====================================================================
__global__ void k_normrows(const float* __restrict__ keys,
                           const float* __restrict__ hard,
                           float* __restrict__ knT, float* __restrict__ hnT)
{
    int gw = (blockIdx.x * blockDim.x + threadIdx.x) >> 5;
    int lane = threadIdx.x & 31;
    if (gw >= 1600) return;
    const float* src; float* dst; int r;
    if (gw < 800) { src = keys; dst = knT; r = gw; }
    else          { src = hard; dst = hnT; r = gw - 800; }
    float4 v = *(const float4*)(src + (size_t)r * 128 + lane * 4);
    float s = v.x * v.x + v.y * v.y + v.z * v.z + v.w * v.w;
#pragma unroll
    for (int o = 16; o > 0; o >>= 1) s += __shfl_xor_sync(0xffffffffu, s, o);
    float d = 1.0f / fmaxf(sqrtf(s), 1e-12f);
    dst[(size_t)(4 * lane + 0) * 800 + r] = v.x * d;
    dst[(size_t)(4 * lane + 1) * 800 + r] = v.y * d;
    dst[(size_t)(4 * lane + 2) * 800 + r] = v.z * d;
    dst[(size_t)(4 * lane + 3) * 800 + r] = v.w * d;
}

// ====================================================================
// Background z_match: bgc -> scores -> topk -> softmax -> gather (1 block)
// ====================================================================
__global__ __launch_bounds__(256) void k_bg(const float* __restrict__ w2,
    const float* __restrict__ b1, const float* __restrict__ b2,
    const float* __restrict__ knT, const float* __restrict__ vals,
    float* __restrict__ bgz)
{
    __shared__ float bgc[128];
    __shared__ float sc[800];
    __shared__ int   swidx[10];
    __shared__ float sww[10];
    const int tid = threadIdx.x;
    if (tid < 128) {
        float s = b2[tid];
        for (int ic = 0; ic < 32; ic++) {
            float wsum = 0.f;
#pragma unroll
            for (int k = 0; k < 9; k++) wsum += w2[((size_t)tid * 32 + ic) * 9 + k];
            s = fmaf(wsum, fmaxf(b1[ic], 0.f), s);
        }
        bgc[tid] = fmaxf(s, 0.f);
    }
    __syncthreads();
    for (int m = tid; m < 800; m += 256) {
        float s = 0.f;
#pragma unroll 8
        for (int c = 0; c < 128; c++) s = fmaf(bgc[c], knT[(size_t)c * 800 + m], s);
        sc[m] = s;
    }
    __syncthreads();
    if (tid < 32) {
        const int lane = tid;
        float ss = 0.f;
#pragma unroll
        for (int j = 0; j < 4; j++) { float v = bgc[lane * 4 + j]; ss = fmaf(v, v, ss); }
#pragma unroll
        for (int o = 16; o > 0; o >>= 1) ss += __shfl_xor_sync(0xffffffffu, ss, o);
        float scale = 1.0f / fmaxf(sqrtf(ss), 1e-12f);
        float lv[10]; int li[10];
#pragma unroll
        for (int j = 0; j < 10; j++) { lv[j] = -INFINITY; li[j] = 0x7fffffff; }
        for (int t = 0; t < 25; t++) {
            int m = lane + 32 * t;
            float v = sc[m];
            int i = m;
#pragma unroll
            for (int j = 0; j < 10; j++) {
                bool better = (v > lv[j]) || (v == lv[j] && i < li[j]);
                if (better) {
                    float tv = lv[j]; lv[j] = v; v = tv;
                    int ti = li[j]; li[j] = i; i = ti;
                }
            }
        }
        float bv[10]; int bi[10];
#pragma unroll
        for (int k = 0; k < 10; k++) {
            float cv = lv[0]; int ci = li[0];
#pragma unroll
            for (int off = 16; off > 0; off >>= 1) {
                float ov = __shfl_xor_sync(0xffffffffu, cv, off);
                int   oi = __shfl_xor_sync(0xffffffffu, ci, off);
                if (ov > cv || (ov == cv && oi < ci)) { cv = ov; ci = oi; }
            }
            bv[k] = cv; bi[k] = ci;
            if (lv[0] == cv && li[0] == ci) {
#pragma unroll
                for (int j = 0; j < 9; j++) { lv[j] = lv[j + 1]; li[j] = li[j + 1]; }
                lv[9] = -INFINITY; li[9] = 0x7fffffff;
            }
        }
        if (lane == 0) {
            float mx = bv[0] * scale;
            float e[10], sum = 0.f;
#pragma unroll
            for (int k = 0; k < 10; k++) { e[k] = expf(bv[k] * scale - mx); sum += e[k]; }
            float inv = 1.0f / sum;
#pragma unroll
            for (int k = 0; k < 10; k++) { swidx[k] = bi[k]; sww[k] = e[k] * inv; }
        }
    }
    __syncthreads();
    if (tid < 128) {
        float a = 0.f;
#pragma unroll
        for (int k = 0; k < 10; k++)
            a = fmaf(vals[(size_t)swidx[k] * 128 + tid], sww[k], a);
        bgz[tid] = a;
    }
}

// ====================================================================
// Fill zm center channels [0,128) with background z_match
// ====================================================================
__global__ void k_fillbg(float* __restrict__ zm, const float* __restrict__ bgz)
{
    int i = blockIdx.x * 256 + threadIdx.x;   // < 16*128*4096
    int c = (i >> 12) & 127;
    int b = i >> 19;
    zm[((size_t)b * 256 + c) * 4096 + (i & 4095)] = __ldg(&bgz[c]);
}

// ====================================================================
// Fill A (enc1-center out) with relu(b1[c])
// ====================================================================
__global__ void k_fillA(float* __restrict__ A, const float* __restrict__ b1)
{
    int i = blockIdx.x * blockDim.x + threadIdx.x;   // < 16*32*16384
    int c = (i >> 14) & 31;
    A[i] = fmaxf(b1[c], 0.f);
}

// ====================================================================
// Encoder stage 1: conv3x3 (1 -> CO) + relu + maxpool2, tile offset.
// ====================================================================
template<int CO, bool MASK>
__global__ __launch_bounds__(256) void k_enc1(const float* __restrict__ x,
    const float* __restrict__ w, const float* __restrict__ bias,
    float* __restrict__ out, int offX, int offY)
{
    __shared__ float tile[34][36];
    __shared__ float sw[CO * 9];
    __shared__ float sb[CO];
    const int t  = threadIdx.x;
    const int b  = blockIdx.z;
    const int Y0 = (blockIdx.y + offY) * 32;
    const int X0 = (blockIdx.x + offX) * 32;
    const float* xb = x + (size_t)b * 65536;
    for (int i = t; i < 34 * 34; i += 256) {
        int r = i / 34, c = i % 34;
        int gy = Y0 + r - 1, gx = X0 + c - 1;
        bool ok = (gy >= 0 && gy < 256 && gx >= 0 && gx < 256);
        if (MASK) ok = ok && (gy >= 96 && gy < 160 && gx >= 96 && gx < 160);
        tile[r][c] = ok ? xb[gy * 256 + gx] : 0.f;
    }
    for (int i = t; i < CO * 9; i += 256) sw[i] = w[i];
    if (t < CO) sb[t] = bias[t];
    __syncthreads();
    const int ty = t >> 4, tx = t & 15;
    float p[4][4];
#pragma unroll
    for (int i = 0; i < 4; i++)
#pragma unroll
        for (int j = 0; j < 4; j++) p[i][j] = tile[2 * ty + i][2 * tx + j];
    const int py = (blockIdx.y + offY) * 16 + ty, px = (blockIdx.x + offX) * 16 + tx;
    float* ob = out + (size_t)b * CO * 128 * 128 + py * 128 + px;
#pragma unroll 4
    for (int oc = 0; oc < CO; oc++) {
        float w9[9];
#pragma unroll
        for (int k = 0; k < 9; k++) w9[k] = sw[oc * 9 + k];
        float bv = sb[oc];
        float m = -INFINITY;
#pragma unroll
        for (int i = 0; i < 2; i++)
#pragma unroll
            for (int j = 0; j < 2; j++) {
                float s = bv;
#pragma unroll
                for (int dy = 0; dy < 3; dy++)
#pragma unroll
                    for (int dx = 0; dx < 3; dx++)
                        s = fmaf(w9[dy * 3 + dx], p[i + dy][j + dx], s);
                m = fmaxf(m, fmaxf(s, 0.f));
            }
        ob[(size_t)oc * 128 * 128] = m;
    }
}

// ====================================================================
// conv3x3 pad1, OIHW weights. 32x32 output tile, 2x2 px per thread,
// IC chunks of 4, optional relu, optional fused 2x2 maxpool.
// ====================================================================
template<int OCB, bool RELU, bool POOL>
__global__ __launch_bounds__(256) void k_conv3b(const float* __restrict__ in,
    const float* __restrict__ w, const float* __restrict__ bias,
    float* __restrict__ out, int IC, int OC, int H, int W, int tilesY,
    int offX, int offY)
{
    __shared__ float tin[4][34][36];
    __shared__ float sw[OCB][4][9];
    const int tY = blockIdx.y % tilesY;
    const int ob = blockIdx.y / tilesY;
    const int Y0 = (tY + offY) * 32;
    const int X0 = (blockIdx.x + offX) * 32;
    const int b  = blockIdx.z;
    const int tid = threadIdx.x;
    const int ty = tid >> 4, tx = tid & 15;
    float acc[OCB][2][2];
#pragma unroll
    for (int o = 0; o < OCB; o++)
#pragma unroll
        for (int e = 0; e < 2; e++)
#pragma unroll
            for (int f = 0; f < 2; f++) acc[o][e][f] = 0.f;
    const float* inb = in + (size_t)b * IC * H * W;
    for (int ic0 = 0; ic0 < IC; ic0 += 4) {
        __syncthreads();
        for (int i = tid; i < 4 * 34 * 34; i += 256) {
            int ic = i / (34 * 34); int rem = i % (34 * 34);
            int r = rem / 34, c = rem % 34;
            int gy = Y0 + r - 1, gx = X0 + c - 1;
            float v = 0.f;
            if (gy >= 0 && gy < H && gx >= 0 && gx < W)
                v = inb[(size_t)(ic0 + ic) * H * W + gy * W + gx];
            tin[ic][r][c] = v;
        }
        for (int i = tid; i < OCB * 4 * 9; i += 256) {
            int o = i / 36; int rem = i % 36; int ic = rem / 9; int k = rem % 9;
            sw[o][ic][k] = w[((size_t)(ob * OCB + o) * IC + ic0 + ic) * 9 + k];
        }
        __syncthreads();
#pragma unroll
        for (int ic = 0; ic < 4; ic++) {
            float p[4][4];
#pragma unroll
            for (int i = 0; i < 4; i++)
#pragma unroll
                for (int j = 0; j < 4; j++)
                    p[i][j] = tin[ic][2 * ty + i][2 * tx + j];
#pragma unroll
            for (int o = 0; o < OCB; o++) {
                float w9[9];
#pragma unroll
                for (int k = 0; k < 9; k++) w9[k] = sw[o][ic][k];
#pragma unroll
                for (int e = 0; e < 2; e++)
#pragma unroll
                    for (int f = 0; f < 2; f++) {
                        float s = acc[o][e][f];
#pragma unroll
                        for (int dy = 0; dy < 3; dy++)
#pragma unroll
                            for (int dx = 0; dx < 3; dx++)
                                s = fmaf(w9[dy * 3 + dx], p[e + dy][f + dx], s);
                        acc[o][e][f] = s;
                    }
            }
        }
    }
#pragma unroll
    for (int o = 0; o < OCB; o++) {
        int oc = ob * OCB + o;
        float bv = bias[oc];
        if (POOL) {
            float m = -INFINITY;
#pragma unroll
            for (int e = 0; e < 2; e++)
#pragma unroll
                for (int f = 0; f < 2; f++)
                    m = fmaxf(m, fmaxf(acc[o][e][f] + bv, 0.f));
            int Ho = H >> 1, Wo = W >> 1;
            out[((size_t)((size_t)b * OC + oc) * Ho + ((Y0 >> 1) + ty)) * Wo
                + (X0 >> 1) + tx] = m;
        } else {
#pragma unroll
            for (int e = 0; e < 2; e++) {
                float v0 = acc[o][e][0] + bv, v1 = acc[o][e][1] + bv;
                if (RELU) { v0 = fmaxf(v0, 0.f); v1 = fmaxf(v1, 0.f); }
                *(float2*)(out + ((size_t)((size_t)b * OC + oc) * H + (Y0 + 2 * ty + e)) * W
                               + X0 + 2 * tx) = make_float2(v0, v1);
            }
        }
    }
}

// ====================================================================
// Center active GEMM: S_act[b*384+ai][m] = sum_c zc[b][c][n(ai)]*knT[c][m]
// ====================================================================
__global__ __launch_bounds__(256) void k_gemm_act(const float* __restrict__ A,
    const float* __restrict__ Bm, float* __restrict__ S)
{
    __shared__ float As[16][128];
    __shared__ float Bs[16][64];
    __shared__ int   map[128];
    const int b  = blockIdx.z;
    const int n0 = blockIdx.y * 128;
    const int m0 = blockIdx.x * 64;
    const int tid = threadIdx.x;
    const int tm = tid & 15, tn = tid >> 4;
    if (tid < 128) {
        int ai = n0 + tid;
        map[tid] = (ai < 324) ? ((23 + ai / 18) * 64 + 23 + ai % 18) : (23 * 64 + 23);
    }
    float acc[8][4];
#pragma unroll
    for (int i = 0; i < 8; i++)
#pragma unroll
        for (int j = 0; j < 4; j++) acc[i][j] = 0.f;
    const float* Ab = A + (size_t)b * 128 * 4096;
    const int lkB = tid >> 4, lmB = (tid * 4) & 63;
    __syncthreads();
    for (int k0 = 0; k0 < 128; k0 += 16) {
        __syncthreads();
#pragma unroll
        for (int j = 0; j < 8; j++) {
            int idx = tid * 8 + j;
            int lk = idx >> 7, ln = idx & 127;
            As[lk][ln] = Ab[(size_t)(k0 + lk) * 4096 + map[ln]];
        }
        float4 bv = make_float4(0.f, 0.f, 0.f, 0.f);
        if (m0 + lmB < 800)
            bv = *(const float4*)&Bm[(size_t)(k0 + lkB) * 800 + m0 + lmB];
        *(float4*)&Bs[lkB][lmB] = bv;
        __syncthreads();
#pragma unroll
        for (int k = 0; k < 16; k++) {
            float4 a0 = *(float4*)&As[k][tn * 8];
            float4 a1 = *(float4*)&As[k][tn * 8 + 4];
            float4 bb = *(float4*)&Bs[k][tm * 4];
            float av[8] = {a0.x, a0.y, a0.z, a0.w, a1.x, a1.y, a1.z, a1.w};
#pragma unroll
            for (int i = 0; i < 8; i++) {
                acc[i][0] = fmaf(av[i], bb.x, acc[i][0]);
                acc[i][1] = fmaf(av[i], bb.y, acc[i][1]);
                acc[i][2] = fmaf(av[i], bb.z, acc[i][2]);
                acc[i][3] = fmaf(av[i], bb.w, acc[i][3]);
            }
        }
    }
    const int m = m0 + tm * 4;
    if (m < 800) {
#pragma unroll
        for (int i = 0; i < 8; i++) {
            size_t row = (size_t)b * 384 + n0 + tn * 8 + i;
            *(float4*)&S[row * 800 + m] =
                make_float4(acc[i][0], acc[i][1], acc[i][2], acc[i][3]);
        }
    }
}

// ====================================================================
// Active top-10 + softmax (scale inline from zc). 5184 warps.
// ====================================================================
__global__ void k_topk_act(const float* __restrict__ S, const float* __restrict__ zc,
                           int* __restrict__ tidx, float* __restrict__ tw)
{
    int gw = (blockIdx.x * blockDim.x + threadIdx.x) >> 5;
    int lane = threadIdx.x & 31;
    if (gw >= 16 * 324) return;
    const int b = gw / 324, ai = gw % 324;
    const int n = (23 + ai / 18) * 64 + 23 + ai % 18;
    const float* zb = zc + (size_t)b * 128 * 4096 + n;
    float ss = 0.f;
#pragma unroll
    for (int j = 0; j < 4; j++) {
        float v = zb[(size_t)(lane + 32 * j) * 4096];
        ss = fmaf(v, v, ss);
    }
#pragma unroll
    for (int o = 16; o > 0; o >>= 1) ss += __shfl_xor_sync(0xffffffffu, ss, o);
    float sc = 1.0f / fmaxf(sqrtf(ss), 1e-12f);

    const float* row = S + ((size_t)b * 384 + ai) * 800;
    float lv[10]; int li[10];
#pragma unroll
    for (int j = 0; j < 10; j++) { lv[j] = -INFINITY; li[j] = 0x7fffffff; }
    for (int t = 0; t < 25; t++) {
        int m = lane + 32 * t;
        float v = row[m];
        int i = m;
#pragma unroll
        for (int j = 0; j < 10; j++) {
            bool better = (v > lv[j]) || (v == lv[j] && i < li[j]);
            if (better) {
                float tv = lv[j]; lv[j] = v; v = tv;
                int ti = li[j]; li[j] = i; i = ti;
            }
        }
    }
    float bv[10]; int bi[10];
#pragma unroll
    for (int k = 0; k < 10; k++) {
        float cv = lv[0]; int ci = li[0];
#pragma unroll
        for (int off = 16; off > 0; off >>= 1) {
            float ov = __shfl_xor_sync(0xffffffffu, cv, off);
            int   oi = __shfl_xor_sync(0xffffffffu, ci, off);
            if (ov > cv || (ov == cv && oi < ci)) { cv = ov; ci = oi; }
        }
        bv[k] = cv; bi[k] = ci;
        if (lv[0] == cv && li[0] == ci) {
#pragma unroll
            for (int j = 0; j < 9; j++) { lv[j] = lv[j + 1]; li[j] = li[j + 1]; }
            lv[9] = -INFINITY; li[9] = 0x7fffffff;
        }
    }
    if (lane == 0) {
        float mx = bv[0] * sc;
        float e[10], sum = 0.f;
#pragma unroll
        for (int k = 0; k < 10; k++) { e[k] = expf(bv[k] * sc - mx); sum += e[k]; }
        float inv = 1.0f / sum;
#pragma unroll
        for (int k = 0; k < 10; k++) {
            tidx[gw * 10 + k] = bi[k];
            tw[gw * 10 + k]   = e[k] * inv;
        }
    }
}

// ====================================================================
// Active weighted gather -> zm channels [0,128)
// ====================================================================
__global__ void k_gatherC_act(const float* __restrict__ vals, const int* __restrict__ tidx,
                              const float* __restrict__ tw, float* __restrict__ zm)
{
    __shared__ int   sidx[8][10];
    __shared__ float swt [8][10];
    const int r0 = blockIdx.x * 8;
    const int tid = threadIdx.x;
    if (tid < 80) {
        int ny = tid / 10, k = tid % 10;
        sidx[ny][k] = tidx[(size_t)(r0 + ny) * 10 + k];
        swt [ny][k] = tw  [(size_t)(r0 + ny) * 10 + k];
    }
    __syncthreads();
    const int cx = tid & 31, ny = tid >> 5;
    const int row = r0 + ny;
    const int b = row / 324, ai = row % 324;
    const int n = (23 + ai / 18) * 64 + 23 + ai % 18;
#pragma unroll
    for (int cc = 0; cc < 4; cc++) {
        int c = cx + 32 * cc;
        float acc = 0.f;
#pragma unroll
        for (int k = 0; k < 10; k++)
            acc = fmaf(vals[(size_t)sidx[ny][k] * 128 + c], swt[ny][k], acc);
        zm[((size_t)b * 256 + c) * 4096 + n] = acc;
    }
}

// ====================================================================
// Skip GEMM + fused argmax. Tile 128n, m chunks of 128, 8x8 micro.
// ====================================================================
__global__ __launch_bounds__(256) void k_gemm_amax(const float* __restrict__ A,
    const float* __restrict__ Bm, int* __restrict__ amax)
{
    __shared__ float As[16][128];
    __shared__ float Bs[16][128];
    __shared__ float rv[128][17];
    __shared__ int   ri[128][17];
    const int b  = blockIdx.y;
    const int n0 = blockIdx.x * 128;
    const int tid = threadIdx.x;
    const int tm = tid & 15, tn = tid >> 4;
    const int lk = tid >> 4, ln = (tid & 15) * 8;
    const float* Ab = A + (size_t)b * 128 * 4096;
    float bestv[8]; int besti[8];
#pragma unroll
    for (int i = 0; i < 8; i++) { bestv[i] = -INFINITY; besti[i] = 0x7fffffff; }
    for (int m0 = 0; m0 < 800; m0 += 128) {
        float acc[8][8];
#pragma unroll
        for (int i = 0; i < 8; i++)
#pragma unroll
            for (int j = 0; j < 8; j++) acc[i][j] = 0.f;
        for (int k0 = 0; k0 < 128; k0 += 16) {
            __syncthreads();
            const float* ap = &Ab[(size_t)(k0 + lk) * 4096 + n0 + ln];
            *(float4*)&As[lk][ln]     = *(const float4*)ap;
            *(float4*)&As[lk][ln + 4] = *(const float4*)(ap + 4);
            if (m0 + ln + 7 < 800) {
                const float* bp = &Bm[(size_t)(k0 + lk) * 800 + m0 + ln];
                *(float4*)&Bs[lk][ln]     = *(const float4*)bp;
                *(float4*)&Bs[lk][ln + 4] = *(const float4*)(bp + 4);
            } else {
#pragma unroll
                for (int j = 0; j < 8; j++)
                    Bs[lk][ln + j] = (m0 + ln + j < 800)
                        ? Bm[(size_t)(k0 + lk) * 800 + m0 + ln + j] : 0.f;
            }
            __syncthreads();
#pragma unroll
            for (int k = 0; k < 16; k++) {
                float4 a0 = *(float4*)&As[k][tn * 8];
                float4 a1 = *(float4*)&As[k][tn * 8 + 4];
                float4 b0 = *(float4*)&Bs[k][tm * 8];
                float4 b1 = *(float4*)&Bs[k][tm * 8 + 4];
                float av[8] = {a0.x, a0.y, a0.z, a0.w, a1.x, a1.y, a1.z, a1.w};
                float bw[8] = {b0.x, b0.y, b0.z, b0.w, b1.x, b1.y, b1.z, b1.w};
#pragma unroll
                for (int i = 0; i < 8; i++)
#pragma unroll
                    for (int j = 0; j < 8; j++)
                        acc[i][j] = fmaf(av[i], bw[j], acc[i][j]);
            }
        }
#pragma unroll
        for (int i = 0; i < 8; i++)
#pragma unroll
            for (int j = 0; j < 8; j++) {
                int m = m0 + tm * 8 + j;
                float v = acc[i][j];
                if (m < 800 && (v > bestv[i] || (v == bestv[i] && m < besti[i]))) {
                    bestv[i] = v; besti[i] = m;
                }
            }
    }
    __syncthreads();
#pragma unroll
    for (int i = 0; i < 8; i++) { rv[tn * 8 + i][tm] = bestv[i]; ri[tn * 8 + i][tm] = besti[i]; }
    __syncthreads();
    if (tid < 128) {
        float bv = -INFINITY; int bi = 0x7fffffff;
#pragma unroll
        for (int t = 0; t < 16; t++) {
            float v = rv[tid][t]; int i = ri[tid][t];
            if (v > bv || (v == bv && i < bi)) { bv = v; bi = i; }
        }
        amax[b * 4096 + n0 + tid] = bi;
    }
}

// ====================================================================
// Hard gather -> zm channels [128,256)
// ====================================================================
__global__ void k_gatherS(const float* __restrict__ hard, const int* __restrict__ amax,
                          float* __restrict__ zm)
{
    const int r0 = blockIdx.x * 8;
    const int tid = threadIdx.x;
    const int cx = tid & 31, ny = tid >> 5;
    const int row = r0 + ny;
    const int b = row >> 12, n = row & 4095;
    const int a = amax[row];
#pragma unroll
    for (int cc = 0; cc < 4; cc++) {
        int c = cx + 32 * cc;
        zm[((size_t)b * 256 + 128 + c) * 4096 + n] = hard[(size_t)a * 128 + c];
    }
}

// ====================================================================
// Transposed conv (k=4, s=2) + relu. 64x64 output tile, 4x4 px/thread.
// ====================================================================
template<int IC, int OC, int OCB>
__global__ __launch_bounds__(256) void k_deconv(const float* __restrict__ in,
    const float* __restrict__ w, const float* __restrict__ bias,
    float* __restrict__ out, int Hi, int tilesY)
{
    __shared__ float tin[2][34][36];
    __shared__ float sw[2][OCB][16];
    const int Ho = 2 * Hi;
    const int tY = blockIdx.y % tilesY;
    const int ob = blockIdx.y / tilesY;
    const int b  = blockIdx.z;
    const int Xo0 = blockIdx.x * 64, Yo0 = tY * 64;
    const int a0 = Yo0 >> 1, c0 = Xo0 >> 1;
    const int tid = threadIdx.x;
    const int ty = tid >> 4, tx = tid & 15;
    float acc[OCB][4][4];
#pragma unroll
    for (int o = 0; o < OCB; o++)
#pragma unroll
        for (int r = 0; r < 4; r++)
#pragma unroll
            for (int c = 0; c < 4; c++) acc[o][r][c] = 0.f;
    const float* inb = in + (size_t)b * IC * Hi * Hi;
    for (int ic0 = 0; ic0 < IC; ic0 += 2) {
        __syncthreads();
        for (int i = tid; i < 2 * 34 * 34; i += 256) {
            int ic = i / (34 * 34); int rem = i % (34 * 34);
            int r = rem / 34, c = rem % 34;
            int gy = a0 + r - 1, gx = c0 + c - 1;
            float v = 0.f;
            if (gy >= 0 && gy < Hi && gx >= 0 && gx < Hi)
                v = inb[(size_t)(ic0 + ic) * Hi * Hi + gy * Hi + gx];
            tin[ic][r][c] = v;
        }
        for (int i = tid; i < 2 * OCB * 16; i += 256) {
            int ic = i / (OCB * 16); int rem = i % (OCB * 16);
            int o = rem / 16; int t = rem % 16;
            sw[ic][o][t] = w[((size_t)(ic0 + ic) * OC + ob * OCB + o) * 16 + t];
        }
        __syncthreads();
#pragma unroll
        for (int ic = 0; ic < 2; ic++) {
            float p[4][4];
#pragma unroll
            for (int i = 0; i < 4; i++)
#pragma unroll
                for (int j = 0; j < 4; j++)
                    p[i][j] = tin[ic][2 * ty + i][2 * tx + j];
#pragma unroll
            for (int o = 0; o < OCB; o++) {
                float W4[16];
#pragma unroll
                for (int t = 0; t < 16; t++) W4[t] = sw[ic][o][t];
#pragma unroll
                for (int e = 0; e < 2; e++)
#pragma unroll
                    for (int f = 0; f < 2; f++) {
                        float P00 = p[e][f],     P01 = p[e][f + 1],     P02 = p[e][f + 2];
                        float P10 = p[e + 1][f], P11 = p[e + 1][f + 1], P12 = p[e + 1][f + 2];
                        float P20 = p[e + 2][f], P21 = p[e + 2][f + 1], P22 = p[e + 2][f + 2];
                        acc[o][2 * e][2 * f]         += W4[15] * P00 + W4[13] * P01 + W4[7] * P10 + W4[5] * P11;
                        acc[o][2 * e][2 * f + 1]     += W4[14] * P01 + W4[12] * P02 + W4[6] * P11 + W4[4] * P12;
                        acc[o][2 * e + 1][2 * f]     += W4[11] * P10 + W4[9]  * P11 + W4[3] * P20 + W4[1] * P21;
                        acc[o][2 * e + 1][2 * f + 1] += W4[10] * P11 + W4[8]  * P12 + W4[2] * P21 + W4[0] * P22;
                    }
            }
        }
    }
#pragma unroll
    for (int o = 0; o < OCB; o++) {
        int oc = ob * OCB + o;
        float bv = bias[oc];
#pragma unroll
        for (int r = 0; r < 4; r++)
#pragma unroll
            for (int c = 0; c < 4; c += 2) {
                float v0 = fmaxf(acc[o][r][c] + bv, 0.f);
                float v1 = fmaxf(acc[o][r][c + 1] + bv, 0.f);
                *(float2*)(out + ((size_t)((size_t)b * OC + oc) * Ho + (Yo0 + 4 * ty + r)) * Ho
                               + Xo0 + 4 * tx + c) = make_float2(v0, v1);
            }
    }
}

// ====================================================================
// Host launcher — fork/join multi-stream (capture-safe event pattern)
// ====================================================================
static cudaStream_t s_bg = nullptr, s_skip = nullptr;
static cudaEvent_t  e_root = nullptr, e_bgdone = nullptr, e_skipdone = nullptr;

extern "C" void kernel_launch(void* const* d_in, const int* in_sizes, int n_in,
                              void* d_out, int out_size)
{
    if (!s_bg) {
        cudaStreamCreateWithFlags(&s_bg,   cudaStreamNonBlocking);
        cudaStreamCreateWithFlags(&s_skip, cudaStreamNonBlocking);
        cudaEventCreateWithFlags(&e_root,     cudaEventDisableTiming);
        cudaEventCreateWithFlags(&e_bgdone,   cudaEventDisableTiming);
        cudaEventCreateWithFlags(&e_skipdone, cudaEventDisableTiming);
    }
    const float* x        = (const float*)d_in[0];
    const float* ce_w1    = (const float*)d_in[1];
    const float* ce_b1    = (const float*)d_in[2];
    const float* ce_w2    = (const float*)d_in[3];
    const float* ce_b2    = (const float*)d_in[4];
    const float* se_w1    = (const float*)d_in[5];
    const float* se_b1    = (const float*)d_in[6];
    const float* se_w2    = (const float*)d_in[7];
    const float* se_b2    = (const float*)d_in[8];
    const float* mem_keys = (const float*)d_in[9];
    const float* mem_vals = (const float*)d_in[10];
    const float* mem_hard = (const float*)d_in[11];
    const float* dec_w1   = (const float*)d_in[12];
    const float* dec_b1   = (const float*)d_in[13];
    const float* dec_tw1  = (const float*)d_in[14];
    const float* dec_tb1  = (const float*)d_in[15];
    const float* dec_tw2  = (const float*)d_in[16];
    const float* dec_tb2  = (const float*)d_in[17];
    const float* dec_w2   = (const float*)d_in[18];
    const float* dec_b2   = (const float*)d_in[19];
    float* outp = (float*)d_out;

    float *knT, *hnT, *A, *A2, *zc, *zs, *Sact, *tw, *bgz, *zm, *d1, *u1, *u2;
    int *tidx, *amax;
    cudaGetSymbolAddress((void**)&knT,  g_knT);
    cudaGetSymbolAddress((void**)&hnT,  g_hnT);
    cudaGetSymbolAddress((void**)&A,    g_A);
    cudaGetSymbolAddress((void**)&A2,   g_A2);
    cudaGetSymbolAddress((void**)&zc,   g_zc);
    cudaGetSymbolAddress((void**)&zs,   g_zs);
    cudaGetSymbolAddress((void**)&Sact, g_Sact);
    cudaGetSymbolAddress((void**)&tidx, g_tidx);
    cudaGetSymbolAddress((void**)&tw,   g_tw);
    cudaGetSymbolAddress((void**)&amax, g_amax);
    cudaGetSymbolAddress((void**)&bgz,  g_bgz);
    cudaGetSymbolAddress((void**)&zm,   g_zm);
    cudaGetSymbolAddress((void**)&d1,   g_d1);
    cudaGetSymbolAddress((void**)&u1,   g_u1);
    cudaGetSymbolAddress((void**)&u2,   g_u2);

    // root: normalized memory tables (needed by bg, center gemm, skip gemm)
    k_normrows<<<200, 256>>>(mem_keys, mem_hard, knT, hnT);
    cudaEventRecord(e_root, 0);

    // ---- bg branch (stream s_bg): background z_match + zm fill ----
    cudaStreamWaitEvent(s_bg, e_root, 0);
    k_bg<<<1, 256, 0, s_bg>>>(ce_w2, ce_b1, ce_b2, knT, mem_vals, bgz);
    k_fillbg<<<(16 * 128 * 4096) / 256, 256, 0, s_bg>>>(zm, bgz);
    cudaEventRecord(e_bgdone, s_bg);

    // ---- skip branch (stream s_skip): encoder + fused matching ----
    cudaStreamWaitEvent(s_skip, e_root, 0);
    k_enc1<16, false><<<dim3(8, 8, 16), 256, 0, s_skip>>>(x, se_w1, se_b1, A2, 0, 0);
    k_conv3b<16, true, true><<<dim3(4, 4 * 8, 16), 256, 0, s_skip>>>(
        A2, se_w2, se_b2, zs, 16, 128, 128, 128, 4, 0, 0);
    k_gemm_amax<<<dim3(32, 16), 256, 0, s_skip>>>(zs, hnT, amax);
    k_gatherS<<<8192, 256, 0, s_skip>>>(mem_hard, amax, zm);
    cudaEventRecord(e_skipdone, s_skip);

    // ---- center branch (main stream) ----
    k_fillA<<<(16 * 32 * 16384) / 256, 256>>>(A, ce_b1);
    k_enc1<32, true><<<dim3(4, 4, 16), 256>>>(x, ce_w1, ce_b1, A, 2, 2);
    k_conv3b<16, true, true><<<dim3(2, 2 * 8, 16), 256>>>(
        A, ce_w2, ce_b2, zc, 32, 128, 128, 128, 2, 1, 1);
    k_gemm_act<<<dim3(13, 3, 16), 256>>>(zc, knT, Sact);
    k_topk_act<<<(16 * 324 + 7) / 8, 256>>>(Sact, zc, tidx, tw);
    cudaStreamWaitEvent(0, e_bgdone, 0);             // fillbg before active overwrite
    k_gatherC_act<<<(16 * 324) / 8, 256>>>(mem_vals, tidx, tw, zm);

    // ---- join skip branch, then decoder (main stream) ----
    cudaStreamWaitEvent(0, e_skipdone, 0);
    k_conv3b<8, true, false><<<dim3(2, 2 * 8, 16), 256>>>(
        zm, dec_w1, dec_b1, d1, 256, 64, 64, 64, 2, 0, 0);
    k_deconv<64, 32, 4><<<dim3(2, 2 * 8, 16), 256>>>(d1, dec_tw1, dec_tb1, u1, 64, 2);
    k_deconv<32, 16, 4><<<dim3(4, 4 * 4, 16), 256>>>(u1, dec_tw2, dec_tb2, u2, 128, 4);
    k_conv3b<1, false, false><<<dim3(8, 8, 16), 256>>>(
        u2, dec_w2, dec_b2, outp, 16, 1, 256, 256, 8, 0, 0);
}

// round 9
// speedup vs baseline: 1.4791x; 1.0148x over previous
#include <cuda_runtime.h>
#include <math.h>
#include <stdint.h>

// ====================================================================
// Static device scratch
// ====================================================================
__device__ __align__(256) float g_knT[128 * 800];
__device__ __align__(256) float g_hnT[128 * 800];
__device__ __align__(256) float g_A  [16 * 32 * 128 * 128];   // center enc1 out
__device__ __align__(256) float g_A2 [16 * 16 * 128 * 128];   // skip enc1 out
__device__ __align__(256) float g_zc [16 * 128 * 64 * 64];
__device__ __align__(256) float g_zs [16 * 128 * 64 * 64];
__device__ __align__(256) float g_Sact[16 * 384 * 800];
__device__ __align__(256) int   g_tidx[16 * 324 * 10];
__device__ __align__(256) float g_tw  [16 * 324 * 10];
__device__ __align__(256) int   g_amax[65536];
__device__ __align__(256) float g_bgz [128];
__device__ __align__(256) float g_zm [16 * 256 * 64 * 64];
__device__ __align__(256) float g_d1 [16 * 64 * 64 * 64];
__device__ __align__(256) float g_u1 [16 * 32 * 128 * 128];
__device__ __align__(256) float g_u2 [16 * 16 * 256 * 256];

// ====================================================================
// Normalize memory rows -> transposed tables knT[c][m], hnT[c][m]
// ====================================================================
__global__ void k_normrows(const float* __restrict__ keys,
                           const float* __restrict__ hard,
                           float* __restrict__ knT, float* __restrict__ hnT)
{
    int gw = (blockIdx.x * blockDim.x + threadIdx.x) >> 5;
    int lane = threadIdx.x & 31;
    if (gw >= 1600) return;
    const float* src; float* dst; int r;
    if (gw < 800) { src = keys; dst = knT; r = gw; }
    else          { src = hard; dst = hnT; r = gw - 800; }
    float4 v = *(const float4*)(src + (size_t)r * 128 + lane * 4);
    float s = v.x * v.x + v.y * v.y + v.z * v.z + v.w * v.w;
#pragma unroll
    for (int o = 16; o > 0; o >>= 1) s += __shfl_xor_sync(0xffffffffu, s, o);
    float d = 1.0f / fmaxf(sqrtf(s), 1e-12f);
    dst[(size_t)(4 * lane + 0) * 800 + r] = v.x * d;
    dst[(size_t)(4 * lane + 1) * 800 + r] = v.y * d;
    dst[(size_t)(4 * lane + 2) * 800 + r] = v.z * d;
    dst[(size_t)(4 * lane + 3) * 800 + r] = v.w * d;
}

// ====================================================================
// Background z_match: bgc -> scores -> topk -> softmax -> gather (1 block)
// ====================================================================
__global__ __launch_bounds__(256) void k_bg(const float* __restrict__ w2,
    const float* __restrict__ b1, const float* __restrict__ b2,
    const float* __restrict__ knT, const float* __restrict__ vals,
    float* __restrict__ bgz)
{
    __shared__ float bgc[128];
    __shared__ float sc[800];
    __shared__ int   swidx[10];
    __shared__ float sww[10];
    const int tid = threadIdx.x;
    if (tid < 128) {
        float s = b2[tid];
        for (int ic = 0; ic < 32; ic++) {
            float wsum = 0.f;
#pragma unroll
            for (int k = 0; k < 9; k++) wsum += w2[((size_t)tid * 32 + ic) * 9 + k];
            s = fmaf(wsum, fmaxf(b1[ic], 0.f), s);
        }
        bgc[tid] = fmaxf(s, 0.f);
    }
    __syncthreads();
    for (int m = tid; m < 800; m += 256) {
        float s = 0.f;
#pragma unroll 8
        for (int c = 0; c < 128; c++) s = fmaf(bgc[c], knT[(size_t)c * 800 + m], s);
        sc[m] = s;
    }
    __syncthreads();
    if (tid < 32) {
        const int lane = tid;
        float ss = 0.f;
#pragma unroll
        for (int j = 0; j < 4; j++) { float v = bgc[lane * 4 + j]; ss = fmaf(v, v, ss); }
#pragma unroll
        for (int o = 16; o > 0; o >>= 1) ss += __shfl_xor_sync(0xffffffffu, ss, o);
        float scale = 1.0f / fmaxf(sqrtf(ss), 1e-12f);
        float lv[10]; int li[10];
#pragma unroll
        for (int j = 0; j < 10; j++) { lv[j] = -INFINITY; li[j] = 0x7fffffff; }
        for (int t = 0; t < 25; t++) {
            int m = lane + 32 * t;
            float v = sc[m];
            int i = m;
#pragma unroll
            for (int j = 0; j < 10; j++) {
                bool better = (v > lv[j]) || (v == lv[j] && i < li[j]);
                if (better) {
                    float tv = lv[j]; lv[j] = v; v = tv;
                    int ti = li[j]; li[j] = i; i = ti;
                }
            }
        }
        float bv[10]; int bi[10];
#pragma unroll
        for (int k = 0; k < 10; k++) {
            float cv = lv[0]; int ci = li[0];
#pragma unroll
            for (int off = 16; off > 0; off >>= 1) {
                float ov = __shfl_xor_sync(0xffffffffu, cv, off);
                int   oi = __shfl_xor_sync(0xffffffffu, ci, off);
                if (ov > cv || (ov == cv && oi < ci)) { cv = ov; ci = oi; }
            }
            bv[k] = cv; bi[k] = ci;
            if (lv[0] == cv && li[0] == ci) {
#pragma unroll
                for (int j = 0; j < 9; j++) { lv[j] = lv[j + 1]; li[j] = li[j + 1]; }
                lv[9] = -INFINITY; li[9] = 0x7fffffff;
            }
        }
        if (lane == 0) {
            float mx = bv[0] * scale;
            float e[10], sum = 0.f;
#pragma unroll
            for (int k = 0; k < 10; k++) { e[k] = expf(bv[k] * scale - mx); sum += e[k]; }
            float inv = 1.0f / sum;
#pragma unroll
            for (int k = 0; k < 10; k++) { swidx[k] = bi[k]; sww[k] = e[k] * inv; }
        }
    }
    __syncthreads();
    if (tid < 128) {
        float a = 0.f;
#pragma unroll
        for (int k = 0; k < 10; k++)
            a = fmaf(vals[(size_t)swidx[k] * 128 + tid], sww[k], a);
        bgz[tid] = a;
    }
}

// ====================================================================
// Fill zm center channels [0,128) with background z_match
// ====================================================================
__global__ void k_fillbg(float* __restrict__ zm, const float* __restrict__ bgz)
{
    int i = blockIdx.x * 256 + threadIdx.x;   // < 16*128*4096
    int c = (i >> 12) & 127;
    int b = i >> 19;
    zm[((size_t)b * 256 + c) * 4096 + (i & 4095)] = __ldg(&bgz[c]);
}

// ====================================================================
// Fill A (enc1-center out) with relu(b1[c])
// ====================================================================
__global__ void k_fillA(float* __restrict__ A, const float* __restrict__ b1)
{
    int i = blockIdx.x * blockDim.x + threadIdx.x;   // < 16*32*16384
    int c = (i >> 14) & 31;
    A[i] = fmaxf(b1[c], 0.f);
}

// ====================================================================
// Encoder stage 1: conv3x3 (1 -> CO) + relu + maxpool2, tile offset.
// ====================================================================
template<int CO, bool MASK>
__global__ __launch_bounds__(256) void k_enc1(const float* __restrict__ x,
    const float* __restrict__ w, const float* __restrict__ bias,
    float* __restrict__ out, int offX, int offY)
{
    __shared__ float tile[34][36];
    __shared__ float sw[CO * 9];
    __shared__ float sb[CO];
    const int t  = threadIdx.x;
    const int b  = blockIdx.z;
    const int Y0 = (blockIdx.y + offY) * 32;
    const int X0 = (blockIdx.x + offX) * 32;
    const float* xb = x + (size_t)b * 65536;
    for (int i = t; i < 34 * 34; i += 256) {
        int r = i / 34, c = i % 34;
        int gy = Y0 + r - 1, gx = X0 + c - 1;
        bool ok = (gy >= 0 && gy < 256 && gx >= 0 && gx < 256);
        if (MASK) ok = ok && (gy >= 96 && gy < 160 && gx >= 96 && gx < 160);
        tile[r][c] = ok ? xb[gy * 256 + gx] : 0.f;
    }
    for (int i = t; i < CO * 9; i += 256) sw[i] = w[i];
    if (t < CO) sb[t] = bias[t];
    __syncthreads();
    const int ty = t >> 4, tx = t & 15;
    float p[4][4];
#pragma unroll
    for (int i = 0; i < 4; i++)
#pragma unroll
        for (int j = 0; j < 4; j++) p[i][j] = tile[2 * ty + i][2 * tx + j];
    const int py = (blockIdx.y + offY) * 16 + ty, px = (blockIdx.x + offX) * 16 + tx;
    float* ob = out + (size_t)b * CO * 128 * 128 + py * 128 + px;
#pragma unroll 4
    for (int oc = 0; oc < CO; oc++) {
        float w9[9];
#pragma unroll
        for (int k = 0; k < 9; k++) w9[k] = sw[oc * 9 + k];
        float bv = sb[oc];
        float m = -INFINITY;
#pragma unroll
        for (int i = 0; i < 2; i++)
#pragma unroll
            for (int j = 0; j < 2; j++) {
                float s = bv;
#pragma unroll
                for (int dy = 0; dy < 3; dy++)
#pragma unroll
                    for (int dx = 0; dx < 3; dx++)
                        s = fmaf(w9[dy * 3 + dx], p[i + dy][j + dx], s);
                m = fmaxf(m, fmaxf(s, 0.f));
            }
        ob[(size_t)oc * 128 * 128] = m;
    }
}

// ====================================================================
// conv3x3 pad1, OIHW weights. 64(w) x 32(h) output tile, 128 threads,
// 4x4 px per thread, IC chunks of 4, optional relu / fused maxpool2.
// offXpx/offYpx are pixel offsets of the tiled region.
// grid: x = tilesX, y = tilesY * (OC/OCB), z = B
// ====================================================================
template<int OCB, bool RELU, bool POOL>
__global__ __launch_bounds__(128) void k_conv3c(const float* __restrict__ in,
    const float* __restrict__ w, const float* __restrict__ bias,
    float* __restrict__ out, int IC, int OC, int H, int W, int tilesY,
    int offXpx, int offYpx)
{
    __shared__ float tin[4][34][66];
    __shared__ float sw[OCB][4][9];
    const int tY = blockIdx.y % tilesY;
    const int ob = blockIdx.y / tilesY;
    const int Y0 = tY * 32 + offYpx;
    const int X0 = blockIdx.x * 64 + offXpx;
    const int b  = blockIdx.z;
    const int tid = threadIdx.x;
    const int ty = tid >> 4;      // 0..7  (4 rows each)
    const int tx = tid & 15;      // 0..15 (4 cols each)
    float acc[OCB][4][4];
#pragma unroll
    for (int o = 0; o < OCB; o++)
#pragma unroll
        for (int e = 0; e < 4; e++)
#pragma unroll
            for (int f = 0; f < 4; f++) acc[o][e][f] = 0.f;
    const float* inb = in + (size_t)b * IC * H * W;
    for (int ic0 = 0; ic0 < IC; ic0 += 4) {
        __syncthreads();
        for (int i = tid; i < 4 * 34 * 66; i += 128) {
            int ic = i / (34 * 66); int rem = i % (34 * 66);
            int r = rem / 66, c = rem % 66;
            int gy = Y0 + r - 1, gx = X0 + c - 1;
            float v = 0.f;
            if (gy >= 0 && gy < H && gx >= 0 && gx < W)
                v = inb[(size_t)(ic0 + ic) * H * W + gy * W + gx];
            tin[ic][r][c] = v;
        }
        for (int i = tid; i < OCB * 4 * 9; i += 128) {
            int o = i / 36; int rem = i % 36; int ic = rem / 9; int k = rem % 9;
            sw[o][ic][k] = w[((size_t)(ob * OCB + o) * IC + ic0 + ic) * 9 + k];
        }
        __syncthreads();
#pragma unroll
        for (int ic = 0; ic < 4; ic++) {
            float p[6][6];
#pragma unroll
            for (int i = 0; i < 6; i++)
#pragma unroll
                for (int j = 0; j < 6; j++)
                    p[i][j] = tin[ic][4 * ty + i][4 * tx + j];
#pragma unroll
            for (int o = 0; o < OCB; o++) {
                float w9[9];
#pragma unroll
                for (int k = 0; k < 9; k++) w9[k] = sw[o][ic][k];
#pragma unroll
                for (int e = 0; e < 4; e++)
#pragma unroll
                    for (int f = 0; f < 4; f++) {
                        float s = acc[o][e][f];
#pragma unroll
                        for (int dy = 0; dy < 3; dy++)
#pragma unroll
                            for (int dx = 0; dx < 3; dx++)
                                s = fmaf(w9[dy * 3 + dx], p[e + dy][f + dx], s);
                        acc[o][e][f] = s;
                    }
            }
        }
    }
#pragma unroll
    for (int o = 0; o < OCB; o++) {
        int oc = ob * OCB + o;
        float bv = bias[oc];
        if (POOL) {
            int Ho = H >> 1, Wo = W >> 1;
#pragma unroll
            for (int e = 0; e < 2; e++)
#pragma unroll
                for (int f = 0; f < 2; f++) {
                    float m = -INFINITY;
#pragma unroll
                    for (int r = 0; r < 2; r++)
#pragma unroll
                        for (int c = 0; c < 2; c++)
                            m = fmaxf(m, fmaxf(acc[o][2 * e + r][2 * f + c] + bv, 0.f));
                    out[((size_t)((size_t)b * OC + oc) * Ho + ((Y0 >> 1) + 2 * ty + e)) * Wo
                        + (X0 >> 1) + 2 * tx + f] = m;
                }
        } else {
#pragma unroll
            for (int e = 0; e < 4; e++) {
                float v0 = acc[o][e][0] + bv, v1 = acc[o][e][1] + bv;
                float v2 = acc[o][e][2] + bv, v3 = acc[o][e][3] + bv;
                if (RELU) {
                    v0 = fmaxf(v0, 0.f); v1 = fmaxf(v1, 0.f);
                    v2 = fmaxf(v2, 0.f); v3 = fmaxf(v3, 0.f);
                }
                *(float4*)(out + ((size_t)((size_t)b * OC + oc) * H + (Y0 + 4 * ty + e)) * W
                               + X0 + 4 * tx) = make_float4(v0, v1, v2, v3);
            }
        }
    }
}

// ====================================================================
// Center active GEMM: S_act[b*384+ai][m] = sum_c zc[b][c][n(ai)]*knT[c][m]
// ====================================================================
__global__ __launch_bounds__(256) void k_gemm_act(const float* __restrict__ A,
    const float* __restrict__ Bm, float* __restrict__ S)
{
    __shared__ float As[16][128];
    __shared__ float Bs[16][64];
    __shared__ int   map[128];
    const int b  = blockIdx.z;
    const int n0 = blockIdx.y * 128;
    const int m0 = blockIdx.x * 64;
    const int tid = threadIdx.x;
    const int tm = tid & 15, tn = tid >> 4;
    if (tid < 128) {
        int ai = n0 + tid;
        map[tid] = (ai < 324) ? ((23 + ai / 18) * 64 + 23 + ai % 18) : (23 * 64 + 23);
    }
    float acc[8][4];
#pragma unroll
    for (int i = 0; i < 8; i++)
#pragma unroll
        for (int j = 0; j < 4; j++) acc[i][j] = 0.f;
    const float* Ab = A + (size_t)b * 128 * 4096;
    const int lkB = tid >> 4, lmB = (tid * 4) & 63;
    __syncthreads();
    for (int k0 = 0; k0 < 128; k0 += 16) {
        __syncthreads();
#pragma unroll
        for (int j = 0; j < 8; j++) {
            int idx = tid * 8 + j;
            int lk = idx >> 7, ln = idx & 127;
            As[lk][ln] = Ab[(size_t)(k0 + lk) * 4096 + map[ln]];
        }
        float4 bv = make_float4(0.f, 0.f, 0.f, 0.f);
        if (m0 + lmB < 800)
            bv = *(const float4*)&Bm[(size_t)(k0 + lkB) * 800 + m0 + lmB];
        *(float4*)&Bs[lkB][lmB] = bv;
        __syncthreads();
#pragma unroll
        for (int k = 0; k < 16; k++) {
            float4 a0 = *(float4*)&As[k][tn * 8];
            float4 a1 = *(float4*)&As[k][tn * 8 + 4];
            float4 bb = *(float4*)&Bs[k][tm * 4];
            float av[8] = {a0.x, a0.y, a0.z, a0.w, a1.x, a1.y, a1.z, a1.w};
#pragma unroll
            for (int i = 0; i < 8; i++) {
                acc[i][0] = fmaf(av[i], bb.x, acc[i][0]);
                acc[i][1] = fmaf(av[i], bb.y, acc[i][1]);
                acc[i][2] = fmaf(av[i], bb.z, acc[i][2]);
                acc[i][3] = fmaf(av[i], bb.w, acc[i][3]);
            }
        }
    }
    const int m = m0 + tm * 4;
    if (m < 800) {
#pragma unroll
        for (int i = 0; i < 8; i++) {
            size_t row = (size_t)b * 384 + n0 + tn * 8 + i;
            *(float4*)&S[row * 800 + m] =
                make_float4(acc[i][0], acc[i][1], acc[i][2], acc[i][3]);
        }
    }
}

// ====================================================================
// Active top-10 + softmax (scale inline from zc). 5184 warps.
// ====================================================================
__global__ void k_topk_act(const float* __restrict__ S, const float* __restrict__ zc,
                           int* __restrict__ tidx, float* __restrict__ tw)
{
    int gw = (blockIdx.x * blockDim.x + threadIdx.x) >> 5;
    int lane = threadIdx.x & 31;
    if (gw >= 16 * 324) return;
    const int b = gw / 324, ai = gw % 324;
    const int n = (23 + ai / 18) * 64 + 23 + ai % 18;
    const float* zb = zc + (size_t)b * 128 * 4096 + n;
    float ss = 0.f;
#pragma unroll
    for (int j = 0; j < 4; j++) {
        float v = zb[(size_t)(lane + 32 * j) * 4096];
        ss = fmaf(v, v, ss);
    }
#pragma unroll
    for (int o = 16; o > 0; o >>= 1) ss += __shfl_xor_sync(0xffffffffu, ss, o);
    float sc = 1.0f / fmaxf(sqrtf(ss), 1e-12f);

    const float* row = S + ((size_t)b * 384 + ai) * 800;
    float lv[10]; int li[10];
#pragma unroll
    for (int j = 0; j < 10; j++) { lv[j] = -INFINITY; li[j] = 0x7fffffff; }
    for (int t = 0; t < 25; t++) {
        int m = lane + 32 * t;
        float v = row[m];
        int i = m;
#pragma unroll
        for (int j = 0; j < 10; j++) {
            bool better = (v > lv[j]) || (v == lv[j] && i < li[j]);
            if (better) {
                float tv = lv[j]; lv[j] = v; v = tv;
                int ti = li[j]; li[j] = i; i = ti;
            }
        }
    }
    float bv[10]; int bi[10];
#pragma unroll
    for (int k = 0; k < 10; k++) {
        float cv = lv[0]; int ci = li[0];
#pragma unroll
        for (int off = 16; off > 0; off >>= 1) {
            float ov = __shfl_xor_sync(0xffffffffu, cv, off);
            int   oi = __shfl_xor_sync(0xffffffffu, ci, off);
            if (ov > cv || (ov == cv && oi < ci)) { cv = ov; ci = oi; }
        }
        bv[k] = cv; bi[k] = ci;
        if (lv[0] == cv && li[0] == ci) {
#pragma unroll
            for (int j = 0; j < 9; j++) { lv[j] = lv[j + 1]; li[j] = li[j + 1]; }
            lv[9] = -INFINITY; li[9] = 0x7fffffff;
        }
    }
    if (lane == 0) {
        float mx = bv[0] * sc;
        float e[10], sum = 0.f;
#pragma unroll
        for (int k = 0; k < 10; k++) { e[k] = expf(bv[k] * sc - mx); sum += e[k]; }
        float inv = 1.0f / sum;
#pragma unroll
        for (int k = 0; k < 10; k++) {
            tidx[gw * 10 + k] = bi[k];
            tw[gw * 10 + k]   = e[k] * inv;
        }
    }
}

// ====================================================================
// Active weighted gather -> zm channels [0,128)
// ====================================================================
__global__ void k_gatherC_act(const float* __restrict__ vals, const int* __restrict__ tidx,
                              const float* __restrict__ tw, float* __restrict__ zm)
{
    __shared__ int   sidx[8][10];
    __shared__ float swt [8][10];
    const int r0 = blockIdx.x * 8;
    const int tid = threadIdx.x;
    if (tid < 80) {
        int ny = tid / 10, k = tid % 10;
        sidx[ny][k] = tidx[(size_t)(r0 + ny) * 10 + k];
        swt [ny][k] = tw  [(size_t)(r0 + ny) * 10 + k];
    }
    __syncthreads();
    const int cx = tid & 31, ny = tid >> 5;
    const int row = r0 + ny;
    const int b = row / 324, ai = row % 324;
    const int n = (23 + ai / 18) * 64 + 23 + ai % 18;
#pragma unroll
    for (int cc = 0; cc < 4; cc++) {
        int c = cx + 32 * cc;
        float acc = 0.f;
#pragma unroll
        for (int k = 0; k < 10; k++)
            acc = fmaf(vals[(size_t)sidx[ny][k] * 128 + c], swt[ny][k], acc);
        zm[((size_t)b * 256 + c) * 4096 + n] = acc;
    }
}

// ====================================================================
// Skip GEMM + fused argmax. Tile 128n, m chunks of 128, 8x8 micro.
// ====================================================================
__global__ __launch_bounds__(256) void k_gemm_amax(const float* __restrict__ A,
    const float* __restrict__ Bm, int* __restrict__ amax)
{
    __shared__ float As[16][128];
    __shared__ float Bs[16][128];
    __shared__ float rv[128][17];
    __shared__ int   ri[128][17];
    const int b  = blockIdx.y;
    const int n0 = blockIdx.x * 128;
    const int tid = threadIdx.x;
    const int tm = tid & 15, tn = tid >> 4;
    const int lk = tid >> 4, ln = (tid & 15) * 8;
    const float* Ab = A + (size_t)b * 128 * 4096;
    float bestv[8]; int besti[8];
#pragma unroll
    for (int i = 0; i < 8; i++) { bestv[i] = -INFINITY; besti[i] = 0x7fffffff; }
    for (int m0 = 0; m0 < 800; m0 += 128) {
        float acc[8][8];
#pragma unroll
        for (int i = 0; i < 8; i++)
#pragma unroll
            for (int j = 0; j < 8; j++) acc[i][j] = 0.f;
        for (int k0 = 0; k0 < 128; k0 += 16) {
            __syncthreads();
            const float* ap = &Ab[(size_t)(k0 + lk) * 4096 + n0 + ln];
            *(float4*)&As[lk][ln]     = *(const float4*)ap;
            *(float4*)&As[lk][ln + 4] = *(const float4*)(ap + 4);
            if (m0 + ln + 7 < 800) {
                const float* bp = &Bm[(size_t)(k0 + lk) * 800 + m0 + ln];
                *(float4*)&Bs[lk][ln]     = *(const float4*)bp;
                *(float4*)&Bs[lk][ln + 4] = *(const float4*)(bp + 4);
            } else {
#pragma unroll
                for (int j = 0; j < 8; j++)
                    Bs[lk][ln + j] = (m0 + ln + j < 800)
                        ? Bm[(size_t)(k0 + lk) * 800 + m0 + ln + j] : 0.f;
            }
            __syncthreads();
#pragma unroll
            for (int k = 0; k < 16; k++) {
                float4 a0 = *(float4*)&As[k][tn * 8];
                float4 a1 = *(float4*)&As[k][tn * 8 + 4];
                float4 b0 = *(float4*)&Bs[k][tm * 8];
                float4 b1 = *(float4*)&Bs[k][tm * 8 + 4];
                float av[8] = {a0.x, a0.y, a0.z, a0.w, a1.x, a1.y, a1.z, a1.w};
                float bw[8] = {b0.x, b0.y, b0.z, b0.w, b1.x, b1.y, b1.z, b1.w};
#pragma unroll
                for (int i = 0; i < 8; i++)
#pragma unroll
                    for (int j = 0; j < 8; j++)
                        acc[i][j] = fmaf(av[i], bw[j], acc[i][j]);
            }
        }
#pragma unroll
        for (int i = 0; i < 8; i++)
#pragma unroll
            for (int j = 0; j < 8; j++) {
                int m = m0 + tm * 8 + j;
                float v = acc[i][j];
                if (m < 800 && (v > bestv[i] || (v == bestv[i] && m < besti[i]))) {
                    bestv[i] = v; besti[i] = m;
                }
            }
    }
    __syncthreads();
#pragma unroll
    for (int i = 0; i < 8; i++) { rv[tn * 8 + i][tm] = bestv[i]; ri[tn * 8 + i][tm] = besti[i]; }
    __syncthreads();
    if (tid < 128) {
        float bv = -INFINITY; int bi = 0x7fffffff;
#pragma unroll
        for (int t = 0; t < 16; t++) {
            float v = rv[tid][t]; int i = ri[tid][t];
            if (v > bv || (v == bv && i < bi)) { bv = v; bi = i; }
        }
        amax[b * 4096 + n0 + tid] = bi;
    }
}

// ====================================================================
// Hard gather -> zm channels [128,256)
// ====================================================================
__global__ void k_gatherS(const float* __restrict__ hard, const int* __restrict__ amax,
                          float* __restrict__ zm)
{
    const int r0 = blockIdx.x * 8;
    const int tid = threadIdx.x;
    const int cx = tid & 31, ny = tid >> 5;
    const int row = r0 + ny;
    const int b = row >> 12, n = row & 4095;
    const int a = amax[row];
#pragma unroll
    for (int cc = 0; cc < 4; cc++) {
        int c = cx + 32 * cc;
        zm[((size_t)b * 256 + 128 + c) * 4096 + n] = hard[(size_t)a * 128 + c];
    }
}

// ====================================================================
// Transposed conv (k=4, s=2) + relu. 64x64 output tile, 4x4 px/thread.
// ====================================================================
template<int IC, int OC, int OCB>
__global__ __launch_bounds__(256) void k_deconv(const float* __restrict__ in,
    const float* __restrict__ w, const float* __restrict__ bias,
    float* __restrict__ out, int Hi, int tilesY)
{
    __shared__ float tin[2][34][36];
    __shared__ float sw[2][OCB][16];
    const int Ho = 2 * Hi;
    const int tY = blockIdx.y % tilesY;
    const int ob = blockIdx.y / tilesY;
    const int b  = blockIdx.z;
    const int Xo0 = blockIdx.x * 64, Yo0 = tY * 64;
    const int a0 = Yo0 >> 1, c0 = Xo0 >> 1;
    const int tid = threadIdx.x;
    const int ty = tid >> 4, tx = tid & 15;
    float acc[OCB][4][4];
#pragma unroll
    for (int o = 0; o < OCB; o++)
#pragma unroll
        for (int r = 0; r < 4; r++)
#pragma unroll
            for (int c = 0; c < 4; c++) acc[o][r][c] = 0.f;
    const float* inb = in + (size_t)b * IC * Hi * Hi;
    for (int ic0 = 0; ic0 < IC; ic0 += 2) {
        __syncthreads();
        for (int i = tid; i < 2 * 34 * 34; i += 256) {
            int ic = i / (34 * 34); int rem = i % (34 * 34);
            int r = rem / 34, c = rem % 34;
            int gy = a0 + r - 1, gx = c0 + c - 1;
            float v = 0.f;
            if (gy >= 0 && gy < Hi && gx >= 0 && gx < Hi)
                v = inb[(size_t)(ic0 + ic) * Hi * Hi + gy * Hi + gx];
            tin[ic][r][c] = v;
        }
        for (int i = tid; i < 2 * OCB * 16; i += 256) {
            int ic = i / (OCB * 16); int rem = i % (OCB * 16);
            int o = rem / 16; int t = rem % 16;
            sw[ic][o][t] = w[((size_t)(ic0 + ic) * OC + ob * OCB + o) * 16 + t];
        }
        __syncthreads();
#pragma unroll
        for (int ic = 0; ic < 2; ic++) {
            float p[4][4];
#pragma unroll
            for (int i = 0; i < 4; i++)
#pragma unroll
                for (int j = 0; j < 4; j++)
                    p[i][j] = tin[ic][2 * ty + i][2 * tx + j];
#pragma unroll
            for (int o = 0; o < OCB; o++) {
                float W4[16];
#pragma unroll
                for (int t = 0; t < 16; t++) W4[t] = sw[ic][o][t];
#pragma unroll
                for (int e = 0; e < 2; e++)
#pragma unroll
                    for (int f = 0; f < 2; f++) {
                        float P00 = p[e][f],     P01 = p[e][f + 1],     P02 = p[e][f + 2];
                        float P10 = p[e + 1][f], P11 = p[e + 1][f + 1], P12 = p[e + 1][f + 2];
                        float P20 = p[e + 2][f], P21 = p[e + 2][f + 1], P22 = p[e + 2][f + 2];
                        acc[o][2 * e][2 * f]         += W4[15] * P00 + W4[13] * P01 + W4[7] * P10 + W4[5] * P11;
                        acc[o][2 * e][2 * f + 1]     += W4[14] * P01 + W4[12] * P02 + W4[6] * P11 + W4[4] * P12;
                        acc[o][2 * e + 1][2 * f]     += W4[11] * P10 + W4[9]  * P11 + W4[3] * P20 + W4[1] * P21;
                        acc[o][2 * e + 1][2 * f + 1] += W4[10] * P11 + W4[8]  * P12 + W4[2] * P21 + W4[0] * P22;
                    }
            }
        }
    }
#pragma unroll
    for (int o = 0; o < OCB; o++) {
        int oc = ob * OCB + o;
        float bv = bias[oc];
#pragma unroll
        for (int r = 0; r < 4; r++)
#pragma unroll
            for (int c = 0; c < 4; c += 2) {
                float v0 = fmaxf(acc[o][r][c] + bv, 0.f);
                float v1 = fmaxf(acc[o][r][c + 1] + bv, 0.f);
                *(float2*)(out + ((size_t)((size_t)b * OC + oc) * Ho + (Yo0 + 4 * ty + r)) * Ho
                               + Xo0 + 4 * tx + c) = make_float2(v0, v1);
            }
    }
}

// ====================================================================
// Host launcher — fork/join multi-stream (capture-safe event pattern)
// ====================================================================
static cudaStream_t s_bg = nullptr, s_skip = nullptr;
static cudaEvent_t  e_root = nullptr, e_bgdone = nullptr, e_skipdone = nullptr;

extern "C" void kernel_launch(void* const* d_in, const int* in_sizes, int n_in,
                              void* d_out, int out_size)
{
    if (!s_bg) {
        cudaStreamCreateWithFlags(&s_bg,   cudaStreamNonBlocking);
        cudaStreamCreateWithFlags(&s_skip, cudaStreamNonBlocking);
        cudaEventCreateWithFlags(&e_root,     cudaEventDisableTiming);
        cudaEventCreateWithFlags(&e_bgdone,   cudaEventDisableTiming);
        cudaEventCreateWithFlags(&e_skipdone, cudaEventDisableTiming);
    }
    const float* x        = (const float*)d_in[0];
    const float* ce_w1    = (const float*)d_in[1];
    const float* ce_b1    = (const float*)d_in[2];
    const float* ce_w2    = (const float*)d_in[3];
    const float* ce_b2    = (const float*)d_in[4];
    const float* se_w1    = (const float*)d_in[5];
    const float* se_b1    = (const float*)d_in[6];
    const float* se_w2    = (const float*)d_in[7];
    const float* se_b2    = (const float*)d_in[8];
    const float* mem_keys = (const float*)d_in[9];
    const float* mem_vals = (const float*)d_in[10];
    const float* mem_hard = (const float*)d_in[11];
    const float* dec_w1   = (const float*)d_in[12];
    const float* dec_b1   = (const float*)d_in[13];
    const float* dec_tw1  = (const float*)d_in[14];
    const float* dec_tb1  = (const float*)d_in[15];
    const float* dec_tw2  = (const float*)d_in[16];
    const float* dec_tb2  = (const float*)d_in[17];
    const float* dec_w2   = (const float*)d_in[18];
    const float* dec_b2   = (const float*)d_in[19];
    float* outp = (float*)d_out;

    float *knT, *hnT, *A, *A2, *zc, *zs, *Sact, *tw, *bgz, *zm, *d1, *u1, *u2;
    int *tidx, *amax;
    cudaGetSymbolAddress((void**)&knT,  g_knT);
    cudaGetSymbolAddress((void**)&hnT,  g_hnT);
    cudaGetSymbolAddress((void**)&A,    g_A);
    cudaGetSymbolAddress((void**)&A2,   g_A2);
    cudaGetSymbolAddress((void**)&zc,   g_zc);
    cudaGetSymbolAddress((void**)&zs,   g_zs);
    cudaGetSymbolAddress((void**)&Sact, g_Sact);
    cudaGetSymbolAddress((void**)&tidx, g_tidx);
    cudaGetSymbolAddress((void**)&tw,   g_tw);
    cudaGetSymbolAddress((void**)&amax, g_amax);
    cudaGetSymbolAddress((void**)&bgz,  g_bgz);
    cudaGetSymbolAddress((void**)&zm,   g_zm);
    cudaGetSymbolAddress((void**)&d1,   g_d1);
    cudaGetSymbolAddress((void**)&u1,   g_u1);
    cudaGetSymbolAddress((void**)&u2,   g_u2);

    // root: normalized memory tables
    k_normrows<<<200, 256>>>(mem_keys, mem_hard, knT, hnT);
    cudaEventRecord(e_root, 0);

    // ---- bg branch ----
    cudaStreamWaitEvent(s_bg, e_root, 0);
    k_bg<<<1, 256, 0, s_bg>>>(ce_w2, ce_b1, ce_b2, knT, mem_vals, bgz);
    k_fillbg<<<(16 * 128 * 4096) / 256, 256, 0, s_bg>>>(zm, bgz);
    cudaEventRecord(e_bgdone, s_bg);

    // ---- skip branch ----
    cudaStreamWaitEvent(s_skip, e_root, 0);
    k_enc1<16, false><<<dim3(8, 8, 16), 256, 0, s_skip>>>(x, se_w1, se_b1, A2, 0, 0);
    k_conv3c<4, true, true><<<dim3(2, 4 * 32, 16), 128, 0, s_skip>>>(
        A2, se_w2, se_b2, zs, 16, 128, 128, 128, 4, 0, 0);
    k_gemm_amax<<<dim3(32, 16), 256, 0, s_skip>>>(zs, hnT, amax);
    k_gatherS<<<8192, 256, 0, s_skip>>>(mem_hard, amax, zm);
    cudaEventRecord(e_skipdone, s_skip);

    // ---- center branch (main stream) ----
    k_fillA<<<(16 * 32 * 16384) / 256, 256>>>(A, ce_b1);
    k_enc1<32, true><<<dim3(4, 4, 16), 256>>>(x, ce_w1, ce_b1, A, 2, 2);
    k_conv3c<4, true, true><<<dim3(1, 2 * 32, 16), 128>>>(
        A, ce_w2, ce_b2, zc, 32, 128, 128, 128, 2, 32, 32);
    k_gemm_act<<<dim3(13, 3, 16), 256>>>(zc, knT, Sact);
    k_topk_act<<<(16 * 324 + 7) / 8, 256>>>(Sact, zc, tidx, tw);
    cudaStreamWaitEvent(0, e_bgdone, 0);
    k_gatherC_act<<<(16 * 324) / 8, 256>>>(mem_vals, tidx, tw, zm);

    // ---- join, decoder ----
    cudaStreamWaitEvent(0, e_skipdone, 0);
    k_conv3c<4, true, false><<<dim3(1, 2 * 16, 16), 128>>>(
        zm, dec_w1, dec_b1, d1, 256, 64, 64, 64, 2, 0, 0);
    k_deconv<64, 32, 4><<<dim3(2, 2 * 8, 16), 256>>>(d1, dec_tw1, dec_tb1, u1, 64, 2);
    k_deconv<32, 16, 4><<<dim3(4, 4 * 4, 16), 256>>>(u1, dec_tw2, dec_tb2, u2, 128, 4);
    k_conv3c<1, false, false><<<dim3(4, 8, 16), 128>>>(
        u2, dec_w2, dec_b2, outp, 16, 1, 256, 256, 8, 0, 0);
}

// round 10
// speedup vs baseline: 1.5887x; 1.0741x over previous
#include <cuda_runtime.h>
#include <math.h>
#include <stdint.h>

// ====================================================================
// Static device scratch
// ====================================================================
__device__ __align__(256) float g_knT[128 * 800];
__device__ __align__(256) float g_hnT[128 * 800];
__device__ __align__(256) float g_A  [16 * 32 * 128 * 128];   // center enc1 out
__device__ __align__(256) float g_A2 [16 * 16 * 128 * 128];   // skip enc1 out
__device__ __align__(256) float g_zc [16 * 128 * 64 * 64];
__device__ __align__(256) float g_zs [16 * 128 * 64 * 64];
__device__ __align__(256) float g_Sact[16 * 384 * 800];
__device__ __align__(256) int   g_tidx[16 * 324 * 10];
__device__ __align__(256) float g_tw  [16 * 324 * 10];
__device__ __align__(256) int   g_amax[65536];
__device__ __align__(256) float g_bgz [128];
__device__ __align__(256) float g_c9  [64 * 9];
__device__ __align__(256) float g_gdelta[16 * 128 * 324];
__device__ __align__(256) float g_zmS[16 * 128 * 64 * 64];    // skip gather only
__device__ __align__(256) float g_d1 [16 * 64 * 64 * 64];     // raw (pre-relu)
__device__ __align__(256) float g_u1 [16 * 32 * 128 * 128];
__device__ __align__(256) float g_u2 [16 * 16 * 256 * 256];

// ====================================================================
// Normalize memory rows -> transposed tables knT[c][m], hnT[c][m]
// ====================================================================
__global__ void k_normrows(const float* __restrict__ keys,
                           const float* __restrict__ hard,
                           float* __restrict__ knT, float* __restrict__ hnT)
{
    int gw = (blockIdx.x * blockDim.x + threadIdx.x) >> 5;
    int lane = threadIdx.x & 31;
    if (gw >= 1600) return;
    const float* src; float* dst; int r;
    if (gw < 800) { src = keys; dst = knT; r = gw; }
    else          { src = hard; dst = hnT; r = gw - 800; }
    float4 v = *(const float4*)(src + (size_t)r * 128 + lane * 4);
    float s = v.x * v.x + v.y * v.y + v.z * v.z + v.w * v.w;
#pragma unroll
    for (int o = 16; o > 0; o >>= 1) s += __shfl_xor_sync(0xffffffffu, s, o);
    float d = 1.0f / fmaxf(sqrtf(s), 1e-12f);
    dst[(size_t)(4 * lane + 0) * 800 + r] = v.x * d;
    dst[(size_t)(4 * lane + 1) * 800 + r] = v.y * d;
    dst[(size_t)(4 * lane + 2) * 800 + r] = v.z * d;
    dst[(size_t)(4 * lane + 3) * 800 + r] = v.w * d;
}

// ====================================================================
// Background z_match: bgc -> scores -> topk -> softmax -> gather (1 block)
// ====================================================================
__global__ __launch_bounds__(256) void k_bg(const float* __restrict__ w2,
    const float* __restrict__ b1, const float* __restrict__ b2,
    const float* __restrict__ knT, const float* __restrict__ vals,
    float* __restrict__ bgz)
{
    __shared__ float bgc[128];
    __shared__ float sc[800];
    __shared__ int   swidx[10];
    __shared__ float sww[10];
    const int tid = threadIdx.x;
    if (tid < 128) {
        float s = b2[tid];
        for (int ic = 0; ic < 32; ic++) {
            float wsum = 0.f;
#pragma unroll
            for (int k = 0; k < 9; k++) wsum += w2[((size_t)tid * 32 + ic) * 9 + k];
            s = fmaf(wsum, fmaxf(b1[ic], 0.f), s);
        }
        bgc[tid] = fmaxf(s, 0.f);
    }
    __syncthreads();
    for (int m = tid; m < 800; m += 256) {
        float s = 0.f;
#pragma unroll 8
        for (int c = 0; c < 128; c++) s = fmaf(bgc[c], knT[(size_t)c * 800 + m], s);
        sc[m] = s;
    }
    __syncthreads();
    if (tid < 32) {
        const int lane = tid;
        float ss = 0.f;
#pragma unroll
        for (int j = 0; j < 4; j++) { float v = bgc[lane * 4 + j]; ss = fmaf(v, v, ss); }
#pragma unroll
        for (int o = 16; o > 0; o >>= 1) ss += __shfl_xor_sync(0xffffffffu, ss, o);
        float scale = 1.0f / fmaxf(sqrtf(ss), 1e-12f);
        float lv[10]; int li[10];
#pragma unroll
        for (int j = 0; j < 10; j++) { lv[j] = -INFINITY; li[j] = 0x7fffffff; }
        for (int t = 0; t < 25; t++) {
            int m = lane + 32 * t;
            float v = sc[m];
            int i = m;
#pragma unroll
            for (int j = 0; j < 10; j++) {
                bool better = (v > lv[j]) || (v == lv[j] && i < li[j]);
                if (better) {
                    float tv = lv[j]; lv[j] = v; v = tv;
                    int ti = li[j]; li[j] = i; i = ti;
                }
            }
        }
        float bv[10]; int bi[10];
#pragma unroll
        for (int k = 0; k < 10; k++) {
            float cv = lv[0]; int ci = li[0];
#pragma unroll
            for (int off = 16; off > 0; off >>= 1) {
                float ov = __shfl_xor_sync(0xffffffffu, cv, off);
                int   oi = __shfl_xor_sync(0xffffffffu, ci, off);
                if (ov > cv || (ov == cv && oi < ci)) { cv = ov; ci = oi; }
            }
            bv[k] = cv; bi[k] = ci;
            if (lv[0] == cv && li[0] == ci) {
#pragma unroll
                for (int j = 0; j < 9; j++) { lv[j] = lv[j + 1]; li[j] = li[j + 1]; }
                lv[9] = -INFINITY; li[9] = 0x7fffffff;
            }
        }
        if (lane == 0) {
            float mx = bv[0] * scale;
            float e[10], sum = 0.f;
#pragma unroll
            for (int k = 0; k < 10; k++) { e[k] = expf(bv[k] * scale - mx); sum += e[k]; }
            float inv = 1.0f / sum;
#pragma unroll
            for (int k = 0; k < 10; k++) { swidx[k] = bi[k]; sww[k] = e[k] * inv; }
        }
    }
    __syncthreads();
    if (tid < 128) {
        float a = 0.f;
#pragma unroll
        for (int k = 0; k < 10; k++)
            a = fmaf(vals[(size_t)swidx[k] * 128 + tid], sww[k], a);
        bgz[tid] = a;
    }
}

// ====================================================================
// C9 prep: c9[oc][cy][cx] = dec_b1[oc] + sum_ic<128 bgz[ic]*sum_{valid taps} w1
// cases: cy=0 (y==0): dy in {1,2}; cy=2 (y==H-1): dy in {0,1}; else all.
// ====================================================================
__global__ void k_prepC9(const float* __restrict__ w, const float* __restrict__ bias,
                         const float* __restrict__ bgz, float* __restrict__ c9)
{
    for (int idx = threadIdx.x; idx < 576; idx += 256) {
        int oc = idx / 9, cs = idx % 9, cy = cs / 3, cx = cs % 3;
        int dy0 = (cy == 0) ? 1 : 0, dy1 = (cy == 2) ? 1 : 2;
        int dx0 = (cx == 0) ? 1 : 0, dx1 = (cx == 2) ? 1 : 2;
        float s = bias[oc];
        for (int ic = 0; ic < 128; ic++) {
            float t = 0.f;
            const float* wp = w + ((size_t)oc * 256 + ic) * 9;
            for (int dy = dy0; dy <= dy1; dy++)
                for (int dx = dx0; dx <= dx1; dx++)
                    t += wp[dy * 3 + dx];
            s = fmaf(bgz[ic], t, s);
        }
        c9[idx] = s;
    }
}

// ====================================================================
// Fill A (enc1-center out) with relu(b1[c])
// ====================================================================
__global__ void k_fillA(float* __restrict__ A, const float* __restrict__ b1)
{
    int i = blockIdx.x * blockDim.x + threadIdx.x;   // < 16*32*16384
    int c = (i >> 14) & 31;
    A[i] = fmaxf(b1[c], 0.f);
}

// ====================================================================
// Encoder stage 1: conv3x3 (1 -> CO) + relu + maxpool2, tile offset.
// ====================================================================
template<int CO, bool MASK>
__global__ __launch_bounds__(256) void k_enc1(const float* __restrict__ x,
    const float* __restrict__ w, const float* __restrict__ bias,
    float* __restrict__ out, int offX, int offY)
{
    __shared__ float tile[34][36];
    __shared__ float sw[CO * 9];
    __shared__ float sb[CO];
    const int t  = threadIdx.x;
    const int b  = blockIdx.z;
    const int Y0 = (blockIdx.y + offY) * 32;
    const int X0 = (blockIdx.x + offX) * 32;
    const float* xb = x + (size_t)b * 65536;
    for (int i = t; i < 34 * 34; i += 256) {
        int r = i / 34, c = i % 34;
        int gy = Y0 + r - 1, gx = X0 + c - 1;
        bool ok = (gy >= 0 && gy < 256 && gx >= 0 && gx < 256);
        if (MASK) ok = ok && (gy >= 96 && gy < 160 && gx >= 96 && gx < 160);
        tile[r][c] = ok ? xb[gy * 256 + gx] : 0.f;
    }
    for (int i = t; i < CO * 9; i += 256) sw[i] = w[i];
    if (t < CO) sb[t] = bias[t];
    __syncthreads();
    const int ty = t >> 4, tx = t & 15;
    float p[4][4];
#pragma unroll
    for (int i = 0; i < 4; i++)
#pragma unroll
        for (int j = 0; j < 4; j++) p[i][j] = tile[2 * ty + i][2 * tx + j];
    const int py = (blockIdx.y + offY) * 16 + ty, px = (blockIdx.x + offX) * 16 + tx;
    float* ob = out + (size_t)b * CO * 128 * 128 + py * 128 + px;
#pragma unroll 4
    for (int oc = 0; oc < CO; oc++) {
        float w9[9];
#pragma unroll
        for (int k = 0; k < 9; k++) w9[k] = sw[oc * 9 + k];
        float bv = sb[oc];
        float m = -INFINITY;
#pragma unroll
        for (int i = 0; i < 2; i++)
#pragma unroll
            for (int j = 0; j < 2; j++) {
                float s = bv;
#pragma unroll
                for (int dy = 0; dy < 3; dy++)
#pragma unroll
                    for (int dx = 0; dx < 3; dx++)
                        s = fmaf(w9[dy * 3 + dx], p[i + dy][j + dx], s);
                m = fmaxf(m, fmaxf(s, 0.f));
            }
        ob[(size_t)oc * 128 * 128] = m;
    }
}

// ====================================================================
// conv3x3 pad1. 64(w) x 32(h) output tile, 128 threads, 4x4 px/thread.
// ICw = weight oc-stride (in ic units) for partial-channel convs.
// C9MODE: out = acc + c9[oc][cy][cx] (bias folded, no relu, no pool).
// ====================================================================
template<int OCB, bool RELU, bool POOL, bool C9MODE>
__global__ __launch_bounds__(128) void k_conv3c(const float* __restrict__ in,
    const float* __restrict__ w, const float* __restrict__ bias,
    float* __restrict__ out, int IC, int ICw, int OC, int H, int W, int tilesY,
    int offXpx, int offYpx, const float* __restrict__ c9)
{
    __shared__ float tin[4][34][66];
    __shared__ float sw[OCB][4][9];
    const int tY = blockIdx.y % tilesY;
    const int ob = blockIdx.y / tilesY;
    const int Y0 = tY * 32 + offYpx;
    const int X0 = blockIdx.x * 64 + offXpx;
    const int b  = blockIdx.z;
    const int tid = threadIdx.x;
    const int ty = tid >> 4;
    const int tx = tid & 15;
    float acc[OCB][4][4];
#pragma unroll
    for (int o = 0; o < OCB; o++)
#pragma unroll
        for (int e = 0; e < 4; e++)
#pragma unroll
            for (int f = 0; f < 4; f++) acc[o][e][f] = 0.f;
    const float* inb = in + (size_t)b * IC * H * W;
    for (int ic0 = 0; ic0 < IC; ic0 += 4) {
        __syncthreads();
        for (int i = tid; i < 4 * 34 * 66; i += 128) {
            int ic = i / (34 * 66); int rem = i % (34 * 66);
            int r = rem / 66, c = rem % 66;
            int gy = Y0 + r - 1, gx = X0 + c - 1;
            float v = 0.f;
            if (gy >= 0 && gy < H && gx >= 0 && gx < W)
                v = inb[(size_t)(ic0 + ic) * H * W + gy * W + gx];
            tin[ic][r][c] = v;
        }
        for (int i = tid; i < OCB * 4 * 9; i += 128) {
            int o = i / 36; int rem = i % 36; int ic = rem / 9; int k = rem % 9;
            sw[o][ic][k] = w[((size_t)(ob * OCB + o) * ICw + ic0 + ic) * 9 + k];
        }
        __syncthreads();
#pragma unroll
        for (int ic = 0; ic < 4; ic++) {
            float p[6][6];
#pragma unroll
            for (int i = 0; i < 6; i++)
#pragma unroll
                for (int j = 0; j < 6; j++)
                    p[i][j] = tin[ic][4 * ty + i][4 * tx + j];
#pragma unroll
            for (int o = 0; o < OCB; o++) {
                float w9[9];
#pragma unroll
                for (int k = 0; k < 9; k++) w9[k] = sw[o][ic][k];
#pragma unroll
                for (int e = 0; e < 4; e++)
#pragma unroll
                    for (int f = 0; f < 4; f++) {
                        float s = acc[o][e][f];
#pragma unroll
                        for (int dy = 0; dy < 3; dy++)
#pragma unroll
                            for (int dx = 0; dx < 3; dx++)
                                s = fmaf(w9[dy * 3 + dx], p[e + dy][f + dx], s);
                        acc[o][e][f] = s;
                    }
            }
        }
    }
#pragma unroll
    for (int o = 0; o < OCB; o++) {
        int oc = ob * OCB + o;
        if (C9MODE) {
#pragma unroll
            for (int e = 0; e < 4; e++) {
                int gy = Y0 + 4 * ty + e;
                int cyi = (gy == 0) ? 0 : ((gy == H - 1) ? 6 : 3);
                float vv[4];
#pragma unroll
                for (int f = 0; f < 4; f++) {
                    int gx = X0 + 4 * tx + f;
                    int cxi = (gx == 0) ? 0 : ((gx == W - 1) ? 2 : 1);
                    vv[f] = acc[o][e][f] + c9[oc * 9 + cyi + cxi];
                }
                *(float4*)(out + ((size_t)((size_t)b * OC + oc) * H + gy) * W
                               + X0 + 4 * tx) = make_float4(vv[0], vv[1], vv[2], vv[3]);
            }
        } else {
            float bv = bias[oc];
            if (POOL) {
                int Ho = H >> 1, Wo = W >> 1;
#pragma unroll
                for (int e = 0; e < 2; e++)
#pragma unroll
                    for (int f = 0; f < 2; f++) {
                        float m = -INFINITY;
#pragma unroll
                        for (int r = 0; r < 2; r++)
#pragma unroll
                            for (int c = 0; c < 2; c++)
                                m = fmaxf(m, fmaxf(acc[o][2 * e + r][2 * f + c] + bv, 0.f));
                        out[((size_t)((size_t)b * OC + oc) * Ho + ((Y0 >> 1) + 2 * ty + e)) * Wo
                            + (X0 >> 1) + 2 * tx + f] = m;
                    }
            } else {
#pragma unroll
                for (int e = 0; e < 4; e++) {
                    float v0 = acc[o][e][0] + bv, v1 = acc[o][e][1] + bv;
                    float v2 = acc[o][e][2] + bv, v3 = acc[o][e][3] + bv;
                    if (RELU) {
                        v0 = fmaxf(v0, 0.f); v1 = fmaxf(v1, 0.f);
                        v2 = fmaxf(v2, 0.f); v3 = fmaxf(v3, 0.f);
                    }
                    *(float4*)(out + ((size_t)((size_t)b * OC + oc) * H + (Y0 + 4 * ty + e)) * W
                                   + X0 + 4 * tx) = make_float4(v0, v1, v2, v3);
                }
            }
        }
    }
}

// ====================================================================
// Delta conv for dec1: d1[b][oc][y][x] += conv(gdelta) on window [22,42)^2
// gdelta: [16][128][324] (18x18, origin (23,23)). grid (4 ocg, 16 b).
// ====================================================================
__global__ __launch_bounds__(256) void k_dec1delta(
    const float* __restrict__ gdelta, const float* __restrict__ w,
    float* __restrict__ d1)
{
    __shared__ float sd[16][324];
    __shared__ float sw[16][16][9];
    const int b  = blockIdx.y;
    const int og = blockIdx.x;          // oc base og*16
    const int tid = threadIdx.x;
    float acc[2][16];
#pragma unroll
    for (int pp = 0; pp < 2; pp++)
#pragma unroll
        for (int o = 0; o < 16; o++) acc[pp][o] = 0.f;
    for (int ic0 = 0; ic0 < 128; ic0 += 16) {
        __syncthreads();
        for (int i = tid; i < 16 * 324; i += 256)
            sd[i / 324][i % 324] = gdelta[((size_t)b * 128 + ic0 + i / 324) * 324 + i % 324];
        for (int i = tid; i < 16 * 16 * 9; i += 256) {
            int o = i / 144, r = i % 144, ic = r / 9, k = r % 9;
            sw[o][ic][k] = w[((size_t)(og * 16 + o) * 256 + ic0 + ic) * 9 + k];
        }
        __syncthreads();
#pragma unroll
        for (int pp = 0; pp < 2; pp++) {
            int p = pp * 256 + tid;
            if (p >= 400) continue;
            int y = 22 + p / 20, x = 22 + p % 20;
            for (int ic = 0; ic < 16; ic++) {
                float pv[9];
#pragma unroll
                for (int dy = 0; dy < 3; dy++)
#pragma unroll
                    for (int dx = 0; dx < 3; dx++) {
                        int r = y - 24 + dy, c = x - 24 + dx;
                        pv[dy * 3 + dx] = (r >= 0 && r < 18 && c >= 0 && c < 18)
                            ? sd[ic][r * 18 + c] : 0.f;
                    }
#pragma unroll
                for (int o = 0; o < 16; o++) {
                    float s = acc[pp][o];
#pragma unroll
                    for (int k = 0; k < 9; k++) s = fmaf(sw[o][ic][k], pv[k], s);
                    acc[pp][o] = s;
                }
            }
        }
    }
#pragma unroll
    for (int pp = 0; pp < 2; pp++) {
        int p = pp * 256 + tid;
        if (p >= 400) continue;
        int y = 22 + p / 20, x = 22 + p % 20;
#pragma unroll
        for (int o = 0; o < 16; o++) {
            size_t idx = ((size_t)b * 64 + og * 16 + o) * 4096 + y * 64 + x;
            d1[idx] += acc[pp][o];
        }
    }
}

// ====================================================================
// Center active GEMM: S_act[b*384+ai][m] = sum_c zc[b][c][n(ai)]*knT[c][m]
// ====================================================================
__global__ __launch_bounds__(256) void k_gemm_act(const float* __restrict__ A,
    const float* __restrict__ Bm, float* __restrict__ S)
{
    __shared__ float As[16][128];
    __shared__ float Bs[16][64];
    __shared__ int   map[128];
    const int b  = blockIdx.z;
    const int n0 = blockIdx.y * 128;
    const int m0 = blockIdx.x * 64;
    const int tid = threadIdx.x;
    const int tm = tid & 15, tn = tid >> 4;
    if (tid < 128) {
        int ai = n0 + tid;
        map[tid] = (ai < 324) ? ((23 + ai / 18) * 64 + 23 + ai % 18) : (23 * 64 + 23);
    }
    float acc[8][4];
#pragma unroll
    for (int i = 0; i < 8; i++)
#pragma unroll
        for (int j = 0; j < 4; j++) acc[i][j] = 0.f;
    const float* Ab = A + (size_t)b * 128 * 4096;
    const int lkB = tid >> 4, lmB = (tid * 4) & 63;
    __syncthreads();
    for (int k0 = 0; k0 < 128; k0 += 16) {
        __syncthreads();
#pragma unroll
        for (int j = 0; j < 8; j++) {
            int idx = tid * 8 + j;
            int lk = idx >> 7, ln = idx & 127;
            As[lk][ln] = Ab[(size_t)(k0 + lk) * 4096 + map[ln]];
        }
        float4 bv = make_float4(0.f, 0.f, 0.f, 0.f);
        if (m0 + lmB < 800)
            bv = *(const float4*)&Bm[(size_t)(k0 + lkB) * 800 + m0 + lmB];
        *(float4*)&Bs[lkB][lmB] = bv;
        __syncthreads();
#pragma unroll
        for (int k = 0; k < 16; k++) {
            float4 a0 = *(float4*)&As[k][tn * 8];
            float4 a1 = *(float4*)&As[k][tn * 8 + 4];
            float4 bb = *(float4*)&Bs[k][tm * 4];
            float av[8] = {a0.x, a0.y, a0.z, a0.w, a1.x, a1.y, a1.z, a1.w};
#pragma unroll
            for (int i = 0; i < 8; i++) {
                acc[i][0] = fmaf(av[i], bb.x, acc[i][0]);
                acc[i][1] = fmaf(av[i], bb.y, acc[i][1]);
                acc[i][2] = fmaf(av[i], bb.z, acc[i][2]);
                acc[i][3] = fmaf(av[i], bb.w, acc[i][3]);
            }
        }
    }
    const int m = m0 + tm * 4;
    if (m < 800) {
#pragma unroll
        for (int i = 0; i < 8; i++) {
            size_t row = (size_t)b * 384 + n0 + tn * 8 + i;
            *(float4*)&S[row * 800 + m] =
                make_float4(acc[i][0], acc[i][1], acc[i][2], acc[i][3]);
        }
    }
}

// ====================================================================
// Active top-10 + softmax (scale inline from zc). 5184 warps.
// ====================================================================
__global__ void k_topk_act(const float* __restrict__ S, const float* __restrict__ zc,
                           int* __restrict__ tidx, float* __restrict__ tw)
{
    int gw = (blockIdx.x * blockDim.x + threadIdx.x) >> 5;
    int lane = threadIdx.x & 31;
    if (gw >= 16 * 324) return;
    const int b = gw / 324, ai = gw % 324;
    const int n = (23 + ai / 18) * 64 + 23 + ai % 18;
    const float* zb = zc + (size_t)b * 128 * 4096 + n;
    float ss = 0.f;
#pragma unroll
    for (int j = 0; j < 4; j++) {
        float v = zb[(size_t)(lane + 32 * j) * 4096];
        ss = fmaf(v, v, ss);
    }
#pragma unroll
    for (int o = 16; o > 0; o >>= 1) ss += __shfl_xor_sync(0xffffffffu, ss, o);
    float sc = 1.0f / fmaxf(sqrtf(ss), 1e-12f);

    const float* row = S + ((size_t)b * 384 + ai) * 800;
    float lv[10]; int li[10];
#pragma unroll
    for (int j = 0; j < 10; j++) { lv[j] = -INFINITY; li[j] = 0x7fffffff; }
    for (int t = 0; t < 25; t++) {
        int m = lane + 32 * t;
        float v = row[m];
        int i = m;
#pragma unroll
        for (int j = 0; j < 10; j++) {
            bool better = (v > lv[j]) || (v == lv[j] && i < li[j]);
            if (better) {
                float tv = lv[j]; lv[j] = v; v = tv;
                int ti = li[j]; li[j] = i; i = ti;
            }
        }
    }
    float bv[10]; int bi[10];
#pragma unroll
    for (int k = 0; k < 10; k++) {
        float cv = lv[0]; int ci = li[0];
#pragma unroll
        for (int off = 16; off > 0; off >>= 1) {
            float ov = __shfl_xor_sync(0xffffffffu, cv, off);
            int   oi = __shfl_xor_sync(0xffffffffu, ci, off);
            if (ov > cv || (ov == cv && oi < ci)) { cv = ov; ci = oi; }
        }
        bv[k] = cv; bi[k] = ci;
        if (lv[0] == cv && li[0] == ci) {
#pragma unroll
            for (int j = 0; j < 9; j++) { lv[j] = lv[j + 1]; li[j] = li[j + 1]; }
            lv[9] = -INFINITY; li[9] = 0x7fffffff;
        }
    }
    if (lane == 0) {
        float mx = bv[0] * sc;
        float e[10], sum = 0.f;
#pragma unroll
        for (int k = 0; k < 10; k++) { e[k] = expf(bv[k] * sc - mx); sum += e[k]; }
        float inv = 1.0f / sum;
#pragma unroll
        for (int k = 0; k < 10; k++) {
            tidx[gw * 10 + k] = bi[k];
            tw[gw * 10 + k]   = e[k] * inv;
        }
    }
}

// ====================================================================
// Active weighted gather -> gdelta[b][c][ai] = z_match - bgz[c]
// ====================================================================
__global__ void k_gatherC_act(const float* __restrict__ vals, const int* __restrict__ tidx,
                              const float* __restrict__ tw, const float* __restrict__ bgz,
                              float* __restrict__ gdelta)
{
    __shared__ int   sidx[8][10];
    __shared__ float swt [8][10];
    const int r0 = blockIdx.x * 8;
    const int tid = threadIdx.x;
    if (tid < 80) {
        int ny = tid / 10, k = tid % 10;
        sidx[ny][k] = tidx[(size_t)(r0 + ny) * 10 + k];
        swt [ny][k] = tw  [(size_t)(r0 + ny) * 10 + k];
    }
    __syncthreads();
    const int cx = tid & 31, ny = tid >> 5;
    const int row = r0 + ny;
    const int b = row / 324, ai = row % 324;
#pragma unroll
    for (int cc = 0; cc < 4; cc++) {
        int c = cx + 32 * cc;
        float acc = 0.f;
#pragma unroll
        for (int k = 0; k < 10; k++)
            acc = fmaf(vals[(size_t)sidx[ny][k] * 128 + c], swt[ny][k], acc);
        gdelta[((size_t)b * 128 + c) * 324 + ai] = acc - bgz[c];
    }
}

// ====================================================================
// Skip GEMM + fused argmax. Tile 128n, m chunks of 128, 8x8 micro.
// ====================================================================
__global__ __launch_bounds__(256) void k_gemm_amax(const float* __restrict__ A,
    const float* __restrict__ Bm, int* __restrict__ amax)
{
    __shared__ float As[16][128];
    __shared__ float Bs[16][128];
    __shared__ float rv[128][17];
    __shared__ int   ri[128][17];
    const int b  = blockIdx.y;
    const int n0 = blockIdx.x * 128;
    const int tid = threadIdx.x;
    const int tm = tid & 15, tn = tid >> 4;
    const int lk = tid >> 4, ln = (tid & 15) * 8;
    const float* Ab = A + (size_t)b * 128 * 4096;
    float bestv[8]; int besti[8];
#pragma unroll
    for (int i = 0; i < 8; i++) { bestv[i] = -INFINITY; besti[i] = 0x7fffffff; }
    for (int m0 = 0; m0 < 800; m0 += 128) {
        float acc[8][8];
#pragma unroll
        for (int i = 0; i < 8; i++)
#pragma unroll
            for (int j = 0; j < 8; j++) acc[i][j] = 0.f;
        for (int k0 = 0; k0 < 128; k0 += 16) {
            __syncthreads();
            const float* ap = &Ab[(size_t)(k0 + lk) * 4096 + n0 + ln];
            *(float4*)&As[lk][ln]     = *(const float4*)ap;
            *(float4*)&As[lk][ln + 4] = *(const float4*)(ap + 4);
            if (m0 + ln + 7 < 800) {
                const float* bp = &Bm[(size_t)(k0 + lk) * 800 + m0 + ln];
                *(float4*)&Bs[lk][ln]     = *(const float4*)bp;
                *(float4*)&Bs[lk][ln + 4] = *(const float4*)(bp + 4);
            } else {
#pragma unroll
                for (int j = 0; j < 8; j++)
                    Bs[lk][ln + j] = (m0 + ln + j < 800)
                        ? Bm[(size_t)(k0 + lk) * 800 + m0 + ln + j] : 0.f;
            }
            __syncthreads();
#pragma unroll
            for (int k = 0; k < 16; k++) {
                float4 a0 = *(float4*)&As[k][tn * 8];
                float4 a1 = *(float4*)&As[k][tn * 8 + 4];
                float4 b0 = *(float4*)&Bs[k][tm * 8];
                float4 b1 = *(float4*)&Bs[k][tm * 8 + 4];
                float av[8] = {a0.x, a0.y, a0.z, a0.w, a1.x, a1.y, a1.z, a1.w};
                float bw[8] = {b0.x, b0.y, b0.z, b0.w, b1.x, b1.y, b1.z, b1.w};
#pragma unroll
                for (int i = 0; i < 8; i++)
#pragma unroll
                    for (int j = 0; j < 8; j++)
                        acc[i][j] = fmaf(av[i], bw[j], acc[i][j]);
            }
        }
#pragma unroll
        for (int i = 0; i < 8; i++)
#pragma unroll
            for (int j = 0; j < 8; j++) {
                int m = m0 + tm * 8 + j;
                float v = acc[i][j];
                if (m < 800 && (v > bestv[i] || (v == bestv[i] && m < besti[i]))) {
                    bestv[i] = v; besti[i] = m;
                }
            }
    }
    __syncthreads();
#pragma unroll
    for (int i = 0; i < 8; i++) { rv[tn * 8 + i][tm] = bestv[i]; ri[tn * 8 + i][tm] = besti[i]; }
    __syncthreads();
    if (tid < 128) {
        float bv = -INFINITY; int bi = 0x7fffffff;
#pragma unroll
        for (int t = 0; t < 16; t++) {
            float v = rv[tid][t]; int i = ri[tid][t];
            if (v > bv || (v == bv && i < bi)) { bv = v; bi = i; }
        }
        amax[b * 4096 + n0 + tid] = bi;
    }
}

// ====================================================================
// Hard gather -> zmS[b][c][n] (128-channel layout)
// ====================================================================
__global__ void k_gatherS(const float* __restrict__ hard, const int* __restrict__ amax,
                          float* __restrict__ zmS)
{
    const int r0 = blockIdx.x * 8;
    const int tid = threadIdx.x;
    const int cx = tid & 31, ny = tid >> 5;
    const int row = r0 + ny;
    const int b = row >> 12, n = row & 4095;
    const int a = amax[row];
#pragma unroll
    for (int cc = 0; cc < 4; cc++) {
        int c = cx + 32 * cc;
        zmS[((size_t)b * 128 + c) * 4096 + n] = hard[(size_t)a * 128 + c];
    }
}

// ====================================================================
// Transposed conv (k=4, s=2) + relu out; RELUIN applies relu on input load.
// ====================================================================
template<int IC, int OC, int OCB, bool RELUIN>
__global__ __launch_bounds__(256) void k_deconv(const float* __restrict__ in,
    const float* __restrict__ w, const float* __restrict__ bias,
    float* __restrict__ out, int Hi, int tilesY)
{
    __shared__ float tin[2][34][36];
    __shared__ float sw[2][OCB][16];
    const int Ho = 2 * Hi;
    const int tY = blockIdx.y % tilesY;
    const int ob = blockIdx.y / tilesY;
    const int b  = blockIdx.z;
    const int Xo0 = blockIdx.x * 64, Yo0 = tY * 64;
    const int a0 = Yo0 >> 1, c0 = Xo0 >> 1;
    const int tid = threadIdx.x;
    const int ty = tid >> 4, tx = tid & 15;
    float acc[OCB][4][4];
#pragma unroll
    for (int o = 0; o < OCB; o++)
#pragma unroll
        for (int r = 0; r < 4; r++)
#pragma unroll
            for (int c = 0; c < 4; c++) acc[o][r][c] = 0.f;
    const float* inb = in + (size_t)b * IC * Hi * Hi;
    for (int ic0 = 0; ic0 < IC; ic0 += 2) {
        __syncthreads();
        for (int i = tid; i < 2 * 34 * 34; i += 256) {
            int ic = i / (34 * 34); int rem = i % (34 * 34);
            int r = rem / 34, c = rem % 34;
            int gy = a0 + r - 1, gx = c0 + c - 1;
            float v = 0.f;
            if (gy >= 0 && gy < Hi && gx >= 0 && gx < Hi) {
                v = inb[(size_t)(ic0 + ic) * Hi * Hi + gy * Hi + gx];
                if (RELUIN) v = fmaxf(v, 0.f);
            }
            tin[ic][r][c] = v;
        }
        for (int i = tid; i < 2 * OCB * 16; i += 256) {
            int ic = i / (OCB * 16); int rem = i % (OCB * 16);
            int o = rem / 16; int t = rem % 16;
            sw[ic][o][t] = w[((size_t)(ic0 + ic) * OC + ob * OCB + o) * 16 + t];
        }
        __syncthreads();
#pragma unroll
        for (int ic = 0; ic < 2; ic++) {
            float p[4][4];
#pragma unroll
            for (int i = 0; i < 4; i++)
#pragma unroll
                for (int j = 0; j < 4; j++)
                    p[i][j] = tin[ic][2 * ty + i][2 * tx + j];
#pragma unroll
            for (int o = 0; o < OCB; o++) {
                float W4[16];
#pragma unroll
                for (int t = 0; t < 16; t++) W4[t] = sw[ic][o][t];
#pragma unroll
                for (int e = 0; e < 2; e++)
#pragma unroll
                    for (int f = 0; f < 2; f++) {
                        float P00 = p[e][f],     P01 = p[e][f + 1],     P02 = p[e][f + 2];
                        float P10 = p[e + 1][f], P11 = p[e + 1][f + 1], P12 = p[e + 1][f + 2];
                        float P20 = p[e + 2][f], P21 = p[e + 2][f + 1], P22 = p[e + 2][f + 2];
                        acc[o][2 * e][2 * f]         += W4[15] * P00 + W4[13] * P01 + W4[7] * P10 + W4[5] * P11;
                        acc[o][2 * e][2 * f + 1]     += W4[14] * P01 + W4[12] * P02 + W4[6] * P11 + W4[4] * P12;
                        acc[o][2 * e + 1][2 * f]     += W4[11] * P10 + W4[9]  * P11 + W4[3] * P20 + W4[1] * P21;
                        acc[o][2 * e + 1][2 * f + 1] += W4[10] * P11 + W4[8]  * P12 + W4[2] * P21 + W4[0] * P22;
                    }
            }
        }
    }
#pragma unroll
    for (int o = 0; o < OCB; o++) {
        int oc = ob * OCB + o;
        float bv = bias[oc];
#pragma unroll
        for (int r = 0; r < 4; r++)
#pragma unroll
            for (int c = 0; c < 4; c += 2) {
                float v0 = fmaxf(acc[o][r][c] + bv, 0.f);
                float v1 = fmaxf(acc[o][r][c + 1] + bv, 0.f);
                *(float2*)(out + ((size_t)((size_t)b * OC + oc) * Ho + (Yo0 + 4 * ty + r)) * Ho
                               + Xo0 + 4 * tx + c) = make_float2(v0, v1);
            }
    }
}

// ====================================================================
// Host launcher — fork/join multi-stream
// ====================================================================
static cudaStream_t s_bg = nullptr, s_skip = nullptr;
static cudaEvent_t  e_root = nullptr, e_bgdone = nullptr, e_skipdone = nullptr;

extern "C" void kernel_launch(void* const* d_in, const int* in_sizes, int n_in,
                              void* d_out, int out_size)
{
    if (!s_bg) {
        cudaStreamCreateWithFlags(&s_bg,   cudaStreamNonBlocking);
        cudaStreamCreateWithFlags(&s_skip, cudaStreamNonBlocking);
        cudaEventCreateWithFlags(&e_root,     cudaEventDisableTiming);
        cudaEventCreateWithFlags(&e_bgdone,   cudaEventDisableTiming);
        cudaEventCreateWithFlags(&e_skipdone, cudaEventDisableTiming);
    }
    const float* x        = (const float*)d_in[0];
    const float* ce_w1    = (const float*)d_in[1];
    const float* ce_b1    = (const float*)d_in[2];
    const float* ce_w2    = (const float*)d_in[3];
    const float* ce_b2    = (const float*)d_in[4];
    const float* se_w1    = (const float*)d_in[5];
    const float* se_b1    = (const float*)d_in[6];
    const float* se_w2    = (const float*)d_in[7];
    const float* se_b2    = (const float*)d_in[8];
    const float* mem_keys = (const float*)d_in[9];
    const float* mem_vals = (const float*)d_in[10];
    const float* mem_hard = (const float*)d_in[11];
    const float* dec_w1   = (const float*)d_in[12];
    const float* dec_b1   = (const float*)d_in[13];
    const float* dec_tw1  = (const float*)d_in[14];
    const float* dec_tb1  = (const float*)d_in[15];
    const float* dec_tw2  = (const float*)d_in[16];
    const float* dec_tb2  = (const float*)d_in[17];
    const float* dec_w2   = (const float*)d_in[18];
    const float* dec_b2   = (const float*)d_in[19];
    float* outp = (float*)d_out;

    float *knT, *hnT, *A, *A2, *zc, *zs, *Sact, *tw, *bgz, *c9, *gdelta, *zmS, *d1, *u1, *u2;
    int *tidx, *amax;
    cudaGetSymbolAddress((void**)&knT,    g_knT);
    cudaGetSymbolAddress((void**)&hnT,    g_hnT);
    cudaGetSymbolAddress((void**)&A,      g_A);
    cudaGetSymbolAddress((void**)&A2,     g_A2);
    cudaGetSymbolAddress((void**)&zc,     g_zc);
    cudaGetSymbolAddress((void**)&zs,     g_zs);
    cudaGetSymbolAddress((void**)&Sact,   g_Sact);
    cudaGetSymbolAddress((void**)&tidx,   g_tidx);
    cudaGetSymbolAddress((void**)&tw,     g_tw);
    cudaGetSymbolAddress((void**)&amax,   g_amax);
    cudaGetSymbolAddress((void**)&bgz,    g_bgz);
    cudaGetSymbolAddress((void**)&c9,     g_c9);
    cudaGetSymbolAddress((void**)&gdelta, g_gdelta);
    cudaGetSymbolAddress((void**)&zmS,    g_zmS);
    cudaGetSymbolAddress((void**)&d1,     g_d1);
    cudaGetSymbolAddress((void**)&u1,     g_u1);
    cudaGetSymbolAddress((void**)&u2,     g_u2);

    // root: normalized memory tables
    k_normrows<<<200, 256>>>(mem_keys, mem_hard, knT, hnT);
    cudaEventRecord(e_root, 0);

    // ---- bg branch: bgz then C9 table ----
    cudaStreamWaitEvent(s_bg, e_root, 0);
    k_bg<<<1, 256, 0, s_bg>>>(ce_w2, ce_b1, ce_b2, knT, mem_vals, bgz);
    k_prepC9<<<1, 256, 0, s_bg>>>(dec_w1, dec_b1, bgz, c9);
    cudaEventRecord(e_bgdone, s_bg);

    // ---- skip branch ----
    cudaStreamWaitEvent(s_skip, e_root, 0);
    k_enc1<16, false><<<dim3(8, 8, 16), 256, 0, s_skip>>>(x, se_w1, se_b1, A2, 0, 0);
    k_conv3c<4, true, true, false><<<dim3(2, 4 * 32, 16), 128, 0, s_skip>>>(
        A2, se_w2, se_b2, zs, 16, 16, 128, 128, 128, 4, 0, 0, nullptr);
    k_gemm_amax<<<dim3(32, 16), 256, 0, s_skip>>>(zs, hnT, amax);
    k_gatherS<<<8192, 256, 0, s_skip>>>(mem_hard, amax, zmS);
    cudaEventRecord(e_skipdone, s_skip);

    // ---- center branch (main stream) ----
    k_fillA<<<(16 * 32 * 16384) / 256, 256>>>(A, ce_b1);
    k_enc1<32, true><<<dim3(4, 4, 16), 256>>>(x, ce_w1, ce_b1, A, 2, 2);
    k_conv3c<4, true, true, false><<<dim3(1, 2 * 32, 16), 128>>>(
        A, ce_w2, ce_b2, zc, 32, 32, 128, 128, 128, 2, 32, 32, nullptr);
    k_gemm_act<<<dim3(13, 3, 16), 256>>>(zc, knT, Sact);
    k_topk_act<<<(16 * 324 + 7) / 8, 256>>>(Sact, zc, tidx, tw);
    cudaStreamWaitEvent(0, e_bgdone, 0);   // bgz + c9 ready
    k_gatherC_act<<<(16 * 324) / 8, 256>>>(mem_vals, tidx, tw, bgz, gdelta);

    // ---- join, decoder ----
    cudaStreamWaitEvent(0, e_skipdone, 0);
    // dec1 main: skip channels only (w offset 128 ic), + C9 background, raw output
    k_conv3c<4, false, false, true><<<dim3(1, 2 * 16, 16), 128>>>(
        zmS, dec_w1 + 128 * 9, dec_b1, d1, 128, 256, 64, 64, 64, 2, 0, 0, c9);
    k_dec1delta<<<dim3(4, 16), 256>>>(gdelta, dec_w1, d1);
    k_deconv<64, 32, 4, true><<<dim3(2, 2 * 8, 16), 256>>>(d1, dec_tw1, dec_tb1, u1, 64, 2);
    k_deconv<32, 16, 4, false><<<dim3(4, 4 * 4, 16), 256>>>(u1, dec_tw2, dec_tb2, u2, 128, 4);
    k_conv3c<1, false, false, false><<<dim3(4, 8, 16), 128>>>(
        u2, dec_w2, dec_b2, outp, 16, 16, 1, 256, 256, 8, 0, 0, nullptr);
}